// round 1
// baseline (speedup 1.0000x reference)
#include <cuda_runtime.h>
#include <cstdint>
#include <cstddef>

#define QLEN   1024
#define BATCH  8
#define DMODEL 512
#define NHEAD  8
#define DHEAD  64
#define DINNER 2048
#define ELEN   1024
#define ATT_SCALE 0.125f
#define ROWS (QLEN * BATCH)   /* 8192 */

// ---------------- scratch (static device allocations; no runtime alloc) ----
__device__ float g_h    [ROWS * DMODEL];
__device__ float g_heads[ROWS * 3 * DMODEL];
__device__ float g_rk   [QLEN * DMODEL];
__device__ float g_vec  [ROWS * DMODEL];
__device__ float g_out1 [ROWS * DMODEL];
__device__ float g_h2   [ROWS * DMODEL];
__device__ float g_q2   [ROWS * DMODEL];
__device__ float g_kv   [ROWS * 2 * DMODEL];
__device__ float g_vec2 [ROWS * DMODEL];
__device__ float g_out2 [ROWS * DMODEL];
__device__ float g_c    [ROWS * DMODEL];
__device__ float g_t    [ROWS * DINNER];

// ---------------- LayerNorm: one block per 512-wide row ---------------------
__global__ __launch_bounds__(128) void ln_k(const float* __restrict__ x,
                                            const float* __restrict__ g,
                                            const float* __restrict__ b,
                                            float* __restrict__ y)
{
    const int row = blockIdx.x;
    const int t = threadIdx.x;
    const float4 v = reinterpret_cast<const float4*>(x + (size_t)row * DMODEL)[t];
    float s  = v.x + v.y + v.z + v.w;
    float sq = v.x*v.x + v.y*v.y + v.z*v.z + v.w*v.w;
    #pragma unroll
    for (int o = 16; o; o >>= 1) {
        s  += __shfl_xor_sync(0xffffffffu, s,  o);
        sq += __shfl_xor_sync(0xffffffffu, sq, o);
    }
    __shared__ float ss[4], sqq[4];
    const int w = t >> 5, lane = t & 31;
    if (lane == 0) { ss[w] = s; sqq[w] = sq; }
    __syncthreads();
    s  = ss[0]  + ss[1]  + ss[2]  + ss[3];
    sq = sqq[0] + sqq[1] + sqq[2] + sqq[3];
    const float mean = s * (1.0f / DMODEL);
    const float var  = sq * (1.0f / DMODEL) - mean * mean;
    const float rstd = rsqrtf(var + 1e-5f);
    const float4 gg = reinterpret_cast<const float4*>(g)[t];
    const float4 bb = reinterpret_cast<const float4*>(b)[t];
    float4 o4;
    o4.x = (v.x - mean) * rstd * gg.x + bb.x;
    o4.y = (v.y - mean) * rstd * gg.y + bb.y;
    o4.z = (v.z - mean) * rstd * gg.z + bb.z;
    o4.w = (v.w - mean) * rstd * gg.w + bb.w;
    reinterpret_cast<float4*>(y + (size_t)row * DMODEL)[t] = o4;
}

// ---------------- generic tiled GEMM: C = A[M,K] @ B[K,N] (+bias)(gelu)(+res)
template <bool GELU>
__global__ __launch_bounds__(256) void gemm_k(const float* __restrict__ A,
                                              const float* __restrict__ Bm,
                                              const float* __restrict__ bias,
                                              const float* __restrict__ res,
                                              float* __restrict__ C,
                                              int M, int N, int K)
{
    __shared__ float As[16][64];
    __shared__ float Bs[16][64];
    const int tid = threadIdx.x;
    const int tx = tid & 15, ty = tid >> 4;
    const int m0 = blockIdx.y << 6, n0 = blockIdx.x << 6;
    float acc[4][4] = {};
    const int la_r = tid >> 2,  la_c = (tid & 3) << 2;
    const int lb_r = tid >> 4,  lb_c = (tid & 15) << 2;
    const float* aBase = A + (size_t)(m0 + la_r) * K + la_c;
    const float* bBase = Bm + (size_t)lb_r * N + n0 + lb_c;
    for (int k0 = 0; k0 < K; k0 += 16) {
        const float4 av = *reinterpret_cast<const float4*>(aBase + k0);
        As[la_c + 0][la_r] = av.x;
        As[la_c + 1][la_r] = av.y;
        As[la_c + 2][la_r] = av.z;
        As[la_c + 3][la_r] = av.w;
        *reinterpret_cast<float4*>(&Bs[lb_r][lb_c]) =
            *reinterpret_cast<const float4*>(bBase + (size_t)k0 * N);
        __syncthreads();
        #pragma unroll
        for (int kk = 0; kk < 16; kk++) {
            const float4 af = *reinterpret_cast<const float4*>(&As[kk][ty << 2]);
            const float4 bf = *reinterpret_cast<const float4*>(&Bs[kk][tx << 2]);
            const float a[4] = {af.x, af.y, af.z, af.w};
            const float b[4] = {bf.x, bf.y, bf.z, bf.w};
            #pragma unroll
            for (int u = 0; u < 4; u++)
                #pragma unroll
                for (int v = 0; v < 4; v++)
                    acc[u][v] = fmaf(a[u], b[v], acc[u][v]);
        }
        __syncthreads();
    }
    #pragma unroll
    for (int u = 0; u < 4; u++) {
        const int m = m0 + (ty << 2) + u;
        #pragma unroll
        for (int v = 0; v < 4; v++) {
            const int n = n0 + (tx << 2) + v;
            float val = acc[u][v];
            if (bias) val += bias[n];
            if (GELU) val = 0.5f * val * (1.0f + erff(val * 0.70710678118654752f));
            if (res)  val += res[(size_t)m * N + n];
            C[(size_t)m * N + n] = val;
        }
    }
}

// ---------------- flash attention 1: relative TXL attention (causal) --------
// score[i,j] = ((q+rwb)[i]·k[j] + (q+rrb)[i]·r_k[1023+j-i]) * SCALE, j<=i
__global__ __launch_bounds__(256) void flash_rel_k(const float* __restrict__ heads,
                                                   const float* __restrict__ rk,
                                                   const float* __restrict__ rwb,
                                                   const float* __restrict__ rrb,
                                                   float* __restrict__ vec)
{
    extern __shared__ float sm[];
    float* qw  = sm;               // [64][64] d-major
    float* qr  = qw + 4096;        // [64][64] d-major
    float* kt  = qr + 4096;        // [64][64] d-major
    float* vt  = kt + 4096;        // [64][64] j-major
    float* rks = vt + 4096;        // [64][129] d-major, padded
    float* ps  = rks + 64 * 129;   // [64][65] tj-major, padded

    const int tid = threadIdx.x;
    const int tx = tid & 15, ty = tid >> 4;
    const int i0 = blockIdx.x << 6;
    const int b  = blockIdx.y >> 3, n = blockIdx.y & 7;

    for (int t = tid; t < 4096; t += 256) {
        const int i = t >> 6, d = t & 63;
        const float qv = heads[((size_t)(i0 + i) * BATCH + b) * (3 * DMODEL) + n * 64 + d];
        qw[d * 64 + i] = qv + rwb[n * 64 + d];
        qr[d * 64 + i] = qv + rrb[n * 64 + d];
    }

    float m_i[4], l_i[4], o[4][4];
    #pragma unroll
    for (int u = 0; u < 4; u++) {
        m_i[u] = -1e30f; l_i[u] = 0.0f;
        #pragma unroll
        for (int v = 0; v < 4; v++) o[u][v] = 0.0f;
    }

    for (int j0 = 0; j0 <= i0; j0 += 64) {
        __syncthreads();
        for (int t = tid; t < 4096; t += 256) {
            const int j = t >> 6, d = t & 63;
            const size_t base = ((size_t)(j0 + j) * BATCH + b) * (3 * DMODEL) + n * 64 + d;
            kt[d * 64 + j] = heads[base + DMODEL];
            vt[j * 64 + d] = heads[base + 2 * DMODEL];
        }
        const int m_base = 960 + j0 - i0;   // >= 0 always
        for (int t = tid; t < 127 * 64; t += 256) {
            const int ml = t >> 6, d = t & 63;
            const int m = m_base + ml;
            rks[d * 129 + ml] = (m <= QLEN - 1) ? rk[(size_t)m * DMODEL + n * 64 + d] : 0.0f;
        }
        __syncthreads();

        float s[4][4] = {};
        #pragma unroll 8
        for (int d = 0; d < 64; d++) {
            const float4 a0 = *reinterpret_cast<const float4*>(&qw[d * 64 + (ty << 2)]);
            const float4 a1 = *reinterpret_cast<const float4*>(&qr[d * 64 + (ty << 2)]);
            const float4 kf = *reinterpret_cast<const float4*>(&kt[d * 64 + (tx << 2)]);
            const float aw[4] = {a0.x, a0.y, a0.z, a0.w};
            const float ar[4] = {a1.x, a1.y, a1.z, a1.w};
            const float kk[4] = {kf.x, kf.y, kf.z, kf.w};
            #pragma unroll
            for (int u = 0; u < 4; u++) {
                const int mlb = (tx << 2) - (ty << 2) - u + 63;
                #pragma unroll
                for (int v = 0; v < 4; v++) {
                    s[u][v] = fmaf(aw[u], kk[v], s[u][v]);
                    s[u][v] = fmaf(ar[u], rks[d * 129 + mlb + v], s[u][v]);
                }
            }
        }

        #pragma unroll
        for (int u = 0; u < 4; u++) {
            const int gi = i0 + (ty << 2) + u;
            float rmax = -1e30f;
            #pragma unroll
            for (int v = 0; v < 4; v++) {
                const int gj = j0 + (tx << 2) + v;
                s[u][v] = (gj > gi) ? -1e30f : s[u][v] * ATT_SCALE;
                rmax = fmaxf(rmax, s[u][v]);
            }
            #pragma unroll
            for (int off = 1; off < 16; off <<= 1)
                rmax = fmaxf(rmax, __shfl_xor_sync(0xffffffffu, rmax, off));
            const float m_new = fmaxf(m_i[u], rmax);
            const float alpha = __expf(m_i[u] - m_new);
            float rsum = 0.0f;
            #pragma unroll
            for (int v = 0; v < 4; v++) {
                const float p = __expf(s[u][v] - m_new);
                s[u][v] = p; rsum += p;
            }
            #pragma unroll
            for (int off = 1; off < 16; off <<= 1)
                rsum += __shfl_xor_sync(0xffffffffu, rsum, off);
            l_i[u] = l_i[u] * alpha + rsum;
            m_i[u] = m_new;
            #pragma unroll
            for (int v = 0; v < 4; v++) o[u][v] *= alpha;
        }

        #pragma unroll
        for (int u = 0; u < 4; u++)
            #pragma unroll
            for (int v = 0; v < 4; v++)
                ps[((tx << 2) + v) * 65 + (ty << 2) + u] = s[u][v];
        __syncthreads();

        #pragma unroll 8
        for (int jd = 0; jd < 64; jd++) {
            float pf[4];
            #pragma unroll
            for (int u = 0; u < 4; u++) pf[u] = ps[jd * 65 + (ty << 2) + u];
            const float4 vf = *reinterpret_cast<const float4*>(&vt[jd * 64 + (tx << 2)]);
            const float vv[4] = {vf.x, vf.y, vf.z, vf.w};
            #pragma unroll
            for (int u = 0; u < 4; u++)
                #pragma unroll
                for (int v = 0; v < 4; v++)
                    o[u][v] = fmaf(pf[u], vv[v], o[u][v]);
        }
    }

    #pragma unroll
    for (int u = 0; u < 4; u++) {
        const float inv = 1.0f / l_i[u];
        const int gi = i0 + (ty << 2) + u;
        #pragma unroll
        for (int v = 0; v < 4; v++)
            vec[((size_t)gi * BATCH + b) * DMODEL + n * 64 + (tx << 2) + v] = o[u][v] * inv;
    }
}

// ---------------- flash attention 2: cross attention over encoder -----------
__global__ __launch_bounds__(256) void flash_ctx_k(const float* __restrict__ q2,
                                                   const float* __restrict__ kv,
                                                   const unsigned char* __restrict__ emask,
                                                   float* __restrict__ vec2)
{
    extern __shared__ float sm[];
    float* qt = sm;              // [64][64] d-major
    float* kt = qt + 4096;       // [64][64] d-major
    float* vt = kt + 4096;       // [64][64] j-major
    float* ps = vt + 4096;       // [64][65]

    const int tid = threadIdx.x;
    const int tx = tid & 15, ty = tid >> 4;
    const int i0 = blockIdx.x << 6;
    const int b  = blockIdx.y >> 3, n = blockIdx.y & 7;

    for (int t = tid; t < 4096; t += 256) {
        const int i = t >> 6, d = t & 63;
        qt[d * 64 + i] = q2[((size_t)(i0 + i) * BATCH + b) * DMODEL + n * 64 + d];
    }

    float m_i[4], l_i[4], o[4][4];
    #pragma unroll
    for (int u = 0; u < 4; u++) {
        m_i[u] = -1e30f; l_i[u] = 0.0f;
        #pragma unroll
        for (int v = 0; v < 4; v++) o[u][v] = 0.0f;
    }

    for (int j0 = 0; j0 < ELEN; j0 += 64) {
        __syncthreads();
        for (int t = tid; t < 4096; t += 256) {
            const int j = t >> 6, d = t & 63;
            const size_t base = ((size_t)(j0 + j) * BATCH + b) * (2 * DMODEL) + n * 64 + d;
            kt[d * 64 + j] = kv[base];
            vt[j * 64 + d] = kv[base + DMODEL];
        }
        __syncthreads();

        float s[4][4] = {};
        #pragma unroll 8
        for (int d = 0; d < 64; d++) {
            const float4 a0 = *reinterpret_cast<const float4*>(&qt[d * 64 + (ty << 2)]);
            const float4 kf = *reinterpret_cast<const float4*>(&kt[d * 64 + (tx << 2)]);
            const float aq[4] = {a0.x, a0.y, a0.z, a0.w};
            const float kk[4] = {kf.x, kf.y, kf.z, kf.w};
            #pragma unroll
            for (int u = 0; u < 4; u++)
                #pragma unroll
                for (int v = 0; v < 4; v++)
                    s[u][v] = fmaf(aq[u], kk[v], s[u][v]);
        }

        float mk[4];
        #pragma unroll
        for (int v = 0; v < 4; v++)
            mk[v] = emask[(size_t)(j0 + (tx << 2) + v) * BATCH + b] ? 1.0f : 0.0f;

        #pragma unroll
        for (int u = 0; u < 4; u++) {
            float rmax = -1e30f;
            #pragma unroll
            for (int v = 0; v < 4; v++) {
                s[u][v] = (mk[v] != 0.0f) ? -1e4f : s[u][v] * ATT_SCALE;
                rmax = fmaxf(rmax, s[u][v]);
            }
            #pragma unroll
            for (int off = 1; off < 16; off <<= 1)
                rmax = fmaxf(rmax, __shfl_xor_sync(0xffffffffu, rmax, off));
            const float m_new = fmaxf(m_i[u], rmax);
            const float alpha = __expf(m_i[u] - m_new);
            float rsum = 0.0f;
            #pragma unroll
            for (int v = 0; v < 4; v++) {
                const float p = __expf(s[u][v] - m_new);
                s[u][v] = p; rsum += p;
            }
            #pragma unroll
            for (int off = 1; off < 16; off <<= 1)
                rsum += __shfl_xor_sync(0xffffffffu, rsum, off);
            l_i[u] = l_i[u] * alpha + rsum;
            m_i[u] = m_new;
            #pragma unroll
            for (int v = 0; v < 4; v++) o[u][v] *= alpha;
        }

        #pragma unroll
        for (int u = 0; u < 4; u++)
            #pragma unroll
            for (int v = 0; v < 4; v++)
                ps[((tx << 2) + v) * 65 + (ty << 2) + u] = s[u][v];
        __syncthreads();

        #pragma unroll 8
        for (int jd = 0; jd < 64; jd++) {
            float pf[4];
            #pragma unroll
            for (int u = 0; u < 4; u++) pf[u] = ps[jd * 65 + (ty << 2) + u];
            const float4 vf = *reinterpret_cast<const float4*>(&vt[jd * 64 + (tx << 2)]);
            const float vv[4] = {vf.x, vf.y, vf.z, vf.w};
            #pragma unroll
            for (int u = 0; u < 4; u++)
                #pragma unroll
                for (int v = 0; v < 4; v++)
                    o[u][v] = fmaf(pf[u], vv[v], o[u][v]);
        }
    }

    #pragma unroll
    for (int u = 0; u < 4; u++) {
        const float inv = 1.0f / l_i[u];
        const int gi = i0 + (ty << 2) + u;
        #pragma unroll
        for (int v = 0; v < 4; v++)
            vec2[((size_t)gi * BATCH + b) * DMODEL + n * 64 + (tx << 2) + v] = o[u][v] * inv;
    }
}

// ---------------- host orchestration ----------------------------------------
extern "C" void kernel_launch(void* const* d_in, const int* in_sizes, int n_in,
                              void* d_out, int out_size)
{
    (void)in_sizes; (void)n_in; (void)out_size;
    const float* dec_inp = (const float*)d_in[0];
    const float* r       = (const float*)d_in[1];
    const float* enc_out = (const float*)d_in[2];
    const float* rwb     = (const float*)d_in[3];
    const float* rrb     = (const float*)d_in[4];
    const float* qkv_w   = (const float*)d_in[5];
    const float* r_w     = (const float*)d_in[6];
    const float* o_w     = (const float*)d_in[7];
    const float* ln1_g   = (const float*)d_in[8];
    const float* ln1_b   = (const float*)d_in[9];
    const float* q_w     = (const float*)d_in[10];
    const float* kv_w    = (const float*)d_in[11];
    const float* o2_w    = (const float*)d_in[12];
    const float* ln2_g   = (const float*)d_in[13];
    const float* ln2_b   = (const float*)d_in[14];
    const float* ff_w1   = (const float*)d_in[15];
    const float* ff_b1   = (const float*)d_in[16];
    const float* ff_w2   = (const float*)d_in[17];
    const float* ff_b2   = (const float*)d_in[18];
    const float* ln3_g   = (const float*)d_in[19];
    const float* ln3_b   = (const float*)d_in[20];
    const unsigned char* emask = (const unsigned char*)d_in[22];
    float* out = (float*)d_out;

    float *h, *heads, *rk, *vec, *out1, *h2, *q2, *kvb, *vec2, *out2, *c, *t;
    cudaGetSymbolAddress((void**)&h,     g_h);
    cudaGetSymbolAddress((void**)&heads, g_heads);
    cudaGetSymbolAddress((void**)&rk,    g_rk);
    cudaGetSymbolAddress((void**)&vec,   g_vec);
    cudaGetSymbolAddress((void**)&out1,  g_out1);
    cudaGetSymbolAddress((void**)&h2,    g_h2);
    cudaGetSymbolAddress((void**)&q2,    g_q2);
    cudaGetSymbolAddress((void**)&kvb,   g_kv);
    cudaGetSymbolAddress((void**)&vec2,  g_vec2);
    cudaGetSymbolAddress((void**)&out2,  g_out2);
    cudaGetSymbolAddress((void**)&c,     g_c);
    cudaGetSymbolAddress((void**)&t,     g_t);

    const int FR_SMEM = (4 * 4096 + 64 * 129 + 64 * 65) * (int)sizeof(float); // 115200
    const int FC_SMEM = (3 * 4096 + 64 * 65) * (int)sizeof(float);            // 65792
    cudaFuncSetAttribute(flash_rel_k, cudaFuncAttributeMaxDynamicSharedMemorySize, FR_SMEM);
    cudaFuncSetAttribute(flash_ctx_k, cudaFuncAttributeMaxDynamicSharedMemorySize, FC_SMEM);

    // ---- block 1: relative self-attention ----
    ln_k<<<ROWS, 128>>>(dec_inp, ln1_g, ln1_b, h);
    gemm_k<false><<<dim3(24, 128), 256>>>(h, qkv_w, nullptr, nullptr, heads, ROWS, 3 * DMODEL, DMODEL);
    gemm_k<false><<<dim3(8, 16),   256>>>(r, r_w,   nullptr, nullptr, rk,    QLEN, DMODEL, DMODEL);
    flash_rel_k<<<dim3(16, 64), 256, FR_SMEM>>>(heads, rk, rwb, rrb, vec);
    gemm_k<false><<<dim3(8, 128),  256>>>(vec, o_w, nullptr, dec_inp, out1, ROWS, DMODEL, DMODEL);

    // ---- block 2: cross attention (residual on normed h2) ----
    ln_k<<<ROWS, 128>>>(out1, ln2_g, ln2_b, h2);
    gemm_k<false><<<dim3(8, 128),  256>>>(h2, q_w, nullptr, nullptr, q2, ROWS, DMODEL, DMODEL);
    gemm_k<false><<<dim3(16, 128), 256>>>(enc_out, kv_w, nullptr, nullptr, kvb, ROWS, 2 * DMODEL, DMODEL);
    flash_ctx_k<<<dim3(16, 64), 256, FC_SMEM>>>(q2, kvb, emask, vec2);
    gemm_k<false><<<dim3(8, 128),  256>>>(vec2, o2_w, nullptr, h2, out2, ROWS, DMODEL, DMODEL);

    // ---- block 3: FF ----
    ln_k<<<ROWS, 128>>>(out2, ln3_g, ln3_b, c);
    gemm_k<true><<<dim3(32, 128),  256>>>(c, ff_w1, ff_b1, nullptr, t, ROWS, DINNER, DMODEL);
    gemm_k<false><<<dim3(8, 128),  256>>>(t, ff_w2, ff_b2, out2, out, ROWS, DMODEL, DINNER);
}

// round 3
// speedup vs baseline: 1.4957x; 1.4957x over previous
#include <cuda_runtime.h>
#include <cuda_bf16.h>
#include <cstdint>
#include <cstddef>

#define QLEN   1024
#define BATCH  8
#define DMODEL 512
#define NHEAD  8
#define DHEAD  64
#define DINNER 2048
#define ELEN   1024
#define ATT_SCALE 0.125f
#define ROWS (QLEN * BATCH)   /* 8192 */

// ===================== warp MMA helpers (sm_80+ PTX, valid on sm_103) =======
__device__ __forceinline__ uint32_t smem_u32(const void* p) {
    uint32_t a;
    asm("{ .reg .u64 t; cvta.to.shared.u64 t, %1; cvt.u32.u64 %0, t; }"
        : "=r"(a) : "l"(p));
    return a;
}

__device__ __forceinline__ void ldsm4(uint32_t* r, uint32_t addr) {
    asm volatile("ldmatrix.sync.aligned.m8n8.x4.shared.b16 {%0,%1,%2,%3}, [%4];"
                 : "=r"(r[0]), "=r"(r[1]), "=r"(r[2]), "=r"(r[3]) : "r"(addr));
}

__device__ __forceinline__ void mma16816(float* d, const uint32_t* a, const uint32_t* b) {
    asm volatile(
        "mma.sync.aligned.m16n8k16.row.col.f32.bf16.bf16.f32 "
        "{%0,%1,%2,%3}, {%4,%5,%6,%7}, {%8,%9}, {%0,%1,%2,%3};"
        : "+f"(d[0]), "+f"(d[1]), "+f"(d[2]), "+f"(d[3])
        : "r"(a[0]), "r"(a[1]), "r"(a[2]), "r"(a[3]), "r"(b[0]), "r"(b[1]));
}

// ===================== scratch ==============================================
__device__ float g_h    [ROWS * DMODEL];
__device__ float g_heads[ROWS * 3 * DMODEL];
__device__ float g_rk   [QLEN * DMODEL];
__device__ float g_vec  [ROWS * DMODEL];
__device__ float g_out1 [ROWS * DMODEL];
__device__ float g_h2   [ROWS * DMODEL];
__device__ float g_q2   [ROWS * DMODEL];
__device__ float g_kv   [ROWS * 2 * DMODEL];
__device__ float g_vec2 [ROWS * DMODEL];
__device__ float g_out2 [ROWS * DMODEL];
__device__ float g_c    [ROWS * DMODEL];
__device__ float g_t    [ROWS * DINNER];

__device__ __nv_bfloat16 g_ahi[ROWS * DINNER];
__device__ __nv_bfloat16 g_alo[ROWS * DINNER];
#define WT_QKV 0
#define WT_RW  786432
#define WT_OW  1048576
#define WT_QW  1310720
#define WT_KVW 1572864
#define WT_O2W 2097152
#define WT_FF1 2359296
#define WT_FF2 3407872
#define WT_TOTAL 4456448
__device__ __nv_bfloat16 g_wthi[WT_TOTAL];
__device__ __nv_bfloat16 g_wtlo[WT_TOTAL];

// ===================== split / transpose-split ===============================
__global__ __launch_bounds__(256) void split_k(const float* __restrict__ x,
                                               __nv_bfloat16* __restrict__ hi,
                                               __nv_bfloat16* __restrict__ lo, int n4)
{
    const int i = blockIdx.x * 256 + threadIdx.x;
    if (i >= n4) return;
    const float4 v = reinterpret_cast<const float4*>(x)[i];
    const __nv_bfloat16 h0 = __float2bfloat16(v.x);
    const __nv_bfloat16 h1 = __float2bfloat16(v.y);
    const __nv_bfloat16 h2 = __float2bfloat16(v.z);
    const __nv_bfloat16 h3 = __float2bfloat16(v.w);
    reinterpret_cast<__nv_bfloat162*>(hi)[i * 2 + 0] = __halves2bfloat162(h0, h1);
    reinterpret_cast<__nv_bfloat162*>(hi)[i * 2 + 1] = __halves2bfloat162(h2, h3);
    const __nv_bfloat16 l0 = __float2bfloat16(v.x - __bfloat162float(h0));
    const __nv_bfloat16 l1 = __float2bfloat16(v.y - __bfloat162float(h1));
    const __nv_bfloat16 l2 = __float2bfloat16(v.z - __bfloat162float(h2));
    const __nv_bfloat16 l3 = __float2bfloat16(v.w - __bfloat162float(h3));
    reinterpret_cast<__nv_bfloat162*>(lo)[i * 2 + 0] = __halves2bfloat162(l0, l1);
    reinterpret_cast<__nv_bfloat162*>(lo)[i * 2 + 1] = __halves2bfloat162(l2, l3);
}

// W[K,N] -> Wt_hi/lo[N,K]
__global__ __launch_bounds__(256) void tsplit_k(const float* __restrict__ W,
                                                __nv_bfloat16* __restrict__ hi,
                                                __nv_bfloat16* __restrict__ lo,
                                                int K, int N)
{
    __shared__ float t[32][33];
    const int n0 = blockIdx.x << 5, k0 = blockIdx.y << 5;
    const int x = threadIdx.x & 31, y = threadIdx.x >> 5;
    #pragma unroll
    for (int i = 0; i < 32; i += 8)
        t[y + i][x] = W[(size_t)(k0 + y + i) * N + n0 + x];
    __syncthreads();
    #pragma unroll
    for (int i = 0; i < 32; i += 8) {
        const float v = t[x][y + i];
        const size_t o = (size_t)(n0 + y + i) * K + k0 + x;
        const __nv_bfloat16 h = __float2bfloat16(v);
        hi[o] = h;
        lo[o] = __float2bfloat16(v - __bfloat162float(h));
    }
}

// ===================== HMMA GEMM ============================================
// C[M,N] = A[M,K]@Bt[N,K]^T; split-bf16 3-term; 128x128 CTA tile, K-chunk 64.
// smem tiles [128][72] bf16 (144B row stride -> conflict-free ldmatrix)
#define TS_A_HI 0
#define TS_A_LO 18432
#define TS_B_HI 36864
#define TS_B_LO 55296
#define GH_SMEM 73728

template <bool GELU>
__global__ __launch_bounds__(256) void gemm_hmma(const __nv_bfloat16* __restrict__ Ahi,
                                                 const __nv_bfloat16* __restrict__ Alo,
                                                 const __nv_bfloat16* __restrict__ Bhi,
                                                 const __nv_bfloat16* __restrict__ Blo,
                                                 const float* __restrict__ bias,
                                                 const float* __restrict__ res,
                                                 float* __restrict__ C,
                                                 int M, int N, int K)
{
    extern __shared__ char smem[];
    const uint32_t sb = smem_u32(smem);
    const int tid = threadIdx.x;
    const int lane = tid & 31, wid = tid >> 5;
    const int m0 = blockIdx.y << 7, n0 = blockIdx.x << 7;
    const int wm = (wid & 3) << 5;    // warp rows [wm, wm+32)
    const int wn = (wid >> 2) << 6;   // warp cols [wn, wn+64)
    (void)M;

    float acc[2][8][4];
    #pragma unroll
    for (int mt = 0; mt < 2; mt++)
        #pragma unroll
        for (int nt = 0; nt < 8; nt++)
            #pragma unroll
            for (int e = 0; e < 4; e++) acc[mt][nt][e] = 0.0f;

    const int lr = lane & 7, lg = lane >> 3;
    // ldmatrix source addresses (byte offsets within a [128][72] bf16 tile)
    // A 16x16 tile at (row base R, k base kk):
    //   g0:(R+lr,kk) g1:(R+8+lr,kk) g2:(R+lr,kk+8) g3:(R+8+lr,kk+8)
    const uint32_t a_off = (uint32_t)(((lg & 1) << 3) + lr) * 144u + (uint32_t)((lg >> 1) << 4);
    // B pair tile at (n base Nb, k base kk):
    //   g0:(Nb+lr,kk) g1:(Nb+lr,kk+8) g2:(Nb+8+lr,kk) g3:(Nb+8+lr,kk+8)
    const uint32_t b_off = (uint32_t)(((lg >> 1) << 3) + lr) * 144u + (uint32_t)((lg & 1) << 4);

    const int nch = K >> 6;
    for (int c = 0; c < nch; c++) {
        const int k0 = c << 6;
        __syncthreads();
        #pragma unroll 4
        for (int i = tid; i < 1024; i += 256) {
            const int r = i >> 3, kc = (i & 7) << 3;       // 8 bf16 = 16B units
            const uint32_t so = (uint32_t)(r * 144 + kc * 2);
            const size_t ga = (size_t)(m0 + r) * K + k0 + kc;
            const size_t gb = (size_t)(n0 + r) * K + k0 + kc;
            *reinterpret_cast<uint4*>(smem + TS_A_HI + so) =
                *reinterpret_cast<const uint4*>(Ahi + ga);
            *reinterpret_cast<uint4*>(smem + TS_A_LO + so) =
                *reinterpret_cast<const uint4*>(Alo + ga);
            *reinterpret_cast<uint4*>(smem + TS_B_HI + so) =
                *reinterpret_cast<const uint4*>(Bhi + gb);
            *reinterpret_cast<uint4*>(smem + TS_B_LO + so) =
                *reinterpret_cast<const uint4*>(Blo + gb);
        }
        __syncthreads();

        #pragma unroll
        for (int ks = 0; ks < 4; ks++) {
            const uint32_t kk2 = (uint32_t)(ks << 5);      // k offset in bytes (16 bf16)
            uint32_t ah[2][4], al[2][4];
            #pragma unroll
            for (int mt = 0; mt < 2; mt++) {
                const uint32_t ra = (uint32_t)((wm + (mt << 4)) * 144) + kk2 + a_off;
                ldsm4(ah[mt], sb + TS_A_HI + ra);
                ldsm4(al[mt], sb + TS_A_LO + ra);
            }
            #pragma unroll
            for (int np = 0; np < 4; np++) {
                uint32_t bh[4], bl[4];
                const uint32_t rb = (uint32_t)((wn + (np << 4)) * 144) + kk2 + b_off;
                ldsm4(bh, sb + TS_B_HI + rb);
                ldsm4(bl, sb + TS_B_LO + rb);
                #pragma unroll
                for (int mt = 0; mt < 2; mt++) {
                    #pragma unroll
                    for (int hf = 0; hf < 2; hf++) {
                        float* d = acc[mt][(np << 1) + hf];
                        mma16816(d, ah[mt], bh + (hf << 1));
                        mma16816(d, ah[mt], bl + (hf << 1));
                        mma16816(d, al[mt], bh + (hf << 1));
                    }
                }
            }
        }
    }

    // epilogue: d frag lane mapping: (row lane/4 [+8], col 2*(lane%4)+{0,1})
    const int er = lane >> 2, ec = (lane & 3) << 1;
    #pragma unroll
    for (int mt = 0; mt < 2; mt++) {
        #pragma unroll
        for (int half = 0; half < 2; half++) {
            const int gr = m0 + wm + (mt << 4) + er + (half << 3);
            #pragma unroll
            for (int nt = 0; nt < 8; nt++) {
                const int gc = n0 + wn + (nt << 3) + ec;
                float v0 = acc[mt][nt][(half << 1) + 0];
                float v1 = acc[mt][nt][(half << 1) + 1];
                if (bias) { v0 += bias[gc]; v1 += bias[gc + 1]; }
                if (GELU) {
                    v0 = 0.5f * v0 * (1.0f + erff(v0 * 0.70710678118654752f));
                    v1 = 0.5f * v1 * (1.0f + erff(v1 * 0.70710678118654752f));
                }
                if (res) {
                    const float2 rr = *reinterpret_cast<const float2*>(&res[(size_t)gr * N + gc]);
                    v0 += rr.x; v1 += rr.y;
                }
                *reinterpret_cast<float2*>(&C[(size_t)gr * N + gc]) = make_float2(v0, v1);
            }
        }
    }
}

// ===================== LayerNorm ============================================
__global__ __launch_bounds__(128) void ln_k(const float* __restrict__ x,
                                            const float* __restrict__ g,
                                            const float* __restrict__ b,
                                            float* __restrict__ y)
{
    const int row = blockIdx.x;
    const int t = threadIdx.x;
    const float4 v = reinterpret_cast<const float4*>(x + (size_t)row * DMODEL)[t];
    float s  = v.x + v.y + v.z + v.w;
    float sq = v.x*v.x + v.y*v.y + v.z*v.z + v.w*v.w;
    #pragma unroll
    for (int o = 16; o; o >>= 1) {
        s  += __shfl_xor_sync(0xffffffffu, s,  o);
        sq += __shfl_xor_sync(0xffffffffu, sq, o);
    }
    __shared__ float ss[4], sqq[4];
    const int w = t >> 5, lane = t & 31;
    if (lane == 0) { ss[w] = s; sqq[w] = sq; }
    __syncthreads();
    s  = ss[0]  + ss[1]  + ss[2]  + ss[3];
    sq = sqq[0] + sqq[1] + sqq[2] + sqq[3];
    const float mean = s * (1.0f / DMODEL);
    const float var  = sq * (1.0f / DMODEL) - mean * mean;
    const float rstd = rsqrtf(var + 1e-5f);
    const float4 gg = reinterpret_cast<const float4*>(g)[t];
    const float4 bb = reinterpret_cast<const float4*>(b)[t];
    float4 o4;
    o4.x = (v.x - mean) * rstd * gg.x + bb.x;
    o4.y = (v.y - mean) * rstd * gg.y + bb.y;
    o4.z = (v.z - mean) * rstd * gg.z + bb.z;
    o4.w = (v.w - mean) * rstd * gg.w + bb.w;
    reinterpret_cast<float4*>(y + (size_t)row * DMODEL)[t] = o4;
}

// ===================== flash attention 1 (rel, causal) ======================
__global__ __launch_bounds__(256) void flash_rel_k(const float* __restrict__ heads,
                                                   const float* __restrict__ rk,
                                                   const float* __restrict__ rwb,
                                                   const float* __restrict__ rrb,
                                                   float* __restrict__ vec)
{
    extern __shared__ float sm[];
    float* qw  = sm;               // [64][64] d-major (q + rwb)
    float* kt  = qw + 4096;        // [64][64] d-major
    float* vt  = kt + 4096;        // [64][64] j-major
    float* rks = vt + 4096;        // [64][129] d-major, padded
    float* ps  = rks + 64 * 129;   // [64][65]
    __shared__ float dbias[64];    // rrb - rwb per d

    const int tid = threadIdx.x;
    const int tx = tid & 15, ty = tid >> 4;
    const int i0 = blockIdx.x << 6;
    const int b  = blockIdx.y >> 3, n = blockIdx.y & 7;

    if (tid < 64) dbias[tid] = rrb[n * 64 + tid] - rwb[n * 64 + tid];
    for (int t = tid; t < 4096; t += 256) {
        const int i = t >> 6, d = t & 63;
        const float qv = heads[((size_t)(i0 + i) * BATCH + b) * (3 * DMODEL) + n * 64 + d];
        qw[d * 64 + i] = qv + rwb[n * 64 + d];
    }

    float m_i[4], l_i[4], o[4][4];
    #pragma unroll
    for (int u = 0; u < 4; u++) {
        m_i[u] = -1e30f; l_i[u] = 0.0f;
        #pragma unroll
        for (int v = 0; v < 4; v++) o[u][v] = 0.0f;
    }

    for (int j0 = 0; j0 <= i0; j0 += 64) {
        __syncthreads();
        for (int t = tid; t < 4096; t += 256) {
            const int j = t >> 6, d = t & 63;
            const size_t base = ((size_t)(j0 + j) * BATCH + b) * (3 * DMODEL) + n * 64 + d;
            kt[d * 64 + j] = heads[base + DMODEL];
            vt[j * 64 + d] = heads[base + 2 * DMODEL];
        }
        const int m_base = 960 + j0 - i0;
        for (int t = tid; t < 127 * 64; t += 256) {
            const int ml = t >> 6, d = t & 63;
            const int m = m_base + ml;
            rks[d * 129 + ml] = (m <= QLEN - 1) ? rk[(size_t)m * DMODEL + n * 64 + d] : 0.0f;
        }
        __syncthreads();

        float s[4][4] = {};
        #pragma unroll 8
        for (int d = 0; d < 64; d++) {
            const float4 a0 = *reinterpret_cast<const float4*>(&qw[d * 64 + (ty << 2)]);
            const float4 kf = *reinterpret_cast<const float4*>(&kt[d * 64 + (tx << 2)]);
            const float db = dbias[d];
            const float aw[4] = {a0.x, a0.y, a0.z, a0.w};
            const float kk[4] = {kf.x, kf.y, kf.z, kf.w};
            #pragma unroll
            for (int u = 0; u < 4; u++) {
                const float ar = aw[u] + db;
                const int mlb = (tx << 2) - (ty << 2) - u + 63;
                #pragma unroll
                for (int v = 0; v < 4; v++) {
                    s[u][v] = fmaf(aw[u], kk[v], s[u][v]);
                    s[u][v] = fmaf(ar, rks[d * 129 + mlb + v], s[u][v]);
                }
            }
        }

        #pragma unroll
        for (int u = 0; u < 4; u++) {
            const int gi = i0 + (ty << 2) + u;
            float rmax = -1e30f;
            #pragma unroll
            for (int v = 0; v < 4; v++) {
                const int gj = j0 + (tx << 2) + v;
                s[u][v] = (gj > gi) ? -1e30f : s[u][v] * ATT_SCALE;
                rmax = fmaxf(rmax, s[u][v]);
            }
            #pragma unroll
            for (int off = 1; off < 16; off <<= 1)
                rmax = fmaxf(rmax, __shfl_xor_sync(0xffffffffu, rmax, off));
            const float m_new = fmaxf(m_i[u], rmax);
            const float alpha = __expf(m_i[u] - m_new);
            float rsum = 0.0f;
            #pragma unroll
            for (int v = 0; v < 4; v++) {
                const float p = __expf(s[u][v] - m_new);
                s[u][v] = p; rsum += p;
            }
            #pragma unroll
            for (int off = 1; off < 16; off <<= 1)
                rsum += __shfl_xor_sync(0xffffffffu, rsum, off);
            l_i[u] = l_i[u] * alpha + rsum;
            m_i[u] = m_new;
            #pragma unroll
            for (int v = 0; v < 4; v++) o[u][v] *= alpha;
        }

        #pragma unroll
        for (int u = 0; u < 4; u++)
            #pragma unroll
            for (int v = 0; v < 4; v++)
                ps[((tx << 2) + v) * 65 + (ty << 2) + u] = s[u][v];
        __syncthreads();

        #pragma unroll 8
        for (int jd = 0; jd < 64; jd++) {
            float pf[4];
            #pragma unroll
            for (int u = 0; u < 4; u++) pf[u] = ps[jd * 65 + (ty << 2) + u];
            const float4 vf = *reinterpret_cast<const float4*>(&vt[jd * 64 + (tx << 2)]);
            const float vv[4] = {vf.x, vf.y, vf.z, vf.w};
            #pragma unroll
            for (int u = 0; u < 4; u++)
                #pragma unroll
                for (int v = 0; v < 4; v++)
                    o[u][v] = fmaf(pf[u], vv[v], o[u][v]);
        }
    }

    #pragma unroll
    for (int u = 0; u < 4; u++) {
        const float inv = 1.0f / l_i[u];
        const int gi = i0 + (ty << 2) + u;
        #pragma unroll
        for (int v = 0; v < 4; v++)
            vec[((size_t)gi * BATCH + b) * DMODEL + n * 64 + (tx << 2) + v] = o[u][v] * inv;
    }
}

// ===================== flash attention 2 (cross) =============================
__global__ __launch_bounds__(256) void flash_ctx_k(const float* __restrict__ q2,
                                                   const float* __restrict__ kv,
                                                   const unsigned char* __restrict__ emask,
                                                   float* __restrict__ vec2)
{
    extern __shared__ float sm[];
    float* qt = sm;
    float* kt = qt + 4096;
    float* vt = kt + 4096;
    float* ps = vt + 4096;

    const int tid = threadIdx.x;
    const int tx = tid & 15, ty = tid >> 4;
    const int i0 = blockIdx.x << 6;
    const int b  = blockIdx.y >> 3, n = blockIdx.y & 7;

    for (int t = tid; t < 4096; t += 256) {
        const int i = t >> 6, d = t & 63;
        qt[d * 64 + i] = q2[((size_t)(i0 + i) * BATCH + b) * DMODEL + n * 64 + d];
    }

    float m_i[4], l_i[4], o[4][4];
    #pragma unroll
    for (int u = 0; u < 4; u++) {
        m_i[u] = -1e30f; l_i[u] = 0.0f;
        #pragma unroll
        for (int v = 0; v < 4; v++) o[u][v] = 0.0f;
    }

    for (int j0 = 0; j0 < ELEN; j0 += 64) {
        __syncthreads();
        for (int t = tid; t < 4096; t += 256) {
            const int j = t >> 6, d = t & 63;
            const size_t base = ((size_t)(j0 + j) * BATCH + b) * (2 * DMODEL) + n * 64 + d;
            kt[d * 64 + j] = kv[base];
            vt[j * 64 + d] = kv[base + DMODEL];
        }
        __syncthreads();

        float s[4][4] = {};
        #pragma unroll 8
        for (int d = 0; d < 64; d++) {
            const float4 a0 = *reinterpret_cast<const float4*>(&qt[d * 64 + (ty << 2)]);
            const float4 kf = *reinterpret_cast<const float4*>(&kt[d * 64 + (tx << 2)]);
            const float aq[4] = {a0.x, a0.y, a0.z, a0.w};
            const float kk[4] = {kf.x, kf.y, kf.z, kf.w};
            #pragma unroll
            for (int u = 0; u < 4; u++)
                #pragma unroll
                for (int v = 0; v < 4; v++)
                    s[u][v] = fmaf(aq[u], kk[v], s[u][v]);
        }

        float mk[4];
        #pragma unroll
        for (int v = 0; v < 4; v++)
            mk[v] = emask[(size_t)(j0 + (tx << 2) + v) * BATCH + b] ? 1.0f : 0.0f;

        #pragma unroll
        for (int u = 0; u < 4; u++) {
            float rmax = -1e30f;
            #pragma unroll
            for (int v = 0; v < 4; v++) {
                s[u][v] = (mk[v] != 0.0f) ? -1e4f : s[u][v] * ATT_SCALE;
                rmax = fmaxf(rmax, s[u][v]);
            }
            #pragma unroll
            for (int off = 1; off < 16; off <<= 1)
                rmax = fmaxf(rmax, __shfl_xor_sync(0xffffffffu, rmax, off));
            const float m_new = fmaxf(m_i[u], rmax);
            const float alpha = __expf(m_i[u] - m_new);
            float rsum = 0.0f;
            #pragma unroll
            for (int v = 0; v < 4; v++) {
                const float p = __expf(s[u][v] - m_new);
                s[u][v] = p; rsum += p;
            }
            #pragma unroll
            for (int off = 1; off < 16; off <<= 1)
                rsum += __shfl_xor_sync(0xffffffffu, rsum, off);
            l_i[u] = l_i[u] * alpha + rsum;
            m_i[u] = m_new;
            #pragma unroll
            for (int v = 0; v < 4; v++) o[u][v] *= alpha;
        }

        #pragma unroll
        for (int u = 0; u < 4; u++)
            #pragma unroll
            for (int v = 0; v < 4; v++)
                ps[((tx << 2) + v) * 65 + (ty << 2) + u] = s[u][v];
        __syncthreads();

        #pragma unroll 8
        for (int jd = 0; jd < 64; jd++) {
            float pf[4];
            #pragma unroll
            for (int u = 0; u < 4; u++) pf[u] = ps[jd * 65 + (ty << 2) + u];
            const float4 vf = *reinterpret_cast<const float4*>(&vt[jd * 64 + (tx << 2)]);
            const float vv[4] = {vf.x, vf.y, vf.z, vf.w};
            #pragma unroll
            for (int u = 0; u < 4; u++)
                #pragma unroll
                for (int v = 0; v < 4; v++)
                    o[u][v] = fmaf(pf[u], vv[v], o[u][v]);
        }
    }

    #pragma unroll
    for (int u = 0; u < 4; u++) {
        const float inv = 1.0f / l_i[u];
        const int gi = i0 + (ty << 2) + u;
        #pragma unroll
        for (int v = 0; v < 4; v++)
            vec2[((size_t)gi * BATCH + b) * DMODEL + n * 64 + (tx << 2) + v] = o[u][v] * inv;
    }
}

// ===================== host orchestration ====================================
static inline void launch_gemm(const __nv_bfloat16* ahi, const __nv_bfloat16* alo,
                               const __nv_bfloat16* bhi, const __nv_bfloat16* blo,
                               const float* bias, const float* res, float* C,
                               int M, int N, int K, bool gelu)
{
    dim3 grid(N / 128, M / 128);
    if (gelu)
        gemm_hmma<true><<<grid, 256, GH_SMEM>>>(ahi, alo, bhi, blo, bias, res, C, M, N, K);
    else
        gemm_hmma<false><<<grid, 256, GH_SMEM>>>(ahi, alo, bhi, blo, bias, res, C, M, N, K);
}

extern "C" void kernel_launch(void* const* d_in, const int* in_sizes, int n_in,
                              void* d_out, int out_size)
{
    (void)in_sizes; (void)n_in; (void)out_size;
    const float* dec_inp = (const float*)d_in[0];
    const float* r       = (const float*)d_in[1];
    const float* enc_out = (const float*)d_in[2];
    const float* rwb     = (const float*)d_in[3];
    const float* rrb     = (const float*)d_in[4];
    const float* qkv_w   = (const float*)d_in[5];
    const float* r_w     = (const float*)d_in[6];
    const float* o_w     = (const float*)d_in[7];
    const float* ln1_g   = (const float*)d_in[8];
    const float* ln1_b   = (const float*)d_in[9];
    const float* q_w     = (const float*)d_in[10];
    const float* kv_w    = (const float*)d_in[11];
    const float* o2_w    = (const float*)d_in[12];
    const float* ln2_g   = (const float*)d_in[13];
    const float* ln2_b   = (const float*)d_in[14];
    const float* ff_w1   = (const float*)d_in[15];
    const float* ff_b1   = (const float*)d_in[16];
    const float* ff_w2   = (const float*)d_in[17];
    const float* ff_b2   = (const float*)d_in[18];
    const float* ln3_g   = (const float*)d_in[19];
    const float* ln3_b   = (const float*)d_in[20];
    const unsigned char* emask = (const unsigned char*)d_in[22];
    float* out = (float*)d_out;

    float *h, *heads, *rk, *vec, *out1, *h2, *q2, *kvb, *vec2, *out2, *c, *t;
    __nv_bfloat16 *ahi, *alo, *wthi, *wtlo;
    cudaGetSymbolAddress((void**)&h,     g_h);
    cudaGetSymbolAddress((void**)&heads, g_heads);
    cudaGetSymbolAddress((void**)&rk,    g_rk);
    cudaGetSymbolAddress((void**)&vec,   g_vec);
    cudaGetSymbolAddress((void**)&out1,  g_out1);
    cudaGetSymbolAddress((void**)&h2,    g_h2);
    cudaGetSymbolAddress((void**)&q2,    g_q2);
    cudaGetSymbolAddress((void**)&kvb,   g_kv);
    cudaGetSymbolAddress((void**)&vec2,  g_vec2);
    cudaGetSymbolAddress((void**)&out2,  g_out2);
    cudaGetSymbolAddress((void**)&c,     g_c);
    cudaGetSymbolAddress((void**)&t,     g_t);
    cudaGetSymbolAddress((void**)&ahi,   g_ahi);
    cudaGetSymbolAddress((void**)&alo,   g_alo);
    cudaGetSymbolAddress((void**)&wthi,  g_wthi);
    cudaGetSymbolAddress((void**)&wtlo,  g_wtlo);

    const int FR_SMEM = (3 * 4096 + 64 * 129 + 64 * 65) * (int)sizeof(float); // 98816
    const int FC_SMEM = (3 * 4096 + 64 * 65) * (int)sizeof(float);            // 65792
    cudaFuncSetAttribute(flash_rel_k, cudaFuncAttributeMaxDynamicSharedMemorySize, FR_SMEM);
    cudaFuncSetAttribute(flash_ctx_k, cudaFuncAttributeMaxDynamicSharedMemorySize, FC_SMEM);
    cudaFuncSetAttribute(gemm_hmma<false>, cudaFuncAttributeMaxDynamicSharedMemorySize, GH_SMEM);
    cudaFuncSetAttribute(gemm_hmma<true>,  cudaFuncAttributeMaxDynamicSharedMemorySize, GH_SMEM);

    // ---- weight transpose+split (inputs only; run up front) ----
    tsplit_k<<<dim3(48, 16), 256>>>(qkv_w, wthi + WT_QKV, wtlo + WT_QKV, 512, 1536);
    tsplit_k<<<dim3(16, 16), 256>>>(r_w,   wthi + WT_RW,  wtlo + WT_RW,  512, 512);
    tsplit_k<<<dim3(16, 16), 256>>>(o_w,   wthi + WT_OW,  wtlo + WT_OW,  512, 512);
    tsplit_k<<<dim3(16, 16), 256>>>(q_w,   wthi + WT_QW,  wtlo + WT_QW,  512, 512);
    tsplit_k<<<dim3(32, 16), 256>>>(kv_w,  wthi + WT_KVW, wtlo + WT_KVW, 512, 1024);
    tsplit_k<<<dim3(16, 16), 256>>>(o2_w,  wthi + WT_O2W, wtlo + WT_O2W, 512, 512);
    tsplit_k<<<dim3(64, 16), 256>>>(ff_w1, wthi + WT_FF1, wtlo + WT_FF1, 512, 2048);
    tsplit_k<<<dim3(16, 64), 256>>>(ff_w2, wthi + WT_FF2, wtlo + WT_FF2, 2048, 512);

    // ---- block 1: relative self-attention ----
    ln_k<<<ROWS, 128>>>(dec_inp, ln1_g, ln1_b, h);
    split_k<<<ROWS * DMODEL / 1024, 256>>>(h, ahi, alo, ROWS * DMODEL / 4);
    launch_gemm(ahi, alo, wthi + WT_QKV, wtlo + WT_QKV, nullptr, nullptr, heads,
                ROWS, 3 * DMODEL, DMODEL, false);
    split_k<<<QLEN * DMODEL / 1024, 256>>>(r, ahi, alo, QLEN * DMODEL / 4);
    launch_gemm(ahi, alo, wthi + WT_RW, wtlo + WT_RW, nullptr, nullptr, rk,
                QLEN, DMODEL, DMODEL, false);
    flash_rel_k<<<dim3(16, 64), 256, FR_SMEM>>>(heads, rk, rwb, rrb, vec);
    split_k<<<ROWS * DMODEL / 1024, 256>>>(vec, ahi, alo, ROWS * DMODEL / 4);
    launch_gemm(ahi, alo, wthi + WT_OW, wtlo + WT_OW, nullptr, dec_inp, out1,
                ROWS, DMODEL, DMODEL, false);

    // ---- block 2: cross attention ----
    ln_k<<<ROWS, 128>>>(out1, ln2_g, ln2_b, h2);
    split_k<<<ROWS * DMODEL / 1024, 256>>>(h2, ahi, alo, ROWS * DMODEL / 4);
    launch_gemm(ahi, alo, wthi + WT_QW, wtlo + WT_QW, nullptr, nullptr, q2,
                ROWS, DMODEL, DMODEL, false);
    split_k<<<ROWS * DMODEL / 1024, 256>>>(enc_out, ahi, alo, ROWS * DMODEL / 4);
    launch_gemm(ahi, alo, wthi + WT_KVW, wtlo + WT_KVW, nullptr, nullptr, kvb,
                ROWS, 2 * DMODEL, DMODEL, false);
    flash_ctx_k<<<dim3(16, 64), 256, FC_SMEM>>>(q2, kvb, emask, vec2);
    split_k<<<ROWS * DMODEL / 1024, 256>>>(vec2, ahi, alo, ROWS * DMODEL / 4);
    launch_gemm(ahi, alo, wthi + WT_O2W, wtlo + WT_O2W, nullptr, h2, out2,
                ROWS, DMODEL, DMODEL, false);

    // ---- block 3: FF ----
    ln_k<<<ROWS, 128>>>(out2, ln3_g, ln3_b, c);
    split_k<<<ROWS * DMODEL / 1024, 256>>>(c, ahi, alo, ROWS * DMODEL / 4);
    launch_gemm(ahi, alo, wthi + WT_FF1, wtlo + WT_FF1, ff_b1, nullptr, t,
                ROWS, DINNER, DMODEL, true);
    split_k<<<ROWS * DINNER / 1024, 256>>>(t, ahi, alo, ROWS * DINNER / 4);
    launch_gemm(ahi, alo, wthi + WT_FF2, wtlo + WT_FF2, ff_b2, out2, out,
                ROWS, DMODEL, DINNER, false);
}

// round 5
// speedup vs baseline: 2.1013x; 1.4049x over previous
#include <cuda_runtime.h>
#include <cuda_bf16.h>
#include <cstdint>
#include <cstddef>

#define QLEN   1024
#define BATCH  8
#define DMODEL 512
#define NHEAD  8
#define DHEAD  64
#define DINNER 2048
#define ELEN   1024
#define ATT_SCALE 0.125f
#define ROWS (QLEN * BATCH)   /* 8192 */

// ===================== warp MMA helpers (sm_80+ PTX, valid on sm_103) =======
__device__ __forceinline__ uint32_t smem_u32(const void* p) {
    uint32_t a;
    asm("{ .reg .u64 t; cvta.to.shared.u64 t, %1; cvt.u32.u64 %0, t; }"
        : "=r"(a) : "l"(p));
    return a;
}

__device__ __forceinline__ void ldsm4(uint32_t* r, uint32_t addr) {
    asm volatile("ldmatrix.sync.aligned.m8n8.x4.shared.b16 {%0,%1,%2,%3}, [%4];"
                 : "=r"(r[0]), "=r"(r[1]), "=r"(r[2]), "=r"(r[3]) : "r"(addr));
}

__device__ __forceinline__ void mma16816(float* d, const uint32_t* a, const uint32_t* b) {
    asm volatile(
        "mma.sync.aligned.m16n8k16.row.col.f32.bf16.bf16.f32 "
        "{%0,%1,%2,%3}, {%4,%5,%6,%7}, {%8,%9}, {%0,%1,%2,%3};"
        : "+f"(d[0]), "+f"(d[1]), "+f"(d[2]), "+f"(d[3])
        : "r"(a[0]), "r"(a[1]), "r"(a[2]), "r"(a[3]), "r"(b[0]), "r"(b[1]));
}

// 3-term split-bf16 warp GEMM: acc[8][4] += Ahi@(Bhi+Blo)^T + Alo@Bhi^T
// A base addrs already include the warp-row offset; tiles are [rows][72] bf16,
// 144-byte row stride; K = 64 (4 k-steps).
__device__ __forceinline__ void wgemm3(uint32_t Ah, uint32_t Al,
                                       uint32_t Bh, uint32_t Bl,
                                       uint32_t a_off, uint32_t b_off,
                                       float acc[8][4])
{
    #pragma unroll
    for (int ks = 0; ks < 4; ks++) {
        const uint32_t ra = (uint32_t)(ks << 5);
        uint32_t ah[4], al[4];
        ldsm4(ah, Ah + ra + a_off);
        ldsm4(al, Al + ra + a_off);
        #pragma unroll
        for (int np = 0; np < 4; np++) {
            uint32_t bh[4], bl[4];
            const uint32_t rb = (uint32_t)(np * 16 * 144 + (ks << 5));
            ldsm4(bh, Bh + rb + b_off);
            ldsm4(bl, Bl + rb + b_off);
            #pragma unroll
            for (int hf = 0; hf < 2; hf++) {
                float* d = acc[(np << 1) + hf];
                mma16816(d, ah, bh + (hf << 1));
                mma16816(d, ah, bl + (hf << 1));
                mma16816(d, al, bh + (hf << 1));
            }
        }
    }
}

__device__ __forceinline__ void split_store4(char* hi, char* lo, float4 v) {
    const __nv_bfloat16 h0 = __float2bfloat16(v.x), h1 = __float2bfloat16(v.y);
    const __nv_bfloat16 h2 = __float2bfloat16(v.z), h3 = __float2bfloat16(v.w);
    *(__nv_bfloat162*)(hi)     = __halves2bfloat162(h0, h1);
    *(__nv_bfloat162*)(hi + 4) = __halves2bfloat162(h2, h3);
    *(__nv_bfloat162*)(lo)     = __halves2bfloat162(
        __float2bfloat16(v.x - __bfloat162float(h0)),
        __float2bfloat16(v.y - __bfloat162float(h1)));
    *(__nv_bfloat162*)(lo + 4) = __halves2bfloat162(
        __float2bfloat16(v.z - __bfloat162float(h2)),
        __float2bfloat16(v.w - __bfloat162float(h3)));
}

__device__ __forceinline__ void split_store1(char* hi, char* lo, float x) {
    const __nv_bfloat16 h = __float2bfloat16(x);
    *(__nv_bfloat16*)hi = h;
    *(__nv_bfloat16*)lo = __float2bfloat16(x - __bfloat162float(h));
}

// ===================== scratch ==============================================
__device__ float g_h    [ROWS * DMODEL];
__device__ float g_heads[ROWS * 3 * DMODEL];
__device__ float g_rk   [QLEN * DMODEL];
__device__ float g_vec  [ROWS * DMODEL];
__device__ float g_out1 [ROWS * DMODEL];
__device__ float g_h2   [ROWS * DMODEL];
__device__ float g_q2   [ROWS * DMODEL];
__device__ float g_kv   [ROWS * 2 * DMODEL];
__device__ float g_vec2 [ROWS * DMODEL];
__device__ float g_out2 [ROWS * DMODEL];
__device__ float g_c    [ROWS * DMODEL];
__device__ float g_t    [ROWS * DINNER];

__device__ __nv_bfloat16 g_ahi[ROWS * DINNER];
__device__ __nv_bfloat16 g_alo[ROWS * DINNER];
#define WT_QKV 0
#define WT_RW  786432
#define WT_OW  1048576
#define WT_QW  1310720
#define WT_KVW 1572864
#define WT_O2W 2097152
#define WT_FF1 2359296
#define WT_FF2 3407872
#define WT_TOTAL 4456448
__device__ __nv_bfloat16 g_wthi[WT_TOTAL];
__device__ __nv_bfloat16 g_wtlo[WT_TOTAL];

// ===================== split / transpose-split ===============================
__global__ __launch_bounds__(256) void split_k(const float* __restrict__ x,
                                               __nv_bfloat16* __restrict__ hi,
                                               __nv_bfloat16* __restrict__ lo, int n4)
{
    const int i = blockIdx.x * 256 + threadIdx.x;
    if (i >= n4) return;
    const float4 v = reinterpret_cast<const float4*>(x)[i];
    split_store4((char*)(hi + (size_t)i * 4), (char*)(lo + (size_t)i * 4), v);
}

// W[K,N] -> Wt_hi/lo[N,K]
__global__ __launch_bounds__(256) void tsplit_k(const float* __restrict__ W,
                                                __nv_bfloat16* __restrict__ hi,
                                                __nv_bfloat16* __restrict__ lo,
                                                int K, int N)
{
    __shared__ float t[32][33];
    const int n0 = blockIdx.x << 5, k0 = blockIdx.y << 5;
    const int x = threadIdx.x & 31, y = threadIdx.x >> 5;
    #pragma unroll
    for (int i = 0; i < 32; i += 8)
        t[y + i][x] = W[(size_t)(k0 + y + i) * N + n0 + x];
    __syncthreads();
    #pragma unroll
    for (int i = 0; i < 32; i += 8) {
        const float v = t[x][y + i];
        const size_t o = (size_t)(n0 + y + i) * K + k0 + x;
        const __nv_bfloat16 h = __float2bfloat16(v);
        hi[o] = h;
        lo[o] = __float2bfloat16(v - __bfloat162float(h));
    }
}

// ===================== HMMA GEMM ============================================
#define TS_A_HI 0
#define TS_A_LO 18432
#define TS_B_HI 36864
#define TS_B_LO 55296
#define GH_SMEM 73728

template <bool GELU>
__global__ __launch_bounds__(256) void gemm_hmma(const __nv_bfloat16* __restrict__ Ahi,
                                                 const __nv_bfloat16* __restrict__ Alo,
                                                 const __nv_bfloat16* __restrict__ Bhi,
                                                 const __nv_bfloat16* __restrict__ Blo,
                                                 const float* __restrict__ bias,
                                                 const float* __restrict__ res,
                                                 float* __restrict__ C,
                                                 int M, int N, int K)
{
    extern __shared__ char smem[];
    const uint32_t sb = smem_u32(smem);
    const int tid = threadIdx.x;
    const int lane = tid & 31, wid = tid >> 5;
    const int m0 = blockIdx.y << 7, n0 = blockIdx.x << 7;
    const int wm = (wid & 3) << 5;
    const int wn = (wid >> 2) << 6;
    (void)M;

    float acc[2][8][4];
    #pragma unroll
    for (int mt = 0; mt < 2; mt++)
        #pragma unroll
        for (int nt = 0; nt < 8; nt++)
            #pragma unroll
            for (int e = 0; e < 4; e++) acc[mt][nt][e] = 0.0f;

    const int lr = lane & 7, lg = lane >> 3;
    const uint32_t a_off = (uint32_t)(((lg & 1) << 3) + lr) * 144u + (uint32_t)((lg >> 1) << 4);
    const uint32_t b_off = (uint32_t)(((lg >> 1) << 3) + lr) * 144u + (uint32_t)((lg & 1) << 4);

    const int nch = K >> 6;
    for (int c = 0; c < nch; c++) {
        const int k0 = c << 6;
        __syncthreads();
        #pragma unroll 4
        for (int i = tid; i < 1024; i += 256) {
            const int r = i >> 3, kc = (i & 7) << 3;
            const uint32_t so = (uint32_t)(r * 144 + kc * 2);
            const size_t ga = (size_t)(m0 + r) * K + k0 + kc;
            const size_t gb = (size_t)(n0 + r) * K + k0 + kc;
            *reinterpret_cast<uint4*>(smem + TS_A_HI + so) =
                *reinterpret_cast<const uint4*>(Ahi + ga);
            *reinterpret_cast<uint4*>(smem + TS_A_LO + so) =
                *reinterpret_cast<const uint4*>(Alo + ga);
            *reinterpret_cast<uint4*>(smem + TS_B_HI + so) =
                *reinterpret_cast<const uint4*>(Bhi + gb);
            *reinterpret_cast<uint4*>(smem + TS_B_LO + so) =
                *reinterpret_cast<const uint4*>(Blo + gb);
        }
        __syncthreads();

        #pragma unroll
        for (int ks = 0; ks < 4; ks++) {
            const uint32_t kk2 = (uint32_t)(ks << 5);
            uint32_t ah[2][4], al[2][4];
            #pragma unroll
            for (int mt = 0; mt < 2; mt++) {
                const uint32_t ra = (uint32_t)((wm + (mt << 4)) * 144) + kk2 + a_off;
                ldsm4(ah[mt], sb + TS_A_HI + ra);
                ldsm4(al[mt], sb + TS_A_LO + ra);
            }
            #pragma unroll
            for (int np = 0; np < 4; np++) {
                uint32_t bh[4], bl[4];
                const uint32_t rb = (uint32_t)((wn + (np << 4)) * 144) + kk2 + b_off;
                ldsm4(bh, sb + TS_B_HI + rb);
                ldsm4(bl, sb + TS_B_LO + rb);
                #pragma unroll
                for (int mt = 0; mt < 2; mt++) {
                    #pragma unroll
                    for (int hf = 0; hf < 2; hf++) {
                        float* d = acc[mt][(np << 1) + hf];
                        mma16816(d, ah[mt], bh + (hf << 1));
                        mma16816(d, ah[mt], bl + (hf << 1));
                        mma16816(d, al[mt], bh + (hf << 1));
                    }
                }
            }
        }
    }

    const int er = lane >> 2, ec = (lane & 3) << 1;
    #pragma unroll
    for (int mt = 0; mt < 2; mt++) {
        #pragma unroll
        for (int half = 0; half < 2; half++) {
            const int gr = m0 + wm + (mt << 4) + er + (half << 3);
            #pragma unroll
            for (int nt = 0; nt < 8; nt++) {
                const int gc = n0 + wn + (nt << 3) + ec;
                float v0 = acc[mt][nt][(half << 1) + 0];
                float v1 = acc[mt][nt][(half << 1) + 1];
                if (bias) { v0 += bias[gc]; v1 += bias[gc + 1]; }
                if (GELU) {
                    v0 = 0.5f * v0 * (1.0f + erff(v0 * 0.70710678118654752f));
                    v1 = 0.5f * v1 * (1.0f + erff(v1 * 0.70710678118654752f));
                }
                if (res) {
                    const float2 rr = *reinterpret_cast<const float2*>(&res[(size_t)gr * N + gc]);
                    v0 += rr.x; v1 += rr.y;
                }
                *reinterpret_cast<float2*>(&C[(size_t)gr * N + gc]) = make_float2(v0, v1);
            }
        }
    }
}

// ===================== LayerNorm ============================================
__global__ __launch_bounds__(128) void ln_k(const float* __restrict__ x,
                                            const float* __restrict__ g,
                                            const float* __restrict__ b,
                                            float* __restrict__ y)
{
    const int row = blockIdx.x;
    const int t = threadIdx.x;
    const float4 v = reinterpret_cast<const float4*>(x + (size_t)row * DMODEL)[t];
    float s  = v.x + v.y + v.z + v.w;
    float sq = v.x*v.x + v.y*v.y + v.z*v.z + v.w*v.w;
    #pragma unroll
    for (int o = 16; o; o >>= 1) {
        s  += __shfl_xor_sync(0xffffffffu, s,  o);
        sq += __shfl_xor_sync(0xffffffffu, sq, o);
    }
    __shared__ float ss[4], sqq[4];
    const int w = t >> 5, lane = t & 31;
    if (lane == 0) { ss[w] = s; sqq[w] = sq; }
    __syncthreads();
    s  = ss[0]  + ss[1]  + ss[2]  + ss[3];
    sq = sqq[0] + sqq[1] + sqq[2] + sqq[3];
    const float mean = s * (1.0f / DMODEL);
    const float var  = sq * (1.0f / DMODEL) - mean * mean;
    const float rstd = rsqrtf(var + 1e-5f);
    const float4 gg = reinterpret_cast<const float4*>(g)[t];
    const float4 bb = reinterpret_cast<const float4*>(b)[t];
    float4 o4;
    o4.x = (v.x - mean) * rstd * gg.x + bb.x;
    o4.y = (v.y - mean) * rstd * gg.y + bb.y;
    o4.z = (v.z - mean) * rstd * gg.z + bb.z;
    o4.w = (v.w - mean) * rstd * gg.w + bb.w;
    reinterpret_cast<float4*>(y + (size_t)row * DMODEL)[t] = o4;
}

// ===================== HMMA flash attention 1 (rel, causal) =================
// smem byte offsets; bf16 tiles are [rows][72] w/ 144B row stride
#define R_QWH 0
#define R_QWL 9216
#define R_QRH 18432
#define R_QRL 27648
#define R_KH  36864
#define R_KL  46080
#define R_VH  55296
#define R_VL  64512
#define R_PH  73728
#define R_PL  82944
#define R_RH  92160
#define R_RL  110592
#define R_GG  129024
#define REL_SMEM 162816   /* R_GG + 64*132*4 */

__global__ __launch_bounds__(128) void flash_rel_mma(
    const float* __restrict__ heads, const float* __restrict__ rkp,
    const float* __restrict__ rwb, const float* __restrict__ rrb,
    float* __restrict__ vec)
{
    extern __shared__ char sm[];
    const uint32_t sb = smem_u32(sm);
    const int tid = threadIdx.x, lane = tid & 31, wid = tid >> 5;
    const int i0 = blockIdx.x << 6;
    const int b = blockIdx.y >> 3, n = blockIdx.y & 7;
    const int wrow = wid << 4;
    const int lr = lane & 7, lg = lane >> 3;
    const uint32_t a_off = (uint32_t)(((lg & 1) << 3) + lr) * 144u + (uint32_t)((lg >> 1) << 4);
    const uint32_t b_off = (uint32_t)(((lg >> 1) << 3) + lr) * 144u + (uint32_t)((lg & 1) << 4);
    float* G = (float*)(sm + R_GG);
    const int qr_ = lane >> 2, qc_ = (lane & 3) << 1;
    const uint32_t AwmH = sb + R_QWH + wrow * 144, AwmL = sb + R_QWL + wrow * 144;
    const uint32_t ArmH = sb + R_QRH + wrow * 144, ArmL = sb + R_QRL + wrow * 144;
    const uint32_t ApH  = sb + R_PH  + wrow * 144, ApL  = sb + R_PL  + wrow * 144;

    // ---- q prologue: qw = q + rwb, qr = q + rrb, split hi/lo
    for (int t = tid; t < 1024; t += 128) {
        const int i = t >> 4, d4 = (t & 15) << 2;
        const float4 qv = *(const float4*)&heads[((size_t)(i0 + i) * BATCH + b) * 1536 + n * 64 + d4];
        const float4 w4 = *(const float4*)&rwb[n * 64 + d4];
        const float4 r4 = *(const float4*)&rrb[n * 64 + d4];
        split_store4(sm + R_QWH + i * 144 + d4 * 2, sm + R_QWL + i * 144 + d4 * 2,
                     make_float4(qv.x + w4.x, qv.y + w4.y, qv.z + w4.z, qv.w + w4.w));
        split_store4(sm + R_QRH + i * 144 + d4 * 2, sm + R_QRL + i * 144 + d4 * 2,
                     make_float4(qv.x + r4.x, qv.y + r4.y, qv.z + r4.z, qv.w + r4.w));
    }
    const int ustart = 960 - i0;
    // ring block 0
    for (int t = tid; t < 1024; t += 128) {
        const int jr = t >> 4, d4 = (t & 15) << 2;
        const int u = ustart + jr;
        const float4 rv = (u < QLEN) ? *(const float4*)&rkp[(size_t)u * 512 + n * 64 + d4]
                                     : make_float4(0.f, 0.f, 0.f, 0.f);
        const int slot = u & 127;
        split_store4(sm + R_RH + slot * 144 + d4 * 2, sm + R_RL + slot * 144 + d4 * 2, rv);
    }
    __syncthreads();
    {   // G for block 0
        float g[8][4];
        #pragma unroll
        for (int nt = 0; nt < 8; nt++) { g[nt][0]=0; g[nt][1]=0; g[nt][2]=0; g[nt][3]=0; }
        const int slotb = ustart & 127;
        wgemm3(ArmH, ArmL, sb + R_RH + slotb * 144, sb + R_RL + slotb * 144, a_off, b_off, g);
        #pragma unroll
        for (int nt = 0; nt < 8; nt++) {
            const int col = slotb + (nt << 3) + qc_;
            *(float2*)&G[(wrow + qr_) * 132 + col]     = make_float2(g[nt][0], g[nt][1]);
            *(float2*)&G[(wrow + qr_ + 8) * 132 + col] = make_float2(g[nt][2], g[nt][3]);
        }
    }

    float m0 = -1e30f, m1 = -1e30f, li0 = 0.f, li1 = 0.f;
    float o[8][4];
    #pragma unroll
    for (int nt = 0; nt < 8; nt++) { o[nt][0]=0; o[nt][1]=0; o[nt][2]=0; o[nt][3]=0; }

    for (int j0 = 0; j0 <= i0; j0 += 64) {
        __syncthreads();
        // ---- K/V tile + next ring block
        for (int t = tid; t < 1024; t += 128) {
            const int j = t >> 4, d4 = (t & 15) << 2;
            const size_t base = ((size_t)(j0 + j) * BATCH + b) * 1536 + n * 64 + d4;
            const float4 kf = *(const float4*)&heads[base + 512];
            split_store4(sm + R_KH + j * 144 + d4 * 2, sm + R_KL + j * 144 + d4 * 2, kf);
            const float4 vf = *(const float4*)&heads[base + 1024];
            split_store1(sm + R_VH + (d4 + 0) * 144 + j * 2, sm + R_VL + (d4 + 0) * 144 + j * 2, vf.x);
            split_store1(sm + R_VH + (d4 + 1) * 144 + j * 2, sm + R_VL + (d4 + 1) * 144 + j * 2, vf.y);
            split_store1(sm + R_VH + (d4 + 2) * 144 + j * 2, sm + R_VL + (d4 + 2) * 144 + j * 2, vf.z);
            split_store1(sm + R_VH + (d4 + 3) * 144 + j * 2, sm + R_VL + (d4 + 3) * 144 + j * 2, vf.w);
        }
        const int ub = ustart + j0 + 64;
        for (int t = tid; t < 1024; t += 128) {
            const int jr = t >> 4, d4 = (t & 15) << 2;
            const int u = ub + jr;
            const float4 rv = (u < QLEN) ? *(const float4*)&rkp[(size_t)u * 512 + n * 64 + d4]
                                         : make_float4(0.f, 0.f, 0.f, 0.f);
            const int slot = u & 127;
            split_store4(sm + R_RH + slot * 144 + d4 * 2, sm + R_RL + slot * 144 + d4 * 2, rv);
        }
        __syncthreads();
        {   // G for new block
            float g[8][4];
            #pragma unroll
            for (int nt = 0; nt < 8; nt++) { g[nt][0]=0; g[nt][1]=0; g[nt][2]=0; g[nt][3]=0; }
            const int slotb = ub & 127;
            wgemm3(ArmH, ArmL, sb + R_RH + slotb * 144, sb + R_RL + slotb * 144, a_off, b_off, g);
            #pragma unroll
            for (int nt = 0; nt < 8; nt++) {
                const int col = slotb + (nt << 3) + qc_;
                *(float2*)&G[(wrow + qr_) * 132 + col]     = make_float2(g[nt][0], g[nt][1]);
                *(float2*)&G[(wrow + qr_ + 8) * 132 + col] = make_float2(g[nt][2], g[nt][3]);
            }
        }
        // ---- QK
        float s[8][4];
        #pragma unroll
        for (int nt = 0; nt < 8; nt++) { s[nt][0]=0; s[nt][1]=0; s[nt][2]=0; s[nt][3]=0; }
        wgemm3(AwmH, AwmL, sb + R_KH, sb + R_KL, a_off, b_off, s);
        __syncwarp();
        // ---- BD gather + scale + mask
        const int cb = 1023 + j0 - i0;
        const int rA = wrow + qr_, rB = rA + 8;
        float rmax0 = -1e30f, rmax1 = -1e30f;
        #pragma unroll
        for (int nt = 0; nt < 8; nt++) {
            const int col = (nt << 3) + qc_;
            s[nt][0] = (s[nt][0] + G[rA * 132 + ((cb + col - rA) & 127)]) * ATT_SCALE;
            s[nt][1] = (s[nt][1] + G[rA * 132 + ((cb + col + 1 - rA) & 127)]) * ATT_SCALE;
            s[nt][2] = (s[nt][2] + G[rB * 132 + ((cb + col - rB) & 127)]) * ATT_SCALE;
            s[nt][3] = (s[nt][3] + G[rB * 132 + ((cb + col + 1 - rB) & 127)]) * ATT_SCALE;
            if (j0 == i0) {
                if (col > rA)     s[nt][0] = -1e30f;
                if (col + 1 > rA) s[nt][1] = -1e30f;
                if (col > rB)     s[nt][2] = -1e30f;
                if (col + 1 > rB) s[nt][3] = -1e30f;
            }
            rmax0 = fmaxf(rmax0, fmaxf(s[nt][0], s[nt][1]));
            rmax1 = fmaxf(rmax1, fmaxf(s[nt][2], s[nt][3]));
        }
        rmax0 = fmaxf(rmax0, __shfl_xor_sync(0xffffffffu, rmax0, 1));
        rmax0 = fmaxf(rmax0, __shfl_xor_sync(0xffffffffu, rmax0, 2));
        rmax1 = fmaxf(rmax1, __shfl_xor_sync(0xffffffffu, rmax1, 1));
        rmax1 = fmaxf(rmax1, __shfl_xor_sync(0xffffffffu, rmax1, 2));
        const float mn0 = fmaxf(m0, rmax0), mn1 = fmaxf(m1, rmax1);
        const float al0 = __expf(m0 - mn0), al1 = __expf(m1 - mn1);
        float rs0 = 0.f, rs1 = 0.f;
        #pragma unroll
        for (int nt = 0; nt < 8; nt++) {
            const int col = (nt << 3) + qc_;
            const float p0 = __expf(s[nt][0] - mn0), p1 = __expf(s[nt][1] - mn0);
            const float p2 = __expf(s[nt][2] - mn1), p3 = __expf(s[nt][3] - mn1);
            rs0 += p0 + p1; rs1 += p2 + p3;
            const __nv_bfloat16 h0 = __float2bfloat16(p0), h1 = __float2bfloat16(p1);
            const __nv_bfloat16 h2 = __float2bfloat16(p2), h3 = __float2bfloat16(p3);
            *(__nv_bfloat162*)(sm + R_PH + rA * 144 + col * 2) = __halves2bfloat162(h0, h1);
            *(__nv_bfloat162*)(sm + R_PL + rA * 144 + col * 2) = __halves2bfloat162(
                __float2bfloat16(p0 - __bfloat162float(h0)),
                __float2bfloat16(p1 - __bfloat162float(h1)));
            *(__nv_bfloat162*)(sm + R_PH + rB * 144 + col * 2) = __halves2bfloat162(h2, h3);
            *(__nv_bfloat162*)(sm + R_PL + rB * 144 + col * 2) = __halves2bfloat162(
                __float2bfloat16(p2 - __bfloat162float(h2)),
                __float2bfloat16(p3 - __bfloat162float(h3)));
            o[nt][0] *= al0; o[nt][1] *= al0; o[nt][2] *= al1; o[nt][3] *= al1;
        }
        rs0 += __shfl_xor_sync(0xffffffffu, rs0, 1);
        rs0 += __shfl_xor_sync(0xffffffffu, rs0, 2);
        rs1 += __shfl_xor_sync(0xffffffffu, rs1, 1);
        rs1 += __shfl_xor_sync(0xffffffffu, rs1, 2);
        li0 = li0 * al0 + rs0; li1 = li1 * al1 + rs1;
        m0 = mn0; m1 = mn1;
        __syncwarp();
        // ---- PV (accumulate)
        wgemm3(ApH, ApL, sb + R_VH, sb + R_VL, a_off, b_off, o);
    }

    const float iv0 = 1.f / li0, iv1 = 1.f / li1;
    #pragma unroll
    for (int nt = 0; nt < 8; nt++) {
        const int d = (nt << 3) + qc_;
        const int rA = wrow + qr_;
        *(float2*)&vec[((size_t)(i0 + rA) * BATCH + b) * 512 + n * 64 + d] =
            make_float2(o[nt][0] * iv0, o[nt][1] * iv0);
        *(float2*)&vec[((size_t)(i0 + rA + 8) * BATCH + b) * 512 + n * 64 + d] =
            make_float2(o[nt][2] * iv1, o[nt][3] * iv1);
    }
}

// ===================== HMMA flash attention 2 (cross) ========================
#define C_QH 0
#define C_QL 9216
#define C_KH 18432
#define C_KL 27648
#define C_VH 36864
#define C_VL 46080
#define C_PH 55296
#define C_PL 64512
#define C_FL 73728
#define CTX_SMEM 73792

__global__ __launch_bounds__(128) void flash_ctx_mma(
    const float* __restrict__ q2, const float* __restrict__ kv,
    const unsigned char* __restrict__ emask, float* __restrict__ vec2)
{
    extern __shared__ char sm[];
    const uint32_t sb = smem_u32(sm);
    const int tid = threadIdx.x, lane = tid & 31, wid = tid >> 5;
    const int i0 = blockIdx.x << 6;
    const int b = blockIdx.y >> 3, n = blockIdx.y & 7;
    const int wrow = wid << 4;
    const int lr = lane & 7, lg = lane >> 3;
    const uint32_t a_off = (uint32_t)(((lg & 1) << 3) + lr) * 144u + (uint32_t)((lg >> 1) << 4);
    const uint32_t b_off = (uint32_t)(((lg >> 1) << 3) + lr) * 144u + (uint32_t)((lg & 1) << 4);
    const int qr_ = lane >> 2, qc_ = (lane & 3) << 1;
    const uint32_t AqH = sb + C_QH + wrow * 144, AqL = sb + C_QL + wrow * 144;
    const uint32_t ApH = sb + C_PH + wrow * 144, ApL = sb + C_PL + wrow * 144;

    for (int t = tid; t < 1024; t += 128) {
        const int i = t >> 4, d4 = (t & 15) << 2;
        const float4 qv = *(const float4*)&q2[((size_t)(i0 + i) * BATCH + b) * 512 + n * 64 + d4];
        split_store4(sm + C_QH + i * 144 + d4 * 2, sm + C_QL + i * 144 + d4 * 2, qv);
    }

    float m0 = -1e30f, m1 = -1e30f, li0 = 0.f, li1 = 0.f;
    float o[8][4];
    #pragma unroll
    for (int nt = 0; nt < 8; nt++) { o[nt][0]=0; o[nt][1]=0; o[nt][2]=0; o[nt][3]=0; }

    for (int j0 = 0; j0 < ELEN; j0 += 64) {
        __syncthreads();
        for (int t = tid; t < 1024; t += 128) {
            const int j = t >> 4, d4 = (t & 15) << 2;
            const size_t base = ((size_t)(j0 + j) * BATCH + b) * 1024 + n * 64 + d4;
            const float4 kf = *(const float4*)&kv[base];
            split_store4(sm + C_KH + j * 144 + d4 * 2, sm + C_KL + j * 144 + d4 * 2, kf);
            const float4 vf = *(const float4*)&kv[base + 512];
            split_store1(sm + C_VH + (d4 + 0) * 144 + j * 2, sm + C_VL + (d4 + 0) * 144 + j * 2, vf.x);
            split_store1(sm + C_VH + (d4 + 1) * 144 + j * 2, sm + C_VL + (d4 + 1) * 144 + j * 2, vf.y);
            split_store1(sm + C_VH + (d4 + 2) * 144 + j * 2, sm + C_VL + (d4 + 2) * 144 + j * 2, vf.z);
            split_store1(sm + C_VH + (d4 + 3) * 144 + j * 2, sm + C_VL + (d4 + 3) * 144 + j * 2, vf.w);
        }
        if (tid < 64) sm[C_FL + tid] = (char)emask[(size_t)(j0 + tid) * BATCH + b];
        __syncthreads();

        float s[8][4];
        #pragma unroll
        for (int nt = 0; nt < 8; nt++) { s[nt][0]=0; s[nt][1]=0; s[nt][2]=0; s[nt][3]=0; }
        wgemm3(AqH, AqL, sb + C_KH, sb + C_KL, a_off, b_off, s);
        __syncwarp();

        const int rA = wrow + qr_, rB = rA + 8;
        float rmax0 = -1e30f, rmax1 = -1e30f;
        #pragma unroll
        for (int nt = 0; nt < 8; nt++) {
            const int col = (nt << 3) + qc_;
            const bool f0 = sm[C_FL + col] != 0, f1 = sm[C_FL + col + 1] != 0;
            s[nt][0] = f0 ? -1e4f : s[nt][0] * ATT_SCALE;
            s[nt][1] = f1 ? -1e4f : s[nt][1] * ATT_SCALE;
            s[nt][2] = f0 ? -1e4f : s[nt][2] * ATT_SCALE;
            s[nt][3] = f1 ? -1e4f : s[nt][3] * ATT_SCALE;
            rmax0 = fmaxf(rmax0, fmaxf(s[nt][0], s[nt][1]));
            rmax1 = fmaxf(rmax1, fmaxf(s[nt][2], s[nt][3]));
        }
        rmax0 = fmaxf(rmax0, __shfl_xor_sync(0xffffffffu, rmax0, 1));
        rmax0 = fmaxf(rmax0, __shfl_xor_sync(0xffffffffu, rmax0, 2));
        rmax1 = fmaxf(rmax1, __shfl_xor_sync(0xffffffffu, rmax1, 1));
        rmax1 = fmaxf(rmax1, __shfl_xor_sync(0xffffffffu, rmax1, 2));
        const float mn0 = fmaxf(m0, rmax0), mn1 = fmaxf(m1, rmax1);
        const float al0 = __expf(m0 - mn0), al1 = __expf(m1 - mn1);
        float rs0 = 0.f, rs1 = 0.f;
        #pragma unroll
        for (int nt = 0; nt < 8; nt++) {
            const int col = (nt << 3) + qc_;
            const float p0 = __expf(s[nt][0] - mn0), p1 = __expf(s[nt][1] - mn0);
            const float p2 = __expf(s[nt][2] - mn1), p3 = __expf(s[nt][3] - mn1);
            rs0 += p0 + p1; rs1 += p2 + p3;
            const __nv_bfloat16 h0 = __float2bfloat16(p0), h1 = __float2bfloat16(p1);
            const __nv_bfloat16 h2 = __float2bfloat16(p2), h3 = __float2bfloat16(p3);
            *(__nv_bfloat162*)(sm + C_PH + rA * 144 + col * 2) = __halves2bfloat162(h0, h1);
            *(__nv_bfloat162*)(sm + C_PL + rA * 144 + col * 2) = __halves2bfloat162(
                __float2bfloat16(p0 - __bfloat162float(h0)),
                __float2bfloat16(p1 - __bfloat162float(h1)));
            *(__nv_bfloat162*)(sm + C_PH + rB * 144 + col * 2) = __halves2bfloat162(h2, h3);
            *(__nv_bfloat162*)(sm + C_PL + rB * 144 + col * 2) = __halves2bfloat162(
                __float2bfloat16(p2 - __bfloat162float(h2)),
                __float2bfloat16(p3 - __bfloat162float(h3)));
            o[nt][0] *= al0; o[nt][1] *= al0; o[nt][2] *= al1; o[nt][3] *= al1;
        }
        rs0 += __shfl_xor_sync(0xffffffffu, rs0, 1);
        rs0 += __shfl_xor_sync(0xffffffffu, rs0, 2);
        rs1 += __shfl_xor_sync(0xffffffffu, rs1, 1);
        rs1 += __shfl_xor_sync(0xffffffffu, rs1, 2);
        li0 = li0 * al0 + rs0; li1 = li1 * al1 + rs1;
        m0 = mn0; m1 = mn1;
        __syncwarp();
        wgemm3(ApH, ApL, sb + C_VH, sb + C_VL, a_off, b_off, o);
    }

    const float iv0 = 1.f / li0, iv1 = 1.f / li1;
    #pragma unroll
    for (int nt = 0; nt < 8; nt++) {
        const int d = (nt << 3) + qc_;
        const int rA = wrow + qr_;
        *(float2*)&vec2[((size_t)(i0 + rA) * BATCH + b) * 512 + n * 64 + d] =
            make_float2(o[nt][0] * iv0, o[nt][1] * iv0);
        *(float2*)&vec2[((size_t)(i0 + rA + 8) * BATCH + b) * 512 + n * 64 + d] =
            make_float2(o[nt][2] * iv1, o[nt][3] * iv1);
    }
}

// ===================== host orchestration ====================================
static inline void launch_gemm(const __nv_bfloat16* ahi, const __nv_bfloat16* alo,
                               const __nv_bfloat16* bhi, const __nv_bfloat16* blo,
                               const float* bias, const float* res, float* C,
                               int M, int N, int K, bool gelu)
{
    dim3 grid(N / 128, M / 128);
    if (gelu)
        gemm_hmma<true><<<grid, 256, GH_SMEM>>>(ahi, alo, bhi, blo, bias, res, C, M, N, K);
    else
        gemm_hmma<false><<<grid, 256, GH_SMEM>>>(ahi, alo, bhi, blo, bias, res, C, M, N, K);
}

extern "C" void kernel_launch(void* const* d_in, const int* in_sizes, int n_in,
                              void* d_out, int out_size)
{
    (void)in_sizes; (void)n_in; (void)out_size;
    const float* dec_inp = (const float*)d_in[0];
    const float* r       = (const float*)d_in[1];
    const float* enc_out = (const float*)d_in[2];
    const float* rwb     = (const float*)d_in[3];
    const float* rrb     = (const float*)d_in[4];
    const float* qkv_w   = (const float*)d_in[5];
    const float* r_w     = (const float*)d_in[6];
    const float* o_w     = (const float*)d_in[7];
    const float* ln1_g   = (const float*)d_in[8];
    const float* ln1_b   = (const float*)d_in[9];
    const float* q_w     = (const float*)d_in[10];
    const float* kv_w    = (const float*)d_in[11];
    const float* o2_w    = (const float*)d_in[12];
    const float* ln2_g   = (const float*)d_in[13];
    const float* ln2_b   = (const float*)d_in[14];
    const float* ff_w1   = (const float*)d_in[15];
    const float* ff_b1   = (const float*)d_in[16];
    const float* ff_w2   = (const float*)d_in[17];
    const float* ff_b2   = (const float*)d_in[18];
    const float* ln3_g   = (const float*)d_in[19];
    const float* ln3_b   = (const float*)d_in[20];
    const unsigned char* emask = (const unsigned char*)d_in[22];
    float* out = (float*)d_out;

    float *h, *heads, *rk, *vec, *out1, *h2, *q2, *kvb, *vec2, *out2, *c, *t;
    __nv_bfloat16 *ahi, *alo, *wthi, *wtlo;
    cudaGetSymbolAddress((void**)&h,     g_h);
    cudaGetSymbolAddress((void**)&heads, g_heads);
    cudaGetSymbolAddress((void**)&rk,    g_rk);
    cudaGetSymbolAddress((void**)&vec,   g_vec);
    cudaGetSymbolAddress((void**)&out1,  g_out1);
    cudaGetSymbolAddress((void**)&h2,    g_h2);
    cudaGetSymbolAddress((void**)&q2,    g_q2);
    cudaGetSymbolAddress((void**)&kvb,   g_kv);
    cudaGetSymbolAddress((void**)&vec2,  g_vec2);
    cudaGetSymbolAddress((void**)&out2,  g_out2);
    cudaGetSymbolAddress((void**)&c,     g_c);
    cudaGetSymbolAddress((void**)&t,     g_t);
    cudaGetSymbolAddress((void**)&ahi,   g_ahi);
    cudaGetSymbolAddress((void**)&alo,   g_alo);
    cudaGetSymbolAddress((void**)&wthi,  g_wthi);
    cudaGetSymbolAddress((void**)&wtlo,  g_wtlo);

    cudaFuncSetAttribute(flash_rel_mma, cudaFuncAttributeMaxDynamicSharedMemorySize, REL_SMEM);
    cudaFuncSetAttribute(flash_ctx_mma, cudaFuncAttributeMaxDynamicSharedMemorySize, CTX_SMEM);
    cudaFuncSetAttribute(gemm_hmma<false>, cudaFuncAttributeMaxDynamicSharedMemorySize, GH_SMEM);
    cudaFuncSetAttribute(gemm_hmma<true>,  cudaFuncAttributeMaxDynamicSharedMemorySize, GH_SMEM);

    // ---- weight transpose+split ----
    tsplit_k<<<dim3(48, 16), 256>>>(qkv_w, wthi + WT_QKV, wtlo + WT_QKV, 512, 1536);
    tsplit_k<<<dim3(16, 16), 256>>>(r_w,   wthi + WT_RW,  wtlo + WT_RW,  512, 512);
    tsplit_k<<<dim3(16, 16), 256>>>(o_w,   wthi + WT_OW,  wtlo + WT_OW,  512, 512);
    tsplit_k<<<dim3(16, 16), 256>>>(q_w,   wthi + WT_QW,  wtlo + WT_QW,  512, 512);
    tsplit_k<<<dim3(32, 16), 256>>>(kv_w,  wthi + WT_KVW, wtlo + WT_KVW, 512, 1024);
    tsplit_k<<<dim3(16, 16), 256>>>(o2_w,  wthi + WT_O2W, wtlo + WT_O2W, 512, 512);
    tsplit_k<<<dim3(64, 16), 256>>>(ff_w1, wthi + WT_FF1, wtlo + WT_FF1, 512, 2048);
    tsplit_k<<<dim3(16, 64), 256>>>(ff_w2, wthi + WT_FF2, wtlo + WT_FF2, 2048, 512);

    // ---- block 1: relative self-attention ----
    ln_k<<<ROWS, 128>>>(dec_inp, ln1_g, ln1_b, h);
    split_k<<<ROWS * DMODEL / 1024, 256>>>(h, ahi, alo, ROWS * DMODEL / 4);
    launch_gemm(ahi, alo, wthi + WT_QKV, wtlo + WT_QKV, nullptr, nullptr, heads,
                ROWS, 3 * DMODEL, DMODEL, false);
    split_k<<<QLEN * DMODEL / 1024, 256>>>(r, ahi, alo, QLEN * DMODEL / 4);
    launch_gemm(ahi, alo, wthi + WT_RW, wtlo + WT_RW, nullptr, nullptr, rk,
                QLEN, DMODEL, DMODEL, false);
    flash_rel_mma<<<dim3(16, 64), 128, REL_SMEM>>>(heads, rk, rwb, rrb, vec);
    split_k<<<ROWS * DMODEL / 1024, 256>>>(vec, ahi, alo, ROWS * DMODEL / 4);
    launch_gemm(ahi, alo, wthi + WT_OW, wtlo + WT_OW, nullptr, dec_inp, out1,
                ROWS, DMODEL, DMODEL, false);

    // ---- block 2: cross attention ----
    ln_k<<<ROWS, 128>>>(out1, ln2_g, ln2_b, h2);
    split_k<<<ROWS * DMODEL / 1024, 256>>>(h2, ahi, alo, ROWS * DMODEL / 4);
    launch_gemm(ahi, alo, wthi + WT_QW, wtlo + WT_QW, nullptr, nullptr, q2,
                ROWS, DMODEL, DMODEL, false);
    split_k<<<ROWS * DMODEL / 1024, 256>>>(enc_out, ahi, alo, ROWS * DMODEL / 4);
    launch_gemm(ahi, alo, wthi + WT_KVW, wtlo + WT_KVW, nullptr, nullptr, kvb,
                ROWS, 2 * DMODEL, DMODEL, false);
    flash_ctx_mma<<<dim3(16, 64), 128, CTX_SMEM>>>(q2, kvb, emask, vec2);
    split_k<<<ROWS * DMODEL / 1024, 256>>>(vec2, ahi, alo, ROWS * DMODEL / 4);
    launch_gemm(ahi, alo, wthi + WT_O2W, wtlo + WT_O2W, nullptr, h2, out2,
                ROWS, DMODEL, DMODEL, false);

    // ---- block 3: FF ----
    ln_k<<<ROWS, 128>>>(out2, ln3_g, ln3_b, c);
    split_k<<<ROWS * DMODEL / 1024, 256>>>(c, ahi, alo, ROWS * DMODEL / 4);
    launch_gemm(ahi, alo, wthi + WT_FF1, wtlo + WT_FF1, ff_b1, nullptr, t,
                ROWS, DINNER, DMODEL, true);
    split_k<<<ROWS * DINNER / 1024, 256>>>(t, ahi, alo, ROWS * DINNER / 4);
    launch_gemm(ahi, alo, wthi + WT_FF2, wtlo + WT_FF2, ff_b2, out2, out,
                ROWS, DMODEL, DINNER, false);
}

// round 8
// speedup vs baseline: 2.3792x; 1.1322x over previous
#include <cuda_runtime.h>
#include <cuda_bf16.h>
#include <cstdint>
#include <cstddef>

#define QLEN   1024
#define BATCH  8
#define DMODEL 512
#define NHEAD  8
#define DHEAD  64
#define DINNER 2048
#define ELEN   1024
#define ATT_SCALE 0.125f
#define ROWS (QLEN * BATCH)   /* 8192 */

// ===================== warp MMA helpers =====================================
__device__ __forceinline__ uint32_t smem_u32(const void* p) {
    uint32_t a;
    asm("{ .reg .u64 t; cvta.to.shared.u64 t, %1; cvt.u32.u64 %0, t; }"
        : "=r"(a) : "l"(p));
    return a;
}

__device__ __forceinline__ void ldsm4(uint32_t* r, uint32_t addr) {
    asm volatile("ldmatrix.sync.aligned.m8n8.x4.shared.b16 {%0,%1,%2,%3}, [%4];"
                 : "=r"(r[0]), "=r"(r[1]), "=r"(r[2]), "=r"(r[3]) : "r"(addr));
}

__device__ __forceinline__ void mma16816(float* d, const uint32_t* a, const uint32_t* b) {
    asm volatile(
        "mma.sync.aligned.m16n8k16.row.col.f32.bf16.bf16.f32 "
        "{%0,%1,%2,%3}, {%4,%5,%6,%7}, {%8,%9}, {%0,%1,%2,%3};"
        : "+f"(d[0]), "+f"(d[1]), "+f"(d[2]), "+f"(d[3])
        : "r"(a[0]), "r"(a[1]), "r"(a[2]), "r"(a[3]), "r"(b[0]), "r"(b[1]));
}

__device__ __forceinline__ void barp(int id) {
    asm volatile("bar.sync %0, %1;" :: "r"(id), "r"(64) : "memory");
}

// 3-term split-bf16 warp GEMM, 64-col B (nt=8), K=64.
__device__ __forceinline__ void wgemm3(uint32_t Ah, uint32_t Al,
                                       uint32_t Bh, uint32_t Bl,
                                       uint32_t a_off, uint32_t b_off,
                                       float acc[8][4])
{
    #pragma unroll
    for (int ks = 0; ks < 4; ks++) {
        const uint32_t ra = (uint32_t)(ks << 5);
        uint32_t ah[4], al[4];
        ldsm4(ah, Ah + ra + a_off);
        ldsm4(al, Al + ra + a_off);
        #pragma unroll
        for (int np = 0; np < 4; np++) {
            uint32_t bh[4], bl[4];
            const uint32_t rb = (uint32_t)(np * 16 * 144 + (ks << 5));
            ldsm4(bh, Bh + rb + b_off);
            ldsm4(bl, Bl + rb + b_off);
            #pragma unroll
            for (int hf = 0; hf < 2; hf++) {
                float* d = acc[(np << 1) + hf];
                mma16816(d, ah, bh + (hf << 1));
                mma16816(d, ah, bl + (hf << 1));
                mma16816(d, al, bh + (hf << 1));
            }
        }
    }
}

// nt=4 variant (32-col B)
__device__ __forceinline__ void wgemm3_nt4(uint32_t Ah, uint32_t Al,
                                           uint32_t Bh, uint32_t Bl,
                                           uint32_t a_off, uint32_t b_off,
                                           float acc[4][4])
{
    #pragma unroll
    for (int ks = 0; ks < 4; ks++) {
        const uint32_t ra = (uint32_t)(ks << 5);
        uint32_t ah[4], al[4];
        ldsm4(ah, Ah + ra + a_off);
        ldsm4(al, Al + ra + a_off);
        #pragma unroll
        for (int np = 0; np < 2; np++) {
            uint32_t bh[4], bl[4];
            const uint32_t rb = (uint32_t)(np * 16 * 144 + (ks << 5));
            ldsm4(bh, Bh + rb + b_off);
            ldsm4(bl, Bl + rb + b_off);
            #pragma unroll
            for (int hf = 0; hf < 2; hf++) {
                float* d = acc[(np << 1) + hf];
                mma16816(d, ah, bh + (hf << 1));
                mma16816(d, ah, bl + (hf << 1));
                mma16816(d, al, bh + (hf << 1));
            }
        }
    }
}

__device__ __forceinline__ void split_store4(char* hi, char* lo, float4 v) {
    const __nv_bfloat16 h0 = __float2bfloat16(v.x), h1 = __float2bfloat16(v.y);
    const __nv_bfloat16 h2 = __float2bfloat16(v.z), h3 = __float2bfloat16(v.w);
    *(__nv_bfloat162*)(hi)     = __halves2bfloat162(h0, h1);
    *(__nv_bfloat162*)(hi + 4) = __halves2bfloat162(h2, h3);
    *(__nv_bfloat162*)(lo)     = __halves2bfloat162(
        __float2bfloat16(v.x - __bfloat162float(h0)),
        __float2bfloat16(v.y - __bfloat162float(h1)));
    *(__nv_bfloat162*)(lo + 4) = __halves2bfloat162(
        __float2bfloat16(v.z - __bfloat162float(h2)),
        __float2bfloat16(v.w - __bfloat162float(h3)));
}

// ===================== scratch ==============================================
__device__ float g_out1[ROWS * DMODEL];
__device__ float g_h2  [ROWS * DMODEL];
__device__ float g_out2[ROWS * DMODEL];
__device__ float g_qbias[3 * DMODEL];
__device__ float g_cc  [NHEAD * 1152];        // zero-init pad beyond 1024

__device__ __nv_bfloat16 g_hh[ROWS * DMODEL],    g_hl[ROWS * DMODEL];
__device__ __nv_bfloat16 g_headsh[ROWS * 1536],  g_headsl[ROWS * 1536];
__device__ __nv_bfloat16 g_rh[QLEN * DMODEL],    g_rl[QLEN * DMODEL];
__device__ __nv_bfloat16 g_rkh[QLEN * DMODEL],   g_rkl[QLEN * DMODEL];
__device__ __nv_bfloat16 g_vth[64 * 64 * QLEN],  g_vtl[64 * 64 * QLEN];
__device__ __nv_bfloat16 g_vech[ROWS * DMODEL],  g_vecl[ROWS * DMODEL];
__device__ __nv_bfloat16 g_h2h[ROWS * DMODEL],   g_h2l[ROWS * DMODEL];
__device__ __nv_bfloat16 g_q2h[ROWS * DMODEL],   g_q2l[ROWS * DMODEL];
__device__ __nv_bfloat16 g_eh[ROWS * DMODEL],    g_el[ROWS * DMODEL];
__device__ __nv_bfloat16 g_kvh[ROWS * 1024],     g_kvl[ROWS * 1024];
__device__ __nv_bfloat16 g_vt2h[64 * 64 * ELEN], g_vt2l[64 * 64 * ELEN];
__device__ __nv_bfloat16 g_vec2h[ROWS * DMODEL], g_vec2l[ROWS * DMODEL];
__device__ __nv_bfloat16 g_th[ROWS * DINNER],    g_tl[ROWS * DINNER];

#define WT_QKV 0
#define WT_RW  786432
#define WT_OW  1048576
#define WT_QW  1310720
#define WT_KVW 1572864
#define WT_O2W 2097152
#define WT_FF1 2359296
#define WT_FF2 3407872
#define WT_TOTAL 4456448
__device__ __nv_bfloat16 g_wthi[WT_TOTAL];
__device__ __nv_bfloat16 g_wtlo[WT_TOTAL];

// ===================== small prep kernels ===================================
__global__ __launch_bounds__(256) void split_k(const float* __restrict__ x,
                                               __nv_bfloat16* __restrict__ hi,
                                               __nv_bfloat16* __restrict__ lo, int n4)
{
    const int i = blockIdx.x * 256 + threadIdx.x;
    if (i >= n4) return;
    const float4 v = reinterpret_cast<const float4*>(x)[i];
    split_store4((char*)(hi + (size_t)i * 4), (char*)(lo + (size_t)i * 4), v);
}

__global__ __launch_bounds__(256) void tsplit_k(const float* __restrict__ W,
                                                __nv_bfloat16* __restrict__ hi,
                                                __nv_bfloat16* __restrict__ lo,
                                                int K, int N)
{
    __shared__ float t[32][33];
    const int n0 = blockIdx.x << 5, k0 = blockIdx.y << 5;
    const int x = threadIdx.x & 31, y = threadIdx.x >> 5;
    #pragma unroll
    for (int i = 0; i < 32; i += 8)
        t[y + i][x] = W[(size_t)(k0 + y + i) * N + n0 + x];
    __syncthreads();
    #pragma unroll
    for (int i = 0; i < 32; i += 8) {
        const float v = t[x][y + i];
        const size_t o = (size_t)(n0 + y + i) * K + k0 + x;
        const __nv_bfloat16 h = __float2bfloat16(v);
        hi[o] = h;
        lo[o] = __float2bfloat16(v - __bfloat162float(h));
    }
}

__global__ void qbias_k(const float* __restrict__ rwb, float* __restrict__ qb) {
    const int i = blockIdx.x * 256 + threadIdx.x;
    if (i < 1536) qb[i] = (i < 512) ? rwb[i] : 0.0f;
}

// c[n][u] = sum_d (rrb-rwb)[n][d] * rk[u][n*64+d]
__global__ __launch_bounds__(256) void c_k(const __nv_bfloat16* __restrict__ rkh,
                                           const __nv_bfloat16* __restrict__ rkl,
                                           const float* __restrict__ rwb,
                                           const float* __restrict__ rrb,
                                           float* __restrict__ cc)
{
    const int u = blockIdx.x;
    const int n = threadIdx.x >> 5, lane = threadIdx.x & 31;
    float s = 0.0f;
    #pragma unroll
    for (int k = 0; k < 2; k++) {
        const int d = lane + k * 32;
        const size_t g = (size_t)u * 512 + n * 64 + d;
        const float rv = __bfloat162float(rkh[g]) + __bfloat162float(rkl[g]);
        s += (rrb[n * 64 + d] - rwb[n * 64 + d]) * rv;
    }
    #pragma unroll
    for (int o = 16; o; o >>= 1) s += __shfl_xor_sync(0xffffffffu, s, o);
    if (lane == 0) cc[n * 1152 + u] = s;
}

// transpose V-part: src[(i*8+b)*stride + off + n*64 + d] -> dst[((b*8+n)*64+d)*1024 + i]
__global__ __launch_bounds__(256) void vtrans_k(const __nv_bfloat16* __restrict__ sh,
                                                const __nv_bfloat16* __restrict__ sl,
                                                __nv_bfloat16* __restrict__ dh,
                                                __nv_bfloat16* __restrict__ dl,
                                                int srcStride, int srcOff)
{
    __shared__ __nv_bfloat16 th[32][72], tl[32][72];
    const int i0 = blockIdx.x << 5;
    const int b = blockIdx.y >> 3, n = blockIdx.y & 7;
    const int t = threadIdx.x;
    {
        const int il = t >> 3, dj = (t & 7) << 3;
        const size_t g = ((size_t)(i0 + il) * 8 + b) * srcStride + srcOff + n * 64 + dj;
        *(uint4*)&th[il][dj] = *(const uint4*)(sh + g);
        *(uint4*)&tl[il][dj] = *(const uint4*)(sl + g);
    }
    __syncthreads();
    {
        const int dr = t >> 2, ij = (t & 3) << 3;
        __nv_bfloat16 oh[8], ol[8];
        #pragma unroll
        for (int k = 0; k < 8; k++) { oh[k] = th[ij + k][dr]; ol[k] = tl[ij + k][dr]; }
        const size_t g = ((size_t)(b * 8 + n) * 64 + dr) * 1024 + i0 + ij;
        *(uint4*)(dh + g) = *(uint4*)oh;
        *(uint4*)(dl + g) = *(uint4*)ol;
    }
}

// ===================== HMMA GEMM ============================================
#define TS_A_HI 0
#define TS_A_LO 18432
#define TS_B_HI 36864
#define TS_B_LO 55296
#define GH_SMEM 73728

template <bool GELU, bool SPLIT>
__global__ __launch_bounds__(256) void gemm_hmma(const __nv_bfloat16* __restrict__ Ahi,
                                                 const __nv_bfloat16* __restrict__ Alo,
                                                 const __nv_bfloat16* __restrict__ Bhi,
                                                 const __nv_bfloat16* __restrict__ Blo,
                                                 const float* __restrict__ bias,
                                                 const float* __restrict__ res,
                                                 float* __restrict__ C,
                                                 __nv_bfloat16* __restrict__ Ch,
                                                 __nv_bfloat16* __restrict__ Cl,
                                                 int M, int N, int K)
{
    extern __shared__ char smem[];
    const uint32_t sb = smem_u32(smem);
    const int tid = threadIdx.x;
    const int lane = tid & 31, wid = tid >> 5;
    const int m0 = blockIdx.y << 7, n0 = blockIdx.x << 7;
    const int wm = (wid & 3) << 5;
    const int wn = (wid >> 2) << 6;
    (void)M;

    float acc[2][8][4];
    #pragma unroll
    for (int mt = 0; mt < 2; mt++)
        #pragma unroll
        for (int nt = 0; nt < 8; nt++)
            #pragma unroll
            for (int e = 0; e < 4; e++) acc[mt][nt][e] = 0.0f;

    const int lr = lane & 7, lg = lane >> 3;
    const uint32_t a_off = (uint32_t)(((lg & 1) << 3) + lr) * 144u + (uint32_t)((lg >> 1) << 4);
    const uint32_t b_off = (uint32_t)(((lg >> 1) << 3) + lr) * 144u + (uint32_t)((lg & 1) << 4);

    const int nch = K >> 6;
    for (int c = 0; c < nch; c++) {
        const int k0 = c << 6;
        __syncthreads();
        #pragma unroll 4
        for (int i = tid; i < 1024; i += 256) {
            const int r = i >> 3, kc = (i & 7) << 3;
            const uint32_t so = (uint32_t)(r * 144 + kc * 2);
            const size_t ga = (size_t)(m0 + r) * K + k0 + kc;
            const size_t gb = (size_t)(n0 + r) * K + k0 + kc;
            *reinterpret_cast<uint4*>(smem + TS_A_HI + so) =
                *reinterpret_cast<const uint4*>(Ahi + ga);
            *reinterpret_cast<uint4*>(smem + TS_A_LO + so) =
                *reinterpret_cast<const uint4*>(Alo + ga);
            *reinterpret_cast<uint4*>(smem + TS_B_HI + so) =
                *reinterpret_cast<const uint4*>(Bhi + gb);
            *reinterpret_cast<uint4*>(smem + TS_B_LO + so) =
                *reinterpret_cast<const uint4*>(Blo + gb);
        }
        __syncthreads();

        #pragma unroll
        for (int ks = 0; ks < 4; ks++) {
            const uint32_t kk2 = (uint32_t)(ks << 5);
            uint32_t ah[2][4], al[2][4];
            #pragma unroll
            for (int mt = 0; mt < 2; mt++) {
                const uint32_t ra = (uint32_t)((wm + (mt << 4)) * 144) + kk2 + a_off;
                ldsm4(ah[mt], sb + TS_A_HI + ra);
                ldsm4(al[mt], sb + TS_A_LO + ra);
            }
            #pragma unroll
            for (int np = 0; np < 4; np++) {
                uint32_t bh[4], bl[4];
                const uint32_t rb = (uint32_t)((wn + (np << 4)) * 144) + kk2 + b_off;
                ldsm4(bh, sb + TS_B_HI + rb);
                ldsm4(bl, sb + TS_B_LO + rb);
                #pragma unroll
                for (int mt = 0; mt < 2; mt++) {
                    #pragma unroll
                    for (int hf = 0; hf < 2; hf++) {
                        float* d = acc[mt][(np << 1) + hf];
                        mma16816(d, ah[mt], bh + (hf << 1));
                        mma16816(d, ah[mt], bl + (hf << 1));
                        mma16816(d, al[mt], bh + (hf << 1));
                    }
                }
            }
        }
    }

    const int er = lane >> 2, ec = (lane & 3) << 1;
    #pragma unroll
    for (int mt = 0; mt < 2; mt++) {
        #pragma unroll
        for (int half = 0; half < 2; half++) {
            const int gr = m0 + wm + (mt << 4) + er + (half << 3);
            #pragma unroll
            for (int nt = 0; nt < 8; nt++) {
                const int gc = n0 + wn + (nt << 3) + ec;
                float v0 = acc[mt][nt][(half << 1) + 0];
                float v1 = acc[mt][nt][(half << 1) + 1];
                if (bias) { v0 += bias[gc]; v1 += bias[gc + 1]; }
                if (GELU) {
                    v0 = 0.5f * v0 * (1.0f + erff(v0 * 0.70710678118654752f));
                    v1 = 0.5f * v1 * (1.0f + erff(v1 * 0.70710678118654752f));
                }
                if (SPLIT) {
                    const __nv_bfloat16 h0 = __float2bfloat16(v0), h1 = __float2bfloat16(v1);
                    *(__nv_bfloat162*)(Ch + (size_t)gr * N + gc) = __halves2bfloat162(h0, h1);
                    *(__nv_bfloat162*)(Cl + (size_t)gr * N + gc) = __halves2bfloat162(
                        __float2bfloat16(v0 - __bfloat162float(h0)),
                        __float2bfloat16(v1 - __bfloat162float(h1)));
                } else {
                    if (res) {
                        const float2 rr = *reinterpret_cast<const float2*>(&res[(size_t)gr * N + gc]);
                        v0 += rr.x; v1 += rr.y;
                    }
                    *reinterpret_cast<float2*>(&C[(size_t)gr * N + gc]) = make_float2(v0, v1);
                }
            }
        }
    }
}

// ===================== LayerNorm ============================================
template <bool F32O, bool SPL>
__global__ __launch_bounds__(128) void ln_k(const float* __restrict__ x,
                                            const float* __restrict__ g,
                                            const float* __restrict__ b,
                                            float* __restrict__ yf,
                                            __nv_bfloat16* __restrict__ yh,
                                            __nv_bfloat16* __restrict__ yl)
{
    const int row = blockIdx.x;
    const int t = threadIdx.x;
    const float4 v = reinterpret_cast<const float4*>(x + (size_t)row * DMODEL)[t];
    float s  = v.x + v.y + v.z + v.w;
    float sq = v.x*v.x + v.y*v.y + v.z*v.z + v.w*v.w;
    #pragma unroll
    for (int o = 16; o; o >>= 1) {
        s  += __shfl_xor_sync(0xffffffffu, s,  o);
        sq += __shfl_xor_sync(0xffffffffu, sq, o);
    }
    __shared__ float ss[4], sqq[4];
    const int w = t >> 5, lane = t & 31;
    if (lane == 0) { ss[w] = s; sqq[w] = sq; }
    __syncthreads();
    s  = ss[0]  + ss[1]  + ss[2]  + ss[3];
    sq = sqq[0] + sqq[1] + sqq[2] + sqq[3];
    const float mean = s * (1.0f / DMODEL);
    const float var  = sq * (1.0f / DMODEL) - mean * mean;
    const float rstd = rsqrtf(var + 1e-5f);
    const float4 gg = reinterpret_cast<const float4*>(g)[t];
    const float4 bb = reinterpret_cast<const float4*>(b)[t];
    float4 o4;
    o4.x = (v.x - mean) * rstd * gg.x + bb.x;
    o4.y = (v.y - mean) * rstd * gg.y + bb.y;
    o4.z = (v.z - mean) * rstd * gg.z + bb.z;
    o4.w = (v.w - mean) * rstd * gg.w + bb.w;
    if (F32O) reinterpret_cast<float4*>(yf + (size_t)row * DMODEL)[t] = o4;
    if (SPL)  split_store4((char*)(yh + (size_t)row * DMODEL + t * 4),
                           (char*)(yl + (size_t)row * DMODEL + t * 4), o4);
}

// ===================== flash attention 1 (rel, causal), 256 thr =============
#define R_QH 0
#define R_QL 9216
#define R_KH 18432
#define R_KL 27648
#define R_VH 36864
#define R_VL 46080
#define R_PH 55296
#define R_PL 64512
#define R_RH 73728
#define R_RL 92160
#define R_G  110592
#define R_C  144384
#define R_PM 144640
#define R_PS 145152
#define REL_SMEM 145664

__global__ __launch_bounds__(256) void flash_rel_mma(
    const __nv_bfloat16* __restrict__ hh, const __nv_bfloat16* __restrict__ hl,
    const __nv_bfloat16* __restrict__ vth, const __nv_bfloat16* __restrict__ vtl,
    const __nv_bfloat16* __restrict__ rkh, const __nv_bfloat16* __restrict__ rkl,
    const float* __restrict__ cc,
    __nv_bfloat16* __restrict__ vech, __nv_bfloat16* __restrict__ vecl)
{
    extern __shared__ char sm[];
    const uint32_t sb = smem_u32(sm);
    const int tid = threadIdx.x, lane = tid & 31, wid = tid >> 5;
    const int p = wid >> 1, h = wid & 1;
    const int i0 = blockIdx.x << 6;
    const int b = blockIdx.y >> 3, n = blockIdx.y & 7;
    const int lr = lane & 7, lg = lane >> 3;
    const uint32_t a_off = (uint32_t)(((lg & 1) << 3) + lr) * 144u + (uint32_t)((lg >> 1) << 4);
    const uint32_t b_off = (uint32_t)(((lg >> 1) << 3) + lr) * 144u + (uint32_t)((lg & 1) << 4);
    const int qr_ = lane >> 2, qc_ = (lane & 3) << 1;
    float* G    = (float*)(sm + R_G);
    float* csm  = (float*)(sm + R_C);
    float* pmax = (float*)(sm + R_PM);
    float* psum = (float*)(sm + R_PS);
    const uint32_t AqH = sb + R_QH + p * 16 * 144, AqL = sb + R_QL + p * 16 * 144;
    const uint32_t ApH = sb + R_PH + p * 16 * 144, ApL = sb + R_PL + p * 16 * 144;

    // ---- prologue: q tile (rwb pre-folded), ring block 0, c block
    for (int t = tid; t < 512; t += 256) {
        const int row = t >> 3, c4 = t & 7;
        const size_t g = ((size_t)(i0 + row) * 8 + b) * 1536 + n * 64 + c4 * 8;
        *(uint4*)(sm + R_QH + row * 144 + c4 * 16) = *(const uint4*)(hh + g);
        *(uint4*)(sm + R_QL + row * 144 + c4 * 16) = *(const uint4*)(hl + g);
    }
    const int ustart = 960 - i0;
    for (int t = tid; t < 512; t += 256) {
        const int jr = t >> 3, c4 = t & 7;
        const int u = ustart + jr, slot = u & 127;
        uint4 vh = make_uint4(0, 0, 0, 0), vl = make_uint4(0, 0, 0, 0);
        if (u < QLEN) {
            const size_t g = (size_t)u * 512 + n * 64 + c4 * 8;
            vh = *(const uint4*)(rkh + g);
            vl = *(const uint4*)(rkl + g);
        }
        *(uint4*)(sm + R_RH + slot * 144 + c4 * 16) = vh;
        *(uint4*)(sm + R_RL + slot * 144 + c4 * 16) = vl;
    }
    if (tid < 64) csm[tid] = cc[n * 1152 + ustart + tid];
    __syncthreads();
    {
        const int slotb = ustart & 127;
        float g4[4][4];
        #pragma unroll
        for (int nt = 0; nt < 4; nt++) { g4[nt][0]=0; g4[nt][1]=0; g4[nt][2]=0; g4[nt][3]=0; }
        wgemm3_nt4(AqH, AqL, sb + R_RH + (slotb + h * 32) * 144,
                   sb + R_RL + (slotb + h * 32) * 144, a_off, b_off, g4);
        #pragma unroll
        for (int nt = 0; nt < 4; nt++) {
            const int cl = h * 32 + (nt << 3) + qc_;
            const int col = slotb + cl;
            const float c0 = csm[cl], c1 = csm[cl + 1];
            *(float2*)&G[(16 * p + qr_) * 132 + col]     = make_float2(g4[nt][0] + c0, g4[nt][1] + c1);
            *(float2*)&G[(16 * p + qr_ + 8) * 132 + col] = make_float2(g4[nt][2] + c0, g4[nt][3] + c1);
        }
    }

    float m0 = -1e30f, m1 = -1e30f, li0 = 0.f, li1 = 0.f;
    float o[4][4];
    #pragma unroll
    for (int nt = 0; nt < 4; nt++) { o[nt][0]=0; o[nt][1]=0; o[nt][2]=0; o[nt][3]=0; }

    for (int j0 = 0; j0 <= i0; j0 += 64) {
        __syncthreads();
        // K tile
        for (int t = tid; t < 512; t += 256) {
            const int row = t >> 3, c4 = t & 7;
            const size_t g = ((size_t)(j0 + row) * 8 + b) * 1536 + 512 + n * 64 + c4 * 8;
            *(uint4*)(sm + R_KH + row * 144 + c4 * 16) = *(const uint4*)(hh + g);
            *(uint4*)(sm + R_KL + row * 144 + c4 * 16) = *(const uint4*)(hl + g);
        }
        // V^T tile
        for (int t = tid; t < 512; t += 256) {
            const int dr = t >> 3, c4 = t & 7;
            const size_t g = ((size_t)(b * 8 + n) * 64 + dr) * 1024 + j0 + c4 * 8;
            *(uint4*)(sm + R_VH + dr * 144 + c4 * 16) = *(const uint4*)(vth + g);
            *(uint4*)(sm + R_VL + dr * 144 + c4 * 16) = *(const uint4*)(vtl + g);
        }
        // new ring block + c block
        const int ub = ustart + j0 + 64;
        for (int t = tid; t < 512; t += 256) {
            const int jr = t >> 3, c4 = t & 7;
            const int u = ub + jr, slot = u & 127;
            uint4 vh = make_uint4(0, 0, 0, 0), vl = make_uint4(0, 0, 0, 0);
            if (u < QLEN) {
                const size_t g = (size_t)u * 512 + n * 64 + c4 * 8;
                vh = *(const uint4*)(rkh + g);
                vl = *(const uint4*)(rkl + g);
            }
            *(uint4*)(sm + R_RH + slot * 144 + c4 * 16) = vh;
            *(uint4*)(sm + R_RL + slot * 144 + c4 * 16) = vl;
        }
        if (tid < 64) csm[tid] = cc[n * 1152 + ub + tid];
        __syncthreads();
        // G for new block
        {
            const int slotb = ub & 127;
            float g4[4][4];
            #pragma unroll
            for (int nt = 0; nt < 4; nt++) { g4[nt][0]=0; g4[nt][1]=0; g4[nt][2]=0; g4[nt][3]=0; }
            wgemm3_nt4(AqH, AqL, sb + R_RH + (slotb + h * 32) * 144,
                       sb + R_RL + (slotb + h * 32) * 144, a_off, b_off, g4);
            #pragma unroll
            for (int nt = 0; nt < 4; nt++) {
                const int cl = h * 32 + (nt << 3) + qc_;
                const int col = slotb + cl;
                const float c0 = csm[cl], c1 = csm[cl + 1];
                *(float2*)&G[(16 * p + qr_) * 132 + col]     = make_float2(g4[nt][0] + c0, g4[nt][1] + c1);
                *(float2*)&G[(16 * p + qr_ + 8) * 132 + col] = make_float2(g4[nt][2] + c0, g4[nt][3] + c1);
            }
        }
        // QK (j-cols half h)
        float s[4][4];
        #pragma unroll
        for (int nt = 0; nt < 4; nt++) { s[nt][0]=0; s[nt][1]=0; s[nt][2]=0; s[nt][3]=0; }
        wgemm3_nt4(AqH, AqL, sb + R_KH + h * 32 * 144, sb + R_KL + h * 32 * 144,
                   a_off, b_off, s);
        barp(1 + p);
        // gather BD + scale + mask
        const int cb = 1023 + j0 - i0;
        const int rA = 16 * p + qr_, rB = rA + 8;
        float rmax0 = -1e30f, rmax1 = -1e30f;
        #pragma unroll
        for (int nt = 0; nt < 4; nt++) {
            const int col = h * 32 + (nt << 3) + qc_;
            s[nt][0] = (s[nt][0] + G[rA * 132 + ((cb + col - rA) & 127)]) * ATT_SCALE;
            s[nt][1] = (s[nt][1] + G[rA * 132 + ((cb + col + 1 - rA) & 127)]) * ATT_SCALE;
            s[nt][2] = (s[nt][2] + G[rB * 132 + ((cb + col - rB) & 127)]) * ATT_SCALE;
            s[nt][3] = (s[nt][3] + G[rB * 132 + ((cb + col + 1 - rB) & 127)]) * ATT_SCALE;
            if (j0 == i0) {
                if (col > rA)     s[nt][0] = -1e30f;
                if (col + 1 > rA) s[nt][1] = -1e30f;
                if (col > rB)     s[nt][2] = -1e30f;
                if (col + 1 > rB) s[nt][3] = -1e30f;
            }
            rmax0 = fmaxf(rmax0, fmaxf(s[nt][0], s[nt][1]));
            rmax1 = fmaxf(rmax1, fmaxf(s[nt][2], s[nt][3]));
        }
        rmax0 = fmaxf(rmax0, __shfl_xor_sync(0xffffffffu, rmax0, 1));
        rmax0 = fmaxf(rmax0, __shfl_xor_sync(0xffffffffu, rmax0, 2));
        rmax1 = fmaxf(rmax1, __shfl_xor_sync(0xffffffffu, rmax1, 1));
        rmax1 = fmaxf(rmax1, __shfl_xor_sync(0xffffffffu, rmax1, 2));
        if ((lane & 3) == 0) {
            pmax[p * 32 + h * 16 + qr_]     = rmax0;
            pmax[p * 32 + h * 16 + qr_ + 8] = rmax1;
        }
        barp(1 + p);
        rmax0 = fmaxf(rmax0, pmax[p * 32 + (1 - h) * 16 + qr_]);
        rmax1 = fmaxf(rmax1, pmax[p * 32 + (1 - h) * 16 + qr_ + 8]);
        const float mn0 = fmaxf(m0, rmax0), mn1 = fmaxf(m1, rmax1);
        const float al0 = __expf(m0 - mn0), al1 = __expf(m1 - mn1);
        float rs0 = 0.f, rs1 = 0.f;
        #pragma unroll
        for (int nt = 0; nt < 4; nt++) {
            const int col = h * 32 + (nt << 3) + qc_;
            const float p0 = __expf(s[nt][0] - mn0), p1 = __expf(s[nt][1] - mn0);
            const float p2 = __expf(s[nt][2] - mn1), p3 = __expf(s[nt][3] - mn1);
            rs0 += p0 + p1; rs1 += p2 + p3;
            const __nv_bfloat16 h0 = __float2bfloat16(p0), h1 = __float2bfloat16(p1);
            const __nv_bfloat16 h2 = __float2bfloat16(p2), h3 = __float2bfloat16(p3);
            *(__nv_bfloat162*)(sm + R_PH + rA * 144 + col * 2) = __halves2bfloat162(h0, h1);
            *(__nv_bfloat162*)(sm + R_PL + rA * 144 + col * 2) = __halves2bfloat162(
                __float2bfloat16(p0 - __bfloat162float(h0)),
                __float2bfloat16(p1 - __bfloat162float(h1)));
            *(__nv_bfloat162*)(sm + R_PH + rB * 144 + col * 2) = __halves2bfloat162(h2, h3);
            *(__nv_bfloat162*)(sm + R_PL + rB * 144 + col * 2) = __halves2bfloat162(
                __float2bfloat16(p2 - __bfloat162float(h2)),
                __float2bfloat16(p3 - __bfloat162float(h3)));
            o[nt][0] *= al0; o[nt][1] *= al0; o[nt][2] *= al1; o[nt][3] *= al1;
        }
        rs0 += __shfl_xor_sync(0xffffffffu, rs0, 1);
        rs0 += __shfl_xor_sync(0xffffffffu, rs0, 2);
        rs1 += __shfl_xor_sync(0xffffffffu, rs1, 1);
        rs1 += __shfl_xor_sync(0xffffffffu, rs1, 2);
        if ((lane & 3) == 0) {
            psum[p * 32 + h * 16 + qr_]     = rs0;
            psum[p * 32 + h * 16 + qr_ + 8] = rs1;
        }
        barp(1 + p);   // psum exchange + P visibility for the pair
        rs0 += psum[p * 32 + (1 - h) * 16 + qr_];
        rs1 += psum[p * 32 + (1 - h) * 16 + qr_ + 8];
        li0 = li0 * al0 + rs0; li1 = li1 * al1 + rs1;
        m0 = mn0; m1 = mn1;
        // PV: d-cols half h
        wgemm3_nt4(ApH, ApL, sb + R_VH + h * 32 * 144, sb + R_VL + h * 32 * 144,
                   a_off, b_off, o);
    }

    const float iv0 = 1.f / li0, iv1 = 1.f / li1;
    const int rA = 16 * p + qr_;
    #pragma unroll
    for (int nt = 0; nt < 4; nt++) {
        const int d = h * 32 + (nt << 3) + qc_;
        const float v0 = o[nt][0] * iv0, v1 = o[nt][1] * iv0;
        const float v2 = o[nt][2] * iv1, v3 = o[nt][3] * iv1;
        const size_t gA = ((size_t)(i0 + rA) * 8 + b) * 512 + n * 64 + d;
        const size_t gB = ((size_t)(i0 + rA + 8) * 8 + b) * 512 + n * 64 + d;
        const __nv_bfloat16 h0 = __float2bfloat16(v0), h1 = __float2bfloat16(v1);
        const __nv_bfloat16 h2 = __float2bfloat16(v2), h3 = __float2bfloat16(v3);
        *(__nv_bfloat162*)(vech + gA) = __halves2bfloat162(h0, h1);
        *(__nv_bfloat162*)(vecl + gA) = __halves2bfloat162(
            __float2bfloat16(v0 - __bfloat162float(h0)),
            __float2bfloat16(v1 - __bfloat162float(h1)));
        *(__nv_bfloat162*)(vech + gB) = __halves2bfloat162(h2, h3);
        *(__nv_bfloat162*)(vecl + gB) = __halves2bfloat162(
            __float2bfloat16(v2 - __bfloat162float(h2)),
            __float2bfloat16(v3 - __bfloat162float(h3)));
    }
}

// ===================== flash attention 2 (cross), 256 thr, 128-row tile =====
#define C_QH 0
#define C_QL 18432
#define C_KH 36864
#define C_KL 46080
#define C_VH 55296
#define C_VL 64512
#define C_PH 73728
#define C_PL 92160
#define C_FL 110592
#define CTX_SMEM 110720

__global__ __launch_bounds__(256) void flash_ctx_mma(
    const __nv_bfloat16* __restrict__ qh, const __nv_bfloat16* __restrict__ ql,
    const __nv_bfloat16* __restrict__ kvh, const __nv_bfloat16* __restrict__ kvl,
    const __nv_bfloat16* __restrict__ vth, const __nv_bfloat16* __restrict__ vtl,
    const unsigned char* __restrict__ emask,
    __nv_bfloat16* __restrict__ vech, __nv_bfloat16* __restrict__ vecl)
{
    extern __shared__ char sm[];
    const uint32_t sb = smem_u32(sm);
    const int tid = threadIdx.x, lane = tid & 31, wid = tid >> 5;
    const int i0 = blockIdx.x << 7;
    const int b = blockIdx.y >> 3, n = blockIdx.y & 7;
    const int wrow = wid << 4;
    const int lr = lane & 7, lg = lane >> 3;
    const uint32_t a_off = (uint32_t)(((lg & 1) << 3) + lr) * 144u + (uint32_t)((lg >> 1) << 4);
    const uint32_t b_off = (uint32_t)(((lg >> 1) << 3) + lr) * 144u + (uint32_t)((lg & 1) << 4);
    const int qr_ = lane >> 2, qc_ = (lane & 3) << 1;
    const uint32_t AqH = sb + C_QH + wrow * 144, AqL = sb + C_QL + wrow * 144;
    const uint32_t ApH = sb + C_PH + wrow * 144, ApL = sb + C_PL + wrow * 144;

    for (int t = tid; t < 1024; t += 256) {
        const int row = t >> 3, c4 = t & 7;
        const size_t g = ((size_t)(i0 + row) * 8 + b) * 512 + n * 64 + c4 * 8;
        *(uint4*)(sm + C_QH + row * 144 + c4 * 16) = *(const uint4*)(qh + g);
        *(uint4*)(sm + C_QL + row * 144 + c4 * 16) = *(const uint4*)(ql + g);
    }

    float m0 = -1e30f, m1 = -1e30f, li0 = 0.f, li1 = 0.f;
    float o[8][4];
    #pragma unroll
    for (int nt = 0; nt < 8; nt++) { o[nt][0]=0; o[nt][1]=0; o[nt][2]=0; o[nt][3]=0; }

    for (int j0 = 0; j0 < ELEN; j0 += 64) {
        __syncthreads();
        for (int t = tid; t < 512; t += 256) {
            const int row = t >> 3, c4 = t & 7;
            const size_t g = ((size_t)(j0 + row) * 8 + b) * 1024 + n * 64 + c4 * 8;
            *(uint4*)(sm + C_KH + row * 144 + c4 * 16) = *(const uint4*)(kvh + g);
            *(uint4*)(sm + C_KL + row * 144 + c4 * 16) = *(const uint4*)(kvl + g);
        }
        for (int t = tid; t < 512; t += 256) {
            const int dr = t >> 3, c4 = t & 7;
            const size_t g = ((size_t)(b * 8 + n) * 64 + dr) * 1024 + j0 + c4 * 8;
            *(uint4*)(sm + C_VH + dr * 144 + c4 * 16) = *(const uint4*)(vth + g);
            *(uint4*)(sm + C_VL + dr * 144 + c4 * 16) = *(const uint4*)(vtl + g);
        }
        if (tid < 64) sm[C_FL + tid] = (char)emask[(size_t)(j0 + tid) * 8 + b];
        __syncthreads();

        float s[8][4];
        #pragma unroll
        for (int nt = 0; nt < 8; nt++) { s[nt][0]=0; s[nt][1]=0; s[nt][2]=0; s[nt][3]=0; }
        wgemm3(AqH, AqL, sb + C_KH, sb + C_KL, a_off, b_off, s);
        __syncwarp();

        const int rA = wrow + qr_, rB = rA + 8;
        float rmax0 = -1e30f, rmax1 = -1e30f;
        #pragma unroll
        for (int nt = 0; nt < 8; nt++) {
            const int col = (nt << 3) + qc_;
            const bool f0 = sm[C_FL + col] != 0, f1 = sm[C_FL + col + 1] != 0;
            s[nt][0] = f0 ? -1e4f : s[nt][0] * ATT_SCALE;
            s[nt][1] = f1 ? -1e4f : s[nt][1] * ATT_SCALE;
            s[nt][2] = f0 ? -1e4f : s[nt][2] * ATT_SCALE;
            s[nt][3] = f1 ? -1e4f : s[nt][3] * ATT_SCALE;
            rmax0 = fmaxf(rmax0, fmaxf(s[nt][0], s[nt][1]));
            rmax1 = fmaxf(rmax1, fmaxf(s[nt][2], s[nt][3]));
        }
        rmax0 = fmaxf(rmax0, __shfl_xor_sync(0xffffffffu, rmax0, 1));
        rmax0 = fmaxf(rmax0, __shfl_xor_sync(0xffffffffu, rmax0, 2));
        rmax1 = fmaxf(rmax1, __shfl_xor_sync(0xffffffffu, rmax1, 1));
        rmax1 = fmaxf(rmax1, __shfl_xor_sync(0xffffffffu, rmax1, 2));
        const float mn0 = fmaxf(m0, rmax0), mn1 = fmaxf(m1, rmax1);
        const float al0 = __expf(m0 - mn0), al1 = __expf(m1 - mn1);
        float rs0 = 0.f, rs1 = 0.f;
        #pragma unroll
        for (int nt = 0; nt < 8; nt++) {
            const int col = (nt << 3) + qc_;
            const float p0 = __expf(s[nt][0] - mn0), p1 = __expf(s[nt][1] - mn0);
            const float p2 = __expf(s[nt][2] - mn1), p3 = __expf(s[nt][3] - mn1);
            rs0 += p0 + p1; rs1 += p2 + p3;
            const __nv_bfloat16 h0 = __float2bfloat16(p0), h1 = __float2bfloat16(p1);
            const __nv_bfloat16 h2 = __float2bfloat16(p2), h3 = __float2bfloat16(p3);
            *(__nv_bfloat162*)(sm + C_PH + rA * 144 + col * 2) = __halves2bfloat162(h0, h1);
            *(__nv_bfloat162*)(sm + C_PL + rA * 144 + col * 2) = __halves2bfloat162(
                __float2bfloat16(p0 - __bfloat162float(h0)),
                __float2bfloat16(p1 - __bfloat162float(h1)));
            *(__nv_bfloat162*)(sm + C_PH + rB * 144 + col * 2) = __halves2bfloat162(h2, h3);
            *(__nv_bfloat162*)(sm + C_PL + rB * 144 + col * 2) = __halves2bfloat162(
                __float2bfloat16(p2 - __bfloat162float(h2)),
                __float2bfloat16(p3 - __bfloat162float(h3)));
            o[nt][0] *= al0; o[nt][1] *= al0; o[nt][2] *= al1; o[nt][3] *= al1;
        }
        rs0 += __shfl_xor_sync(0xffffffffu, rs0, 1);
        rs0 += __shfl_xor_sync(0xffffffffu, rs0, 2);
        rs1 += __shfl_xor_sync(0xffffffffu, rs1, 1);
        rs1 += __shfl_xor_sync(0xffffffffu, rs1, 2);
        li0 = li0 * al0 + rs0; li1 = li1 * al1 + rs1;
        m0 = mn0; m1 = mn1;
        __syncwarp();
        wgemm3(ApH, ApL, sb + C_VH, sb + C_VL, a_off, b_off, o);
    }

    const float iv0 = 1.f / li0, iv1 = 1.f / li1;
    const int rA = wrow + qr_;
    #pragma unroll
    for (int nt = 0; nt < 8; nt++) {
        const int d = (nt << 3) + qc_;
        const float v0 = o[nt][0] * iv0, v1 = o[nt][1] * iv0;
        const float v2 = o[nt][2] * iv1, v3 = o[nt][3] * iv1;
        const size_t gA = ((size_t)(i0 + rA) * 8 + b) * 512 + n * 64 + d;
        const size_t gB = ((size_t)(i0 + rA + 8) * 8 + b) * 512 + n * 64 + d;
        const __nv_bfloat16 h0 = __float2bfloat16(v0), h1 = __float2bfloat16(v1);
        const __nv_bfloat16 h2 = __float2bfloat16(v2), h3 = __float2bfloat16(v3);
        *(__nv_bfloat162*)(vech + gA) = __halves2bfloat162(h0, h1);
        *(__nv_bfloat162*)(vecl + gA) = __halves2bfloat162(
            __float2bfloat16(v0 - __bfloat162float(h0)),
            __float2bfloat16(v1 - __bfloat162float(h1)));
        *(__nv_bfloat162*)(vech + gB) = __halves2bfloat162(h2, h3);
        *(__nv_bfloat162*)(vecl + gB) = __halves2bfloat162(
            __float2bfloat16(v2 - __bfloat162float(h2)),
            __float2bfloat16(v3 - __bfloat162float(h3)));
    }
}

// ===================== host orchestration ====================================
extern "C" void kernel_launch(void* const* d_in, const int* in_sizes, int n_in,
                              void* d_out, int out_size)
{
    (void)in_sizes; (void)n_in; (void)out_size;
    const float* dec_inp = (const float*)d_in[0];
    const float* r       = (const float*)d_in[1];
    const float* enc_out = (const float*)d_in[2];
    const float* rwb     = (const float*)d_in[3];
    const float* rrb     = (const float*)d_in[4];
    const float* qkv_w   = (const float*)d_in[5];
    const float* r_w     = (const float*)d_in[6];
    const float* o_w     = (const float*)d_in[7];
    const float* ln1_g   = (const float*)d_in[8];
    const float* ln1_b   = (const float*)d_in[9];
    const float* q_w     = (const float*)d_in[10];
    const float* kv_w    = (const float*)d_in[11];
    const float* o2_w    = (const float*)d_in[12];
    const float* ln2_g   = (const float*)d_in[13];
    const float* ln2_b   = (const float*)d_in[14];
    const float* ff_w1   = (const float*)d_in[15];
    const float* ff_b1   = (const float*)d_in[16];
    const float* ff_w2   = (const float*)d_in[17];
    const float* ff_b2   = (const float*)d_in[18];
    const float* ln3_g   = (const float*)d_in[19];
    const float* ln3_b   = (const float*)d_in[20];
    const unsigned char* emask = (const unsigned char*)d_in[22];
    float* out = (float*)d_out;

    float *out1, *h2, *out2, *qbias, *ccv;
    __nv_bfloat16 *wthi, *wtlo, *hh, *hl, *headsh, *headsl, *rh, *rl, *rkh, *rkl;
    __nv_bfloat16 *vth, *vtl, *vech, *vecl, *h2h, *h2l, *q2h, *q2l, *eh, *el;
    __nv_bfloat16 *kvh, *kvl, *vt2h, *vt2l, *vec2h, *vec2l, *th, *tl;
    cudaGetSymbolAddress((void**)&out1,  g_out1);
    cudaGetSymbolAddress((void**)&h2,    g_h2);
    cudaGetSymbolAddress((void**)&out2,  g_out2);
    cudaGetSymbolAddress((void**)&qbias, g_qbias);
    cudaGetSymbolAddress((void**)&ccv,   g_cc);
    cudaGetSymbolAddress((void**)&wthi,  g_wthi);
    cudaGetSymbolAddress((void**)&wtlo,  g_wtlo);
    cudaGetSymbolAddress((void**)&hh,    g_hh);
    cudaGetSymbolAddress((void**)&hl,    g_hl);
    cudaGetSymbolAddress((void**)&headsh,g_headsh);
    cudaGetSymbolAddress((void**)&headsl,g_headsl);
    cudaGetSymbolAddress((void**)&rh,    g_rh);
    cudaGetSymbolAddress((void**)&rl,    g_rl);
    cudaGetSymbolAddress((void**)&rkh,   g_rkh);
    cudaGetSymbolAddress((void**)&rkl,   g_rkl);
    cudaGetSymbolAddress((void**)&vth,   g_vth);
    cudaGetSymbolAddress((void**)&vtl,   g_vtl);
    cudaGetSymbolAddress((void**)&vech,  g_vech);
    cudaGetSymbolAddress((void**)&vecl,  g_vecl);
    cudaGetSymbolAddress((void**)&h2h,   g_h2h);
    cudaGetSymbolAddress((void**)&h2l,   g_h2l);
    cudaGetSymbolAddress((void**)&q2h,   g_q2h);
    cudaGetSymbolAddress((void**)&q2l,   g_q2l);
    cudaGetSymbolAddress((void**)&eh,    g_eh);
    cudaGetSymbolAddress((void**)&el,    g_el);
    cudaGetSymbolAddress((void**)&kvh,   g_kvh);
    cudaGetSymbolAddress((void**)&kvl,   g_kvl);
    cudaGetSymbolAddress((void**)&vt2h,  g_vt2h);
    cudaGetSymbolAddress((void**)&vt2l,  g_vt2l);
    cudaGetSymbolAddress((void**)&vec2h, g_vec2h);
    cudaGetSymbolAddress((void**)&vec2l, g_vec2l);
    cudaGetSymbolAddress((void**)&th,    g_th);
    cudaGetSymbolAddress((void**)&tl,    g_tl);

    cudaFuncSetAttribute(flash_rel_mma, cudaFuncAttributeMaxDynamicSharedMemorySize, REL_SMEM);
    cudaFuncSetAttribute(flash_ctx_mma, cudaFuncAttributeMaxDynamicSharedMemorySize, CTX_SMEM);
    cudaFuncSetAttribute(gemm_hmma<false, false>, cudaFuncAttributeMaxDynamicSharedMemorySize, GH_SMEM);
    cudaFuncSetAttribute(gemm_hmma<false, true>,  cudaFuncAttributeMaxDynamicSharedMemorySize, GH_SMEM);
    cudaFuncSetAttribute(gemm_hmma<true, true>,   cudaFuncAttributeMaxDynamicSharedMemorySize, GH_SMEM);

    // ---- weights + misc prep ----
    tsplit_k<<<dim3(48, 16), 256>>>(qkv_w, wthi + WT_QKV, wtlo + WT_QKV, 512, 1536);
    tsplit_k<<<dim3(16, 16), 256>>>(r_w,   wthi + WT_RW,  wtlo + WT_RW,  512, 512);
    tsplit_k<<<dim3(16, 16), 256>>>(o_w,   wthi + WT_OW,  wtlo + WT_OW,  512, 512);
    tsplit_k<<<dim3(16, 16), 256>>>(q_w,   wthi + WT_QW,  wtlo + WT_QW,  512, 512);
    tsplit_k<<<dim3(32, 16), 256>>>(kv_w,  wthi + WT_KVW, wtlo + WT_KVW, 512, 1024);
    tsplit_k<<<dim3(16, 16), 256>>>(o2_w,  wthi + WT_O2W, wtlo + WT_O2W, 512, 512);
    tsplit_k<<<dim3(64, 16), 256>>>(ff_w1, wthi + WT_FF1, wtlo + WT_FF1, 512, 2048);
    tsplit_k<<<dim3(16, 64), 256>>>(ff_w2, wthi + WT_FF2, wtlo + WT_FF2, 2048, 512);
    qbias_k<<<6, 256>>>(rwb, qbias);
    split_k<<<QLEN * DMODEL / 1024, 256>>>(r, rh, rl, QLEN * DMODEL / 4);
    split_k<<<ROWS * DMODEL / 1024, 256>>>(enc_out, eh, el, ROWS * DMODEL / 4);

    // ---- block 1: relative self-attention ----
    ln_k<false, true><<<ROWS, 128>>>(dec_inp, ln1_g, ln1_b, nullptr, hh, hl);
    gemm_hmma<false, true><<<dim3(12, 64), 256, GH_SMEM>>>(
        hh, hl, wthi + WT_QKV, wtlo + WT_QKV, qbias, nullptr,
        nullptr, headsh, headsl, ROWS, 1536, 512);
    gemm_hmma<false, true><<<dim3(4, 8), 256, GH_SMEM>>>(
        rh, rl, wthi + WT_RW, wtlo + WT_RW, nullptr, nullptr,
        nullptr, rkh, rkl, QLEN, 512, 512);
    vtrans_k<<<dim3(32, 64), 256>>>(headsh, headsl, vth, vtl, 1536, 1024);
    c_k<<<1024, 256>>>(rkh, rkl, rwb, rrb, ccv);
    flash_rel_mma<<<dim3(16, 64), 256, REL_SMEM>>>(headsh, headsl, vth, vtl,
                                                   rkh, rkl, ccv, vech, vecl);
    gemm_hmma<false, false><<<dim3(4, 64), 256, GH_SMEM>>>(
        vech, vecl, wthi + WT_OW, wtlo + WT_OW, nullptr, dec_inp,
        out1, nullptr, nullptr, ROWS, 512, 512);

    // ---- block 2: cross attention ----
    ln_k<true, true><<<ROWS, 128>>>(out1, ln2_g, ln2_b, h2, h2h, h2l);
    gemm_hmma<false, true><<<dim3(4, 64), 256, GH_SMEM>>>(
        h2h, h2l, wthi + WT_QW, wtlo + WT_QW, nullptr, nullptr,
        nullptr, q2h, q2l, ROWS, 512, 512);
    gemm_hmma<false, true><<<dim3(8, 64), 256, GH_SMEM>>>(
        eh, el, wthi + WT_KVW, wtlo + WT_KVW, nullptr, nullptr,
        nullptr, kvh, kvl, ROWS, 1024, 512);
    vtrans_k<<<dim3(32, 64), 256>>>(kvh, kvl, vt2h, vt2l, 1024, 512);
    flash_ctx_mma<<<dim3(8, 64), 256, CTX_SMEM>>>(q2h, q2l, kvh, kvl, vt2h, vt2l,
                                                  emask, vec2h, vec2l);
    gemm_hmma<false, false><<<dim3(4, 64), 256, GH_SMEM>>>(
        vec2h, vec2l, wthi + WT_O2W, wtlo + WT_O2W, nullptr, h2,
        out2, nullptr, nullptr, ROWS, 512, 512);

    // ---- block 3: FF ----
    ln_k<false, true><<<ROWS, 128>>>(out2, ln3_g, ln3_b, nullptr, hh, hl);
    gemm_hmma<true, true><<<dim3(16, 64), 256, GH_SMEM>>>(
        hh, hl, wthi + WT_FF1, wtlo + WT_FF1, ff_b1, nullptr,
        nullptr, th, tl, ROWS, 2048, 512);
    gemm_hmma<false, false><<<dim3(4, 64), 256, GH_SMEM>>>(
        th, tl, wthi + WT_FF2, wtlo + WT_FF2, ff_b2, out2,
        out, nullptr, nullptr, ROWS, 512, 2048);
}

// round 10
// speedup vs baseline: 2.6505x; 1.1140x over previous
#include <cuda_runtime.h>
#include <cuda_bf16.h>
#include <cstdint>
#include <cstddef>

#define QLEN   1024
#define BATCH  8
#define DMODEL 512
#define NHEAD  8
#define DHEAD  64
#define DINNER 2048
#define ELEN   1024
#define ATT_SCALE 0.125f
#define ROWS (QLEN * BATCH)   /* 8192 */

// ===================== warp MMA helpers =====================================
__device__ __forceinline__ uint32_t smem_u32(const void* p) {
    uint32_t a;
    asm("{ .reg .u64 t; cvta.to.shared.u64 t, %1; cvt.u32.u64 %0, t; }"
        : "=r"(a) : "l"(p));
    return a;
}

__device__ __forceinline__ void ldsm4(uint32_t* r, uint32_t addr) {
    asm volatile("ldmatrix.sync.aligned.m8n8.x4.shared.b16 {%0,%1,%2,%3}, [%4];"
                 : "=r"(r[0]), "=r"(r[1]), "=r"(r[2]), "=r"(r[3]) : "r"(addr));
}

__device__ __forceinline__ void mma16816(float* d, const uint32_t* a, const uint32_t* b) {
    asm volatile(
        "mma.sync.aligned.m16n8k16.row.col.f32.bf16.bf16.f32 "
        "{%0,%1,%2,%3}, {%4,%5,%6,%7}, {%8,%9}, {%0,%1,%2,%3};"
        : "+f"(d[0]), "+f"(d[1]), "+f"(d[2]), "+f"(d[3])
        : "r"(a[0]), "r"(a[1]), "r"(a[2]), "r"(a[3]), "r"(b[0]), "r"(b[1]));
}

__device__ __forceinline__ void cpa16(uint32_t dst, const void* src) {
    asm volatile("cp.async.cg.shared.global [%0], [%1], 16;" :: "r"(dst), "l"(src));
}

__device__ __forceinline__ void barp(int id) {
    asm volatile("bar.sync %0, %1;" :: "r"(id), "r"(64) : "memory");
}

// 3-term split-bf16 warp GEMM, 64-col B (nt=8), K=64, 144B stride (flash)
__device__ __forceinline__ void wgemm3(uint32_t Ah, uint32_t Al,
                                       uint32_t Bh, uint32_t Bl,
                                       uint32_t a_off, uint32_t b_off,
                                       float acc[8][4])
{
    #pragma unroll
    for (int ks = 0; ks < 4; ks++) {
        const uint32_t ra = (uint32_t)(ks << 5);
        uint32_t ah[4], al[4];
        ldsm4(ah, Ah + ra + a_off);
        ldsm4(al, Al + ra + a_off);
        #pragma unroll
        for (int np = 0; np < 4; np++) {
            uint32_t bh[4], bl[4];
            const uint32_t rb = (uint32_t)(np * 16 * 144 + (ks << 5));
            ldsm4(bh, Bh + rb + b_off);
            ldsm4(bl, Bl + rb + b_off);
            #pragma unroll
            for (int hf = 0; hf < 2; hf++) {
                float* d = acc[(np << 1) + hf];
                mma16816(d, ah, bh + (hf << 1));
                mma16816(d, ah, bl + (hf << 1));
                mma16816(d, al, bh + (hf << 1));
            }
        }
    }
}

// nt=4 variant (32-col B), 144B stride
__device__ __forceinline__ void wgemm3_nt4(uint32_t Ah, uint32_t Al,
                                           uint32_t Bh, uint32_t Bl,
                                           uint32_t a_off, uint32_t b_off,
                                           float acc[4][4])
{
    #pragma unroll
    for (int ks = 0; ks < 4; ks++) {
        const uint32_t ra = (uint32_t)(ks << 5);
        uint32_t ah[4], al[4];
        ldsm4(ah, Ah + ra + a_off);
        ldsm4(al, Al + ra + a_off);
        #pragma unroll
        for (int np = 0; np < 2; np++) {
            uint32_t bh[4], bl[4];
            const uint32_t rb = (uint32_t)(np * 16 * 144 + (ks << 5));
            ldsm4(bh, Bh + rb + b_off);
            ldsm4(bl, Bl + rb + b_off);
            #pragma unroll
            for (int hf = 0; hf < 2; hf++) {
                float* d = acc[(np << 1) + hf];
                mma16816(d, ah, bh + (hf << 1));
                mma16816(d, ah, bl + (hf << 1));
                mma16816(d, al, bh + (hf << 1));
            }
        }
    }
}

__device__ __forceinline__ void split_store4(char* hi, char* lo, float4 v) {
    const __nv_bfloat16 h0 = __float2bfloat16(v.x), h1 = __float2bfloat16(v.y);
    const __nv_bfloat16 h2 = __float2bfloat16(v.z), h3 = __float2bfloat16(v.w);
    *(__nv_bfloat162*)(hi)     = __halves2bfloat162(h0, h1);
    *(__nv_bfloat162*)(hi + 4) = __halves2bfloat162(h2, h3);
    *(__nv_bfloat162*)(lo)     = __halves2bfloat162(
        __float2bfloat16(v.x - __bfloat162float(h0)),
        __float2bfloat16(v.y - __bfloat162float(h1)));
    *(__nv_bfloat162*)(lo + 4) = __halves2bfloat162(
        __float2bfloat16(v.z - __bfloat162float(h2)),
        __float2bfloat16(v.w - __bfloat162float(h3)));
}

// ===================== scratch ==============================================
__device__ float g_out1[ROWS * DMODEL];
__device__ float g_h2  [ROWS * DMODEL];
__device__ float g_out2[ROWS * DMODEL];
__device__ float g_qbias[3 * DMODEL];
__device__ float g_cc  [NHEAD * 1152];        // zero-init pad beyond 1024

__device__ __nv_bfloat16 g_hh[ROWS * DMODEL],    g_hl[ROWS * DMODEL];
__device__ __nv_bfloat16 g_headsh[ROWS * 1536],  g_headsl[ROWS * 1536];
__device__ __nv_bfloat16 g_rh[QLEN * DMODEL],    g_rl[QLEN * DMODEL];
__device__ __nv_bfloat16 g_rkh[QLEN * DMODEL],   g_rkl[QLEN * DMODEL];
__device__ __nv_bfloat16 g_vth[64 * 64 * QLEN],  g_vtl[64 * 64 * QLEN];
__device__ __nv_bfloat16 g_vech[ROWS * DMODEL],  g_vecl[ROWS * DMODEL];
__device__ __nv_bfloat16 g_h2h[ROWS * DMODEL],   g_h2l[ROWS * DMODEL];
__device__ __nv_bfloat16 g_q2h[ROWS * DMODEL],   g_q2l[ROWS * DMODEL];
__device__ __nv_bfloat16 g_eh[ROWS * DMODEL],    g_el[ROWS * DMODEL];
__device__ __nv_bfloat16 g_kvh[ROWS * 1024],     g_kvl[ROWS * 1024];
__device__ __nv_bfloat16 g_vt2h[64 * 64 * ELEN], g_vt2l[64 * 64 * ELEN];
__device__ __nv_bfloat16 g_vec2h[ROWS * DMODEL], g_vec2l[ROWS * DMODEL];
__device__ __nv_bfloat16 g_th[ROWS * DINNER],    g_tl[ROWS * DINNER];

#define WT_QKV 0
#define WT_RW  786432
#define WT_OW  1048576
#define WT_QW  1310720
#define WT_KVW 1572864
#define WT_O2W 2097152
#define WT_FF1 2359296
#define WT_FF2 3407872
#define WT_TOTAL 4456448
__device__ __nv_bfloat16 g_wthi[WT_TOTAL];
__device__ __nv_bfloat16 g_wtlo[WT_TOTAL];

// ===================== small prep kernels ===================================
__global__ __launch_bounds__(256) void split_k(const float* __restrict__ x,
                                               __nv_bfloat16* __restrict__ hi,
                                               __nv_bfloat16* __restrict__ lo, int n4)
{
    const int i = blockIdx.x * 256 + threadIdx.x;
    if (i >= n4) return;
    const float4 v = reinterpret_cast<const float4*>(x)[i];
    split_store4((char*)(hi + (size_t)i * 4), (char*)(lo + (size_t)i * 4), v);
}

// all 8 weight transposes+splits in one launch (linear block-range dispatch)
__global__ __launch_bounds__(256) void tsplit_all(
    const float* __restrict__ qkv, const float* __restrict__ rw,
    const float* __restrict__ ow,  const float* __restrict__ qw,
    const float* __restrict__ kvw, const float* __restrict__ o2w,
    const float* __restrict__ ff1, const float* __restrict__ ff2,
    __nv_bfloat16* __restrict__ hi, __nv_bfloat16* __restrict__ lo)
{
    int bid = blockIdx.x;
    const float* W; int K, N, gx; size_t off;
    if (bid < 768)                      { W = qkv; K = 512;  N = 1536; gx = 48; off = WT_QKV; }
    else if ((bid -= 768)  < 256)       { W = rw;  K = 512;  N = 512;  gx = 16; off = WT_RW;  }
    else if ((bid -= 256)  < 256)       { W = ow;  K = 512;  N = 512;  gx = 16; off = WT_OW;  }
    else if ((bid -= 256)  < 256)       { W = qw;  K = 512;  N = 512;  gx = 16; off = WT_QW;  }
    else if ((bid -= 256)  < 512)       { W = kvw; K = 512;  N = 1024; gx = 32; off = WT_KVW; }
    else if ((bid -= 512)  < 256)       { W = o2w; K = 512;  N = 512;  gx = 16; off = WT_O2W; }
    else if ((bid -= 256)  < 1024)      { W = ff1; K = 512;  N = 2048; gx = 64; off = WT_FF1; }
    else { bid -= 1024;                   W = ff2; K = 2048; N = 512;  gx = 16; off = WT_FF2; }

    __shared__ float t[32][33];
    const int n0 = (bid % gx) << 5, k0 = (bid / gx) << 5;
    const int x = threadIdx.x & 31, y = threadIdx.x >> 5;
    #pragma unroll
    for (int i = 0; i < 32; i += 8)
        t[y + i][x] = W[(size_t)(k0 + y + i) * N + n0 + x];
    __syncthreads();
    #pragma unroll
    for (int i = 0; i < 32; i += 8) {
        const float v = t[x][y + i];
        const size_t o = off + (size_t)(n0 + y + i) * K + k0 + x;
        const __nv_bfloat16 h = __float2bfloat16(v);
        hi[o] = h;
        lo[o] = __float2bfloat16(v - __bfloat162float(h));
    }
}

__global__ void qbias_k(const float* __restrict__ rwb, float* __restrict__ qb) {
    const int i = blockIdx.x * 256 + threadIdx.x;
    if (i < 1536) qb[i] = (i < 512) ? rwb[i] : 0.0f;
}

// c[n][u] = sum_d (rrb-rwb)[n][d] * rk[u][n*64+d]
__global__ __launch_bounds__(256) void c_k(const __nv_bfloat16* __restrict__ rkh,
                                           const __nv_bfloat16* __restrict__ rkl,
                                           const float* __restrict__ rwb,
                                           const float* __restrict__ rrb,
                                           float* __restrict__ cc)
{
    const int u = blockIdx.x;
    const int n = threadIdx.x >> 5, lane = threadIdx.x & 31;
    float s = 0.0f;
    #pragma unroll
    for (int k = 0; k < 2; k++) {
        const int d = lane + k * 32;
        const size_t g = (size_t)u * 512 + n * 64 + d;
        const float rv = __bfloat162float(rkh[g]) + __bfloat162float(rkl[g]);
        s += (rrb[n * 64 + d] - rwb[n * 64 + d]) * rv;
    }
    #pragma unroll
    for (int o = 16; o; o >>= 1) s += __shfl_xor_sync(0xffffffffu, s, o);
    if (lane == 0) cc[n * 1152 + u] = s;
}

// transpose V-part: src[(i*8+b)*stride + off + n*64 + d] -> dst[((b*8+n)*64+d)*1024 + i]
__global__ __launch_bounds__(256) void vtrans_k(const __nv_bfloat16* __restrict__ sh,
                                                const __nv_bfloat16* __restrict__ sl,
                                                __nv_bfloat16* __restrict__ dh,
                                                __nv_bfloat16* __restrict__ dl,
                                                int srcStride, int srcOff)
{
    __shared__ __nv_bfloat16 th[32][72], tl[32][72];
    const int i0 = blockIdx.x << 5;
    const int b = blockIdx.y >> 3, n = blockIdx.y & 7;
    const int t = threadIdx.x;
    {
        const int il = t >> 3, dj = (t & 7) << 3;
        const size_t g = ((size_t)(i0 + il) * 8 + b) * srcStride + srcOff + n * 64 + dj;
        *(uint4*)&th[il][dj] = *(const uint4*)(sh + g);
        *(uint4*)&tl[il][dj] = *(const uint4*)(sl + g);
    }
    __syncthreads();
    {
        const int dr = t >> 2, ij = (t & 3) << 3;
        __nv_bfloat16 oh[8], ol[8];
        #pragma unroll
        for (int k = 0; k < 8; k++) { oh[k] = th[ij + k][dr]; ol[k] = tl[ij + k][dr]; }
        const size_t g = ((size_t)(b * 8 + n) * 64 + dr) * 1024 + i0 + ij;
        *(uint4*)(dh + g) = *(uint4*)oh;
        *(uint4*)(dl + g) = *(uint4*)ol;
    }
}

// ===================== pipelined HMMA GEMM ==================================
// K-chunk 32, 2-stage cp.async double buffer. Tiles [128][40] bf16, 80B stride.
// stage s base = s*40960; tiles: AH +0, AL +10240, BH +20480, BL +30720
#define GP_STAGE 40960
#define GP_SMEM  81920

template <bool GELU, bool SPLIT>
__global__ __launch_bounds__(256, 2) void gemm_hmma(const __nv_bfloat16* __restrict__ Ahi,
                                                    const __nv_bfloat16* __restrict__ Alo,
                                                    const __nv_bfloat16* __restrict__ Bhi,
                                                    const __nv_bfloat16* __restrict__ Blo,
                                                    const float* __restrict__ bias,
                                                    const float* __restrict__ res,
                                                    float* __restrict__ C,
                                                    __nv_bfloat16* __restrict__ Ch,
                                                    __nv_bfloat16* __restrict__ Cl,
                                                    int M, int N, int K)
{
    extern __shared__ char smem[];
    const uint32_t sb = smem_u32(smem);
    const int tid = threadIdx.x;
    const int lane = tid & 31, wid = tid >> 5;
    const int m0 = blockIdx.y << 7, n0 = blockIdx.x << 7;
    const int wm = (wid & 3) << 5;
    const int wn = (wid >> 2) << 6;
    (void)M;

    float acc[2][8][4];
    #pragma unroll
    for (int mt = 0; mt < 2; mt++)
        #pragma unroll
        for (int nt = 0; nt < 8; nt++)
            #pragma unroll
            for (int e = 0; e < 4; e++) acc[mt][nt][e] = 0.0f;

    const int lr = lane & 7, lg = lane >> 3;
    const uint32_t a_off = (uint32_t)(((lg & 1) << 3) + lr) * 80u + (uint32_t)((lg >> 1) << 4);
    const uint32_t b_off = (uint32_t)(((lg >> 1) << 3) + lr) * 80u + (uint32_t)((lg & 1) << 4);

    const int nch = K >> 5;

    // chunk loader: 2048 cp.async of 16B (4 tiles x 128 rows x 64B)
    auto load_chunk = [&](int c, int s) {
        const int k0 = c << 5;
        const uint32_t sbase = sb + s * GP_STAGE;
        #pragma unroll
        for (int i = tid; i < 2048; i += 256) {
            const int tile = i >> 9;
            const int idx = i & 511;
            const int row = idx >> 2, kc = (idx & 3) << 3;
            const uint32_t dst = sbase + tile * 10240 + row * 80 + (idx & 3) * 16;
            const __nv_bfloat16* src;
            if (tile == 0)      src = Ahi + (size_t)(m0 + row) * K + k0 + kc;
            else if (tile == 1) src = Alo + (size_t)(m0 + row) * K + k0 + kc;
            else if (tile == 2) src = Bhi + (size_t)(n0 + row) * K + k0 + kc;
            else                src = Blo + (size_t)(n0 + row) * K + k0 + kc;
            cpa16(dst, src);
        }
        asm volatile("cp.async.commit_group;" ::: "memory");
    };

    load_chunk(0, 0);
    load_chunk(1, 1);

    for (int c = 0; c < nch; c++) {
        if (c + 1 < nch) asm volatile("cp.async.wait_group 1;" ::: "memory");
        else             asm volatile("cp.async.wait_group 0;" ::: "memory");
        __syncthreads();

        const uint32_t sbase = sb + (c & 1) * GP_STAGE;
        #pragma unroll
        for (int ks = 0; ks < 2; ks++) {
            const uint32_t kk2 = (uint32_t)(ks << 5);
            uint32_t ah[2][4], al[2][4];
            #pragma unroll
            for (int mt = 0; mt < 2; mt++) {
                const uint32_t ra = (uint32_t)((wm + (mt << 4)) * 80) + kk2 + a_off;
                ldsm4(ah[mt], sbase + ra);
                ldsm4(al[mt], sbase + 10240 + ra);
            }
            #pragma unroll
            for (int np = 0; np < 4; np++) {
                uint32_t bh[4], bl[4];
                const uint32_t rb = (uint32_t)((wn + (np << 4)) * 80) + kk2 + b_off;
                ldsm4(bh, sbase + 20480 + rb);
                ldsm4(bl, sbase + 30720 + rb);
                #pragma unroll
                for (int mt = 0; mt < 2; mt++) {
                    #pragma unroll
                    for (int hf = 0; hf < 2; hf++) {
                        float* d = acc[mt][(np << 1) + hf];
                        mma16816(d, ah[mt], bh + (hf << 1));
                        mma16816(d, ah[mt], bl + (hf << 1));
                        mma16816(d, al[mt], bh + (hf << 1));
                    }
                }
            }
        }
        __syncthreads();
        if (c + 2 < nch) load_chunk(c + 2, c & 1);
    }

    const int er = lane >> 2, ec = (lane & 3) << 1;
    #pragma unroll
    for (int mt = 0; mt < 2; mt++) {
        #pragma unroll
        for (int half = 0; half < 2; half++) {
            const int gr = m0 + wm + (mt << 4) + er + (half << 3);
            #pragma unroll
            for (int nt = 0; nt < 8; nt++) {
                const int gc = n0 + wn + (nt << 3) + ec;
                float v0 = acc[mt][nt][(half << 1) + 0];
                float v1 = acc[mt][nt][(half << 1) + 1];
                if (bias) { v0 += bias[gc]; v1 += bias[gc + 1]; }
                if (GELU) {
                    v0 = 0.5f * v0 * (1.0f + erff(v0 * 0.70710678118654752f));
                    v1 = 0.5f * v1 * (1.0f + erff(v1 * 0.70710678118654752f));
                }
                if (SPLIT) {
                    const __nv_bfloat16 h0 = __float2bfloat16(v0), h1 = __float2bfloat16(v1);
                    *(__nv_bfloat162*)(Ch + (size_t)gr * N + gc) = __halves2bfloat162(h0, h1);
                    *(__nv_bfloat162*)(Cl + (size_t)gr * N + gc) = __halves2bfloat162(
                        __float2bfloat16(v0 - __bfloat162float(h0)),
                        __float2bfloat16(v1 - __bfloat162float(h1)));
                } else {
                    if (res) {
                        const float2 rr = *reinterpret_cast<const float2*>(&res[(size_t)gr * N + gc]);
                        v0 += rr.x; v1 += rr.y;
                    }
                    *reinterpret_cast<float2*>(&C[(size_t)gr * N + gc]) = make_float2(v0, v1);
                }
            }
        }
    }
}

// ===================== LayerNorm ============================================
template <bool F32O, bool SPL>
__global__ __launch_bounds__(128) void ln_k(const float* __restrict__ x,
                                            const float* __restrict__ g,
                                            const float* __restrict__ b,
                                            float* __restrict__ yf,
                                            __nv_bfloat16* __restrict__ yh,
                                            __nv_bfloat16* __restrict__ yl)
{
    const int row = blockIdx.x;
    const int t = threadIdx.x;
    const float4 v = reinterpret_cast<const float4*>(x + (size_t)row * DMODEL)[t];
    float s  = v.x + v.y + v.z + v.w;
    float sq = v.x*v.x + v.y*v.y + v.z*v.z + v.w*v.w;
    #pragma unroll
    for (int o = 16; o; o >>= 1) {
        s  += __shfl_xor_sync(0xffffffffu, s,  o);
        sq += __shfl_xor_sync(0xffffffffu, sq, o);
    }
    __shared__ float ss[4], sqq[4];
    const int w = t >> 5, lane = t & 31;
    if (lane == 0) { ss[w] = s; sqq[w] = sq; }
    __syncthreads();
    s  = ss[0]  + ss[1]  + ss[2]  + ss[3];
    sq = sqq[0] + sqq[1] + sqq[2] + sqq[3];
    const float mean = s * (1.0f / DMODEL);
    const float var  = sq * (1.0f / DMODEL) - mean * mean;
    const float rstd = rsqrtf(var + 1e-5f);
    const float4 gg = reinterpret_cast<const float4*>(g)[t];
    const float4 bb = reinterpret_cast<const float4*>(b)[t];
    float4 o4;
    o4.x = (v.x - mean) * rstd * gg.x + bb.x;
    o4.y = (v.y - mean) * rstd * gg.y + bb.y;
    o4.z = (v.z - mean) * rstd * gg.z + bb.z;
    o4.w = (v.w - mean) * rstd * gg.w + bb.w;
    if (F32O) reinterpret_cast<float4*>(yf + (size_t)row * DMODEL)[t] = o4;
    if (SPL)  split_store4((char*)(yh + (size_t)row * DMODEL + t * 4),
                           (char*)(yl + (size_t)row * DMODEL + t * 4), o4);
}

// ===================== flash attention 1 (rel, causal), 256 thr =============
#define R_QH 0
#define R_QL 9216
#define R_KH 18432
#define R_KL 27648
#define R_VH 36864
#define R_VL 46080
#define R_PH 55296
#define R_PL 64512
#define R_RH 73728
#define R_RL 92160
#define R_G  110592
#define R_C  144384
#define R_PM 144640
#define R_PS 145152
#define REL_SMEM 145664

__global__ __launch_bounds__(256) void flash_rel_mma(
    const __nv_bfloat16* __restrict__ hh, const __nv_bfloat16* __restrict__ hl,
    const __nv_bfloat16* __restrict__ vth, const __nv_bfloat16* __restrict__ vtl,
    const __nv_bfloat16* __restrict__ rkh, const __nv_bfloat16* __restrict__ rkl,
    const float* __restrict__ cc,
    __nv_bfloat16* __restrict__ vech, __nv_bfloat16* __restrict__ vecl)
{
    extern __shared__ char sm[];
    const uint32_t sb = smem_u32(sm);
    const int tid = threadIdx.x, lane = tid & 31, wid = tid >> 5;
    const int p = wid >> 1, h = wid & 1;
    const int i0 = blockIdx.x << 6;
    const int b = blockIdx.y >> 3, n = blockIdx.y & 7;
    const int lr = lane & 7, lg = lane >> 3;
    const uint32_t a_off = (uint32_t)(((lg & 1) << 3) + lr) * 144u + (uint32_t)((lg >> 1) << 4);
    const uint32_t b_off = (uint32_t)(((lg >> 1) << 3) + lr) * 144u + (uint32_t)((lg & 1) << 4);
    const int qr_ = lane >> 2, qc_ = (lane & 3) << 1;
    float* G    = (float*)(sm + R_G);
    float* csm  = (float*)(sm + R_C);
    float* pmax = (float*)(sm + R_PM);
    float* psum = (float*)(sm + R_PS);
    const uint32_t AqH = sb + R_QH + p * 16 * 144, AqL = sb + R_QL + p * 16 * 144;
    const uint32_t ApH = sb + R_PH + p * 16 * 144, ApL = sb + R_PL + p * 16 * 144;

    // ---- prologue: q tile (rwb pre-folded), ring block 0, c block
    for (int t = tid; t < 512; t += 256) {
        const int row = t >> 3, c4 = t & 7;
        const size_t g = ((size_t)(i0 + row) * 8 + b) * 1536 + n * 64 + c4 * 8;
        *(uint4*)(sm + R_QH + row * 144 + c4 * 16) = *(const uint4*)(hh + g);
        *(uint4*)(sm + R_QL + row * 144 + c4 * 16) = *(const uint4*)(hl + g);
    }
    const int ustart = 960 - i0;
    for (int t = tid; t < 512; t += 256) {
        const int jr = t >> 3, c4 = t & 7;
        const int u = ustart + jr, slot = u & 127;
        uint4 vh = make_uint4(0, 0, 0, 0), vl = make_uint4(0, 0, 0, 0);
        if (u < QLEN) {
            const size_t g = (size_t)u * 512 + n * 64 + c4 * 8;
            vh = *(const uint4*)(rkh + g);
            vl = *(const uint4*)(rkl + g);
        }
        *(uint4*)(sm + R_RH + slot * 144 + c4 * 16) = vh;
        *(uint4*)(sm + R_RL + slot * 144 + c4 * 16) = vl;
    }
    if (tid < 64) csm[tid] = cc[n * 1152 + ustart + tid];
    __syncthreads();
    {
        const int slotb = ustart & 127;
        float g4[4][4];
        #pragma unroll
        for (int nt = 0; nt < 4; nt++) { g4[nt][0]=0; g4[nt][1]=0; g4[nt][2]=0; g4[nt][3]=0; }
        wgemm3_nt4(AqH, AqL, sb + R_RH + (slotb + h * 32) * 144,
                   sb + R_RL + (slotb + h * 32) * 144, a_off, b_off, g4);
        #pragma unroll
        for (int nt = 0; nt < 4; nt++) {
            const int cl = h * 32 + (nt << 3) + qc_;
            const int col = slotb + cl;
            const float c0 = csm[cl], c1 = csm[cl + 1];
            *(float2*)&G[(16 * p + qr_) * 132 + col]     = make_float2(g4[nt][0] + c0, g4[nt][1] + c1);
            *(float2*)&G[(16 * p + qr_ + 8) * 132 + col] = make_float2(g4[nt][2] + c0, g4[nt][3] + c1);
        }
    }

    float m0 = -1e30f, m1 = -1e30f, li0 = 0.f, li1 = 0.f;
    float o[4][4];
    #pragma unroll
    for (int nt = 0; nt < 4; nt++) { o[nt][0]=0; o[nt][1]=0; o[nt][2]=0; o[nt][3]=0; }

    for (int j0 = 0; j0 <= i0; j0 += 64) {
        __syncthreads();
        // K tile
        for (int t = tid; t < 512; t += 256) {
            const int row = t >> 3, c4 = t & 7;
            const size_t g = ((size_t)(j0 + row) * 8 + b) * 1536 + 512 + n * 64 + c4 * 8;
            *(uint4*)(sm + R_KH + row * 144 + c4 * 16) = *(const uint4*)(hh + g);
            *(uint4*)(sm + R_KL + row * 144 + c4 * 16) = *(const uint4*)(hl + g);
        }
        // V^T tile
        for (int t = tid; t < 512; t += 256) {
            const int dr = t >> 3, c4 = t & 7;
            const size_t g = ((size_t)(b * 8 + n) * 64 + dr) * 1024 + j0 + c4 * 8;
            *(uint4*)(sm + R_VH + dr * 144 + c4 * 16) = *(const uint4*)(vth + g);
            *(uint4*)(sm + R_VL + dr * 144 + c4 * 16) = *(const uint4*)(vtl + g);
        }
        // new ring block + c block
        const int ub = ustart + j0 + 64;
        for (int t = tid; t < 512; t += 256) {
            const int jr = t >> 3, c4 = t & 7;
            const int u = ub + jr, slot = u & 127;
            uint4 vh = make_uint4(0, 0, 0, 0), vl = make_uint4(0, 0, 0, 0);
            if (u < QLEN) {
                const size_t g = (size_t)u * 512 + n * 64 + c4 * 8;
                vh = *(const uint4*)(rkh + g);
                vl = *(const uint4*)(rkl + g);
            }
            *(uint4*)(sm + R_RH + slot * 144 + c4 * 16) = vh;
            *(uint4*)(sm + R_RL + slot * 144 + c4 * 16) = vl;
        }
        if (tid < 64) csm[tid] = cc[n * 1152 + ub + tid];
        __syncthreads();
        // G for new block
        {
            const int slotb = ub & 127;
            float g4[4][4];
            #pragma unroll
            for (int nt = 0; nt < 4; nt++) { g4[nt][0]=0; g4[nt][1]=0; g4[nt][2]=0; g4[nt][3]=0; }
            wgemm3_nt4(AqH, AqL, sb + R_RH + (slotb + h * 32) * 144,
                       sb + R_RL + (slotb + h * 32) * 144, a_off, b_off, g4);
            #pragma unroll
            for (int nt = 0; nt < 4; nt++) {
                const int cl = h * 32 + (nt << 3) + qc_;
                const int col = slotb + cl;
                const float c0 = csm[cl], c1 = csm[cl + 1];
                *(float2*)&G[(16 * p + qr_) * 132 + col]     = make_float2(g4[nt][0] + c0, g4[nt][1] + c1);
                *(float2*)&G[(16 * p + qr_ + 8) * 132 + col] = make_float2(g4[nt][2] + c0, g4[nt][3] + c1);
            }
        }
        // QK (j-cols half h)
        float s[4][4];
        #pragma unroll
        for (int nt = 0; nt < 4; nt++) { s[nt][0]=0; s[nt][1]=0; s[nt][2]=0; s[nt][3]=0; }
        wgemm3_nt4(AqH, AqL, sb + R_KH + h * 32 * 144, sb + R_KL + h * 32 * 144,
                   a_off, b_off, s);
        barp(1 + p);
        // gather BD + scale + mask
        const int cb = 1023 + j0 - i0;
        const int rA = 16 * p + qr_, rB = rA + 8;
        float rmax0 = -1e30f, rmax1 = -1e30f;
        #pragma unroll
        for (int nt = 0; nt < 4; nt++) {
            const int col = h * 32 + (nt << 3) + qc_;
            s[nt][0] = (s[nt][0] + G[rA * 132 + ((cb + col - rA) & 127)]) * ATT_SCALE;
            s[nt][1] = (s[nt][1] + G[rA * 132 + ((cb + col + 1 - rA) & 127)]) * ATT_SCALE;
            s[nt][2] = (s[nt][2] + G[rB * 132 + ((cb + col - rB) & 127)]) * ATT_SCALE;
            s[nt][3] = (s[nt][3] + G[rB * 132 + ((cb + col + 1 - rB) & 127)]) * ATT_SCALE;
            if (j0 == i0) {
                if (col > rA)     s[nt][0] = -1e30f;
                if (col + 1 > rA) s[nt][1] = -1e30f;
                if (col > rB)     s[nt][2] = -1e30f;
                if (col + 1 > rB) s[nt][3] = -1e30f;
            }
            rmax0 = fmaxf(rmax0, fmaxf(s[nt][0], s[nt][1]));
            rmax1 = fmaxf(rmax1, fmaxf(s[nt][2], s[nt][3]));
        }
        rmax0 = fmaxf(rmax0, __shfl_xor_sync(0xffffffffu, rmax0, 1));
        rmax0 = fmaxf(rmax0, __shfl_xor_sync(0xffffffffu, rmax0, 2));
        rmax1 = fmaxf(rmax1, __shfl_xor_sync(0xffffffffu, rmax1, 1));
        rmax1 = fmaxf(rmax1, __shfl_xor_sync(0xffffffffu, rmax1, 2));
        if ((lane & 3) == 0) {
            pmax[p * 32 + h * 16 + qr_]     = rmax0;
            pmax[p * 32 + h * 16 + qr_ + 8] = rmax1;
        }
        barp(1 + p);
        rmax0 = fmaxf(rmax0, pmax[p * 32 + (1 - h) * 16 + qr_]);
        rmax1 = fmaxf(rmax1, pmax[p * 32 + (1 - h) * 16 + qr_ + 8]);
        const float mn0 = fmaxf(m0, rmax0), mn1 = fmaxf(m1, rmax1);
        const float al0 = __expf(m0 - mn0), al1 = __expf(m1 - mn1);
        float rs0 = 0.f, rs1 = 0.f;
        #pragma unroll
        for (int nt = 0; nt < 4; nt++) {
            const int col = h * 32 + (nt << 3) + qc_;
            const float p0 = __expf(s[nt][0] - mn0), p1 = __expf(s[nt][1] - mn0);
            const float p2 = __expf(s[nt][2] - mn1), p3 = __expf(s[nt][3] - mn1);
            rs0 += p0 + p1; rs1 += p2 + p3;
            const __nv_bfloat16 h0 = __float2bfloat16(p0), h1 = __float2bfloat16(p1);
            const __nv_bfloat16 h2 = __float2bfloat16(p2), h3 = __float2bfloat16(p3);
            *(__nv_bfloat162*)(sm + R_PH + rA * 144 + col * 2) = __halves2bfloat162(h0, h1);
            *(__nv_bfloat162*)(sm + R_PL + rA * 144 + col * 2) = __halves2bfloat162(
                __float2bfloat16(p0 - __bfloat162float(h0)),
                __float2bfloat16(p1 - __bfloat162float(h1)));
            *(__nv_bfloat162*)(sm + R_PH + rB * 144 + col * 2) = __halves2bfloat162(h2, h3);
            *(__nv_bfloat162*)(sm + R_PL + rB * 144 + col * 2) = __halves2bfloat162(
                __float2bfloat16(p2 - __bfloat162float(h2)),
                __float2bfloat16(p3 - __bfloat162float(h3)));
            o[nt][0] *= al0; o[nt][1] *= al0; o[nt][2] *= al1; o[nt][3] *= al1;
        }
        rs0 += __shfl_xor_sync(0xffffffffu, rs0, 1);
        rs0 += __shfl_xor_sync(0xffffffffu, rs0, 2);
        rs1 += __shfl_xor_sync(0xffffffffu, rs1, 1);
        rs1 += __shfl_xor_sync(0xffffffffu, rs1, 2);
        if ((lane & 3) == 0) {
            psum[p * 32 + h * 16 + qr_]     = rs0;
            psum[p * 32 + h * 16 + qr_ + 8] = rs1;
        }
        barp(1 + p);   // psum exchange + P visibility for the pair
        rs0 += psum[p * 32 + (1 - h) * 16 + qr_];
        rs1 += psum[p * 32 + (1 - h) * 16 + qr_ + 8];
        li0 = li0 * al0 + rs0; li1 = li1 * al1 + rs1;
        m0 = mn0; m1 = mn1;
        // PV: d-cols half h
        wgemm3_nt4(ApH, ApL, sb + R_VH + h * 32 * 144, sb + R_VL + h * 32 * 144,
                   a_off, b_off, o);
    }

    const float iv0 = 1.f / li0, iv1 = 1.f / li1;
    const int rA = 16 * p + qr_;
    #pragma unroll
    for (int nt = 0; nt < 4; nt++) {
        const int d = h * 32 + (nt << 3) + qc_;
        const float v0 = o[nt][0] * iv0, v1 = o[nt][1] * iv0;
        const float v2 = o[nt][2] * iv1, v3 = o[nt][3] * iv1;
        const size_t gA = ((size_t)(i0 + rA) * 8 + b) * 512 + n * 64 + d;
        const size_t gB = ((size_t)(i0 + rA + 8) * 8 + b) * 512 + n * 64 + d;
        const __nv_bfloat16 h0 = __float2bfloat16(v0), h1 = __float2bfloat16(v1);
        const __nv_bfloat16 h2 = __float2bfloat16(v2), h3 = __float2bfloat16(v3);
        *(__nv_bfloat162*)(vech + gA) = __halves2bfloat162(h0, h1);
        *(__nv_bfloat162*)(vecl + gA) = __halves2bfloat162(
            __float2bfloat16(v0 - __bfloat162float(h0)),
            __float2bfloat16(v1 - __bfloat162float(h1)));
        *(__nv_bfloat162*)(vech + gB) = __halves2bfloat162(h2, h3);
        *(__nv_bfloat162*)(vecl + gB) = __halves2bfloat162(
            __float2bfloat16(v2 - __bfloat162float(h2)),
            __float2bfloat16(v3 - __bfloat162float(h3)));
    }
}

// ===================== flash attention 2 (cross), 256 thr, 128-row tile =====
#define C_QH 0
#define C_QL 18432
#define C_KH 36864
#define C_KL 46080
#define C_VH 55296
#define C_VL 64512
#define C_PH 73728
#define C_PL 92160
#define C_FL 110592
#define CTX_SMEM 110720

__global__ __launch_bounds__(256) void flash_ctx_mma(
    const __nv_bfloat16* __restrict__ qh, const __nv_bfloat16* __restrict__ ql,
    const __nv_bfloat16* __restrict__ kvh, const __nv_bfloat16* __restrict__ kvl,
    const __nv_bfloat16* __restrict__ vth, const __nv_bfloat16* __restrict__ vtl,
    const unsigned char* __restrict__ emask,
    __nv_bfloat16* __restrict__ vech, __nv_bfloat16* __restrict__ vecl)
{
    extern __shared__ char sm[];
    const uint32_t sb = smem_u32(sm);
    const int tid = threadIdx.x, lane = tid & 31, wid = tid >> 5;
    const int i0 = blockIdx.x << 7;
    const int b = blockIdx.y >> 3, n = blockIdx.y & 7;
    const int wrow = wid << 4;
    const int lr = lane & 7, lg = lane >> 3;
    const uint32_t a_off = (uint32_t)(((lg & 1) << 3) + lr) * 144u + (uint32_t)((lg >> 1) << 4);
    const uint32_t b_off = (uint32_t)(((lg >> 1) << 3) + lr) * 144u + (uint32_t)((lg & 1) << 4);
    const int qr_ = lane >> 2, qc_ = (lane & 3) << 1;
    const uint32_t AqH = sb + C_QH + wrow * 144, AqL = sb + C_QL + wrow * 144;
    const uint32_t ApH = sb + C_PH + wrow * 144, ApL = sb + C_PL + wrow * 144;

    for (int t = tid; t < 1024; t += 256) {
        const int row = t >> 3, c4 = t & 7;
        const size_t g = ((size_t)(i0 + row) * 8 + b) * 512 + n * 64 + c4 * 8;
        *(uint4*)(sm + C_QH + row * 144 + c4 * 16) = *(const uint4*)(qh + g);
        *(uint4*)(sm + C_QL + row * 144 + c4 * 16) = *(const uint4*)(ql + g);
    }

    float m0 = -1e30f, m1 = -1e30f, li0 = 0.f, li1 = 0.f;
    float o[8][4];
    #pragma unroll
    for (int nt = 0; nt < 8; nt++) { o[nt][0]=0; o[nt][1]=0; o[nt][2]=0; o[nt][3]=0; }

    for (int j0 = 0; j0 < ELEN; j0 += 64) {
        __syncthreads();
        for (int t = tid; t < 512; t += 256) {
            const int row = t >> 3, c4 = t & 7;
            const size_t g = ((size_t)(j0 + row) * 8 + b) * 1024 + n * 64 + c4 * 8;
            *(uint4*)(sm + C_KH + row * 144 + c4 * 16) = *(const uint4*)(kvh + g);
            *(uint4*)(sm + C_KL + row * 144 + c4 * 16) = *(const uint4*)(kvl + g);
        }
        for (int t = tid; t < 512; t += 256) {
            const int dr = t >> 3, c4 = t & 7;
            const size_t g = ((size_t)(b * 8 + n) * 64 + dr) * 1024 + j0 + c4 * 8;
            *(uint4*)(sm + C_VH + dr * 144 + c4 * 16) = *(const uint4*)(vth + g);
            *(uint4*)(sm + C_VL + dr * 144 + c4 * 16) = *(const uint4*)(vtl + g);
        }
        if (tid < 64) sm[C_FL + tid] = (char)emask[(size_t)(j0 + tid) * 8 + b];
        __syncthreads();

        float s[8][4];
        #pragma unroll
        for (int nt = 0; nt < 8; nt++) { s[nt][0]=0; s[nt][1]=0; s[nt][2]=0; s[nt][3]=0; }
        wgemm3(AqH, AqL, sb + C_KH, sb + C_KL, a_off, b_off, s);
        __syncwarp();

        const int rA = wrow + qr_, rB = rA + 8;
        float rmax0 = -1e30f, rmax1 = -1e30f;
        #pragma unroll
        for (int nt = 0; nt < 8; nt++) {
            const int col = (nt << 3) + qc_;
            const bool f0 = sm[C_FL + col] != 0, f1 = sm[C_FL + col + 1] != 0;
            s[nt][0] = f0 ? -1e4f : s[nt][0] * ATT_SCALE;
            s[nt][1] = f1 ? -1e4f : s[nt][1] * ATT_SCALE;
            s[nt][2] = f0 ? -1e4f : s[nt][2] * ATT_SCALE;
            s[nt][3] = f1 ? -1e4f : s[nt][3] * ATT_SCALE;
            rmax0 = fmaxf(rmax0, fmaxf(s[nt][0], s[nt][1]));
            rmax1 = fmaxf(rmax1, fmaxf(s[nt][2], s[nt][3]));
        }
        rmax0 = fmaxf(rmax0, __shfl_xor_sync(0xffffffffu, rmax0, 1));
        rmax0 = fmaxf(rmax0, __shfl_xor_sync(0xffffffffu, rmax0, 2));
        rmax1 = fmaxf(rmax1, __shfl_xor_sync(0xffffffffu, rmax1, 1));
        rmax1 = fmaxf(rmax1, __shfl_xor_sync(0xffffffffu, rmax1, 2));
        const float mn0 = fmaxf(m0, rmax0), mn1 = fmaxf(m1, rmax1);
        const float al0 = __expf(m0 - mn0), al1 = __expf(m1 - mn1);
        float rs0 = 0.f, rs1 = 0.f;
        #pragma unroll
        for (int nt = 0; nt < 8; nt++) {
            const int col = (nt << 3) + qc_;
            const float p0 = __expf(s[nt][0] - mn0), p1 = __expf(s[nt][1] - mn0);
            const float p2 = __expf(s[nt][2] - mn1), p3 = __expf(s[nt][3] - mn1);
            rs0 += p0 + p1; rs1 += p2 + p3;
            const __nv_bfloat16 h0 = __float2bfloat16(p0), h1 = __float2bfloat16(p1);
            const __nv_bfloat16 h2 = __float2bfloat16(p2), h3 = __float2bfloat16(p3);
            *(__nv_bfloat162*)(sm + C_PH + rA * 144 + col * 2) = __halves2bfloat162(h0, h1);
            *(__nv_bfloat162*)(sm + C_PL + rA * 144 + col * 2) = __halves2bfloat162(
                __float2bfloat16(p0 - __bfloat162float(h0)),
                __float2bfloat16(p1 - __bfloat162float(h1)));
            *(__nv_bfloat162*)(sm + C_PH + rB * 144 + col * 2) = __halves2bfloat162(h2, h3);
            *(__nv_bfloat162*)(sm + C_PL + rB * 144 + col * 2) = __halves2bfloat162(
                __float2bfloat16(p2 - __bfloat162float(h2)),
                __float2bfloat16(p3 - __bfloat162float(h3)));
            o[nt][0] *= al0; o[nt][1] *= al0; o[nt][2] *= al1; o[nt][3] *= al1;
        }
        rs0 += __shfl_xor_sync(0xffffffffu, rs0, 1);
        rs0 += __shfl_xor_sync(0xffffffffu, rs0, 2);
        rs1 += __shfl_xor_sync(0xffffffffu, rs1, 1);
        rs1 += __shfl_xor_sync(0xffffffffu, rs1, 2);
        li0 = li0 * al0 + rs0; li1 = li1 * al1 + rs1;
        m0 = mn0; m1 = mn1;
        __syncwarp();
        wgemm3(ApH, ApL, sb + C_VH, sb + C_VL, a_off, b_off, o);
    }

    const float iv0 = 1.f / li0, iv1 = 1.f / li1;
    const int rA = wrow + qr_;
    #pragma unroll
    for (int nt = 0; nt < 8; nt++) {
        const int d = (nt << 3) + qc_;
        const float v0 = o[nt][0] * iv0, v1 = o[nt][1] * iv0;
        const float v2 = o[nt][2] * iv1, v3 = o[nt][3] * iv1;
        const size_t gA = ((size_t)(i0 + rA) * 8 + b) * 512 + n * 64 + d;
        const size_t gB = ((size_t)(i0 + rA + 8) * 8 + b) * 512 + n * 64 + d;
        const __nv_bfloat16 h0 = __float2bfloat16(v0), h1 = __float2bfloat16(v1);
        const __nv_bfloat16 h2 = __float2bfloat16(v2), h3 = __float2bfloat16(v3);
        *(__nv_bfloat162*)(vech + gA) = __halves2bfloat162(h0, h1);
        *(__nv_bfloat162*)(vecl + gA) = __halves2bfloat162(
            __float2bfloat16(v0 - __bfloat162float(h0)),
            __float2bfloat16(v1 - __bfloat162float(h1)));
        *(__nv_bfloat162*)(vech + gB) = __halves2bfloat162(h2, h3);
        *(__nv_bfloat162*)(vecl + gB) = __halves2bfloat162(
            __float2bfloat16(v2 - __bfloat162float(h2)),
            __float2bfloat16(v3 - __bfloat162float(h3)));
    }
}

// ===================== host orchestration ====================================
extern "C" void kernel_launch(void* const* d_in, const int* in_sizes, int n_in,
                              void* d_out, int out_size)
{
    (void)in_sizes; (void)n_in; (void)out_size;
    const float* dec_inp = (const float*)d_in[0];
    const float* r       = (const float*)d_in[1];
    const float* enc_out = (const float*)d_in[2];
    const float* rwb     = (const float*)d_in[3];
    const float* rrb     = (const float*)d_in[4];
    const float* qkv_w   = (const float*)d_in[5];
    const float* r_w     = (const float*)d_in[6];
    const float* o_w     = (const float*)d_in[7];
    const float* ln1_g   = (const float*)d_in[8];
    const float* ln1_b   = (const float*)d_in[9];
    const float* q_w     = (const float*)d_in[10];
    const float* kv_w    = (const float*)d_in[11];
    const float* o2_w    = (const float*)d_in[12];
    const float* ln2_g   = (const float*)d_in[13];
    const float* ln2_b   = (const float*)d_in[14];
    const float* ff_w1   = (const float*)d_in[15];
    const float* ff_b1   = (const float*)d_in[16];
    const float* ff_w2   = (const float*)d_in[17];
    const float* ff_b2   = (const float*)d_in[18];
    const float* ln3_g   = (const float*)d_in[19];
    const float* ln3_b   = (const float*)d_in[20];
    const unsigned char* emask = (const unsigned char*)d_in[22];
    float* out = (float*)d_out;

    float *out1, *h2, *out2, *qbias, *ccv;
    __nv_bfloat16 *wthi, *wtlo, *hh, *hl, *headsh, *headsl, *rh, *rl, *rkh, *rkl;
    __nv_bfloat16 *vth, *vtl, *vech, *vecl, *h2h, *h2l, *q2h, *q2l, *eh, *el;
    __nv_bfloat16 *kvh, *kvl, *vt2h, *vt2l, *vec2h, *vec2l, *th, *tl;
    cudaGetSymbolAddress((void**)&out1,  g_out1);
    cudaGetSymbolAddress((void**)&h2,    g_h2);
    cudaGetSymbolAddress((void**)&out2,  g_out2);
    cudaGetSymbolAddress((void**)&qbias, g_qbias);
    cudaGetSymbolAddress((void**)&ccv,   g_cc);
    cudaGetSymbolAddress((void**)&wthi,  g_wthi);
    cudaGetSymbolAddress((void**)&wtlo,  g_wtlo);
    cudaGetSymbolAddress((void**)&hh,    g_hh);
    cudaGetSymbolAddress((void**)&hl,    g_hl);
    cudaGetSymbolAddress((void**)&headsh,g_headsh);
    cudaGetSymbolAddress((void**)&headsl,g_headsl);
    cudaGetSymbolAddress((void**)&rh,    g_rh);
    cudaGetSymbolAddress((void**)&rl,    g_rl);
    cudaGetSymbolAddress((void**)&rkh,   g_rkh);
    cudaGetSymbolAddress((void**)&rkl,   g_rkl);
    cudaGetSymbolAddress((void**)&vth,   g_vth);
    cudaGetSymbolAddress((void**)&vtl,   g_vtl);
    cudaGetSymbolAddress((void**)&vech,  g_vech);
    cudaGetSymbolAddress((void**)&vecl,  g_vecl);
    cudaGetSymbolAddress((void**)&h2h,   g_h2h);
    cudaGetSymbolAddress((void**)&h2l,   g_h2l);
    cudaGetSymbolAddress((void**)&q2h,   g_q2h);
    cudaGetSymbolAddress((void**)&q2l,   g_q2l);
    cudaGetSymbolAddress((void**)&eh,    g_eh);
    cudaGetSymbolAddress((void**)&el,    g_el);
    cudaGetSymbolAddress((void**)&kvh,   g_kvh);
    cudaGetSymbolAddress((void**)&kvl,   g_kvl);
    cudaGetSymbolAddress((void**)&vt2h,  g_vt2h);
    cudaGetSymbolAddress((void**)&vt2l,  g_vt2l);
    cudaGetSymbolAddress((void**)&vec2h, g_vec2h);
    cudaGetSymbolAddress((void**)&vec2l, g_vec2l);
    cudaGetSymbolAddress((void**)&th,    g_th);
    cudaGetSymbolAddress((void**)&tl,    g_tl);

    cudaFuncSetAttribute(flash_rel_mma, cudaFuncAttributeMaxDynamicSharedMemorySize, REL_SMEM);
    cudaFuncSetAttribute(flash_ctx_mma, cudaFuncAttributeMaxDynamicSharedMemorySize, CTX_SMEM);
    cudaFuncSetAttribute(gemm_hmma<false, false>, cudaFuncAttributeMaxDynamicSharedMemorySize, GP_SMEM);
    cudaFuncSetAttribute(gemm_hmma<false, true>,  cudaFuncAttributeMaxDynamicSharedMemorySize, GP_SMEM);
    cudaFuncSetAttribute(gemm_hmma<true, true>,   cudaFuncAttributeMaxDynamicSharedMemorySize, GP_SMEM);

    // ---- weights + misc prep ----
    tsplit_all<<<4352, 256>>>(qkv_w, r_w, o_w, q_w, kv_w, o2_w, ff_w1, ff_w2,
                              wthi, wtlo);
    qbias_k<<<6, 256>>>(rwb, qbias);
    split_k<<<QLEN * DMODEL / 1024, 256>>>(r, rh, rl, QLEN * DMODEL / 4);
    split_k<<<ROWS * DMODEL / 1024, 256>>>(enc_out, eh, el, ROWS * DMODEL / 4);

    // ---- block 1: relative self-attention ----
    ln_k<false, true><<<ROWS, 128>>>(dec_inp, ln1_g, ln1_b, nullptr, hh, hl);
    gemm_hmma<false, true><<<dim3(12, 64), 256, GP_SMEM>>>(
        hh, hl, wthi + WT_QKV, wtlo + WT_QKV, qbias, nullptr,
        nullptr, headsh, headsl, ROWS, 1536, 512);
    gemm_hmma<false, true><<<dim3(4, 8), 256, GP_SMEM>>>(
        rh, rl, wthi + WT_RW, wtlo + WT_RW, nullptr, nullptr,
        nullptr, rkh, rkl, QLEN, 512, 512);
    vtrans_k<<<dim3(32, 64), 256>>>(headsh, headsl, vth, vtl, 1536, 1024);
    c_k<<<1024, 256>>>(rkh, rkl, rwb, rrb, ccv);
    flash_rel_mma<<<dim3(16, 64), 256, REL_SMEM>>>(headsh, headsl, vth, vtl,
                                                   rkh, rkl, ccv, vech, vecl);
    gemm_hmma<false, false><<<dim3(4, 64), 256, GP_SMEM>>>(
        vech, vecl, wthi + WT_OW, wtlo + WT_OW, nullptr, dec_inp,
        out1, nullptr, nullptr, ROWS, 512, 512);

    // ---- block 2: cross attention ----
    ln_k<true, true><<<ROWS, 128>>>(out1, ln2_g, ln2_b, h2, h2h, h2l);
    gemm_hmma<false, true><<<dim3(4, 64), 256, GP_SMEM>>>(
        h2h, h2l, wthi + WT_QW, wtlo + WT_QW, nullptr, nullptr,
        nullptr, q2h, q2l, ROWS, 512, 512);
    gemm_hmma<false, true><<<dim3(8, 64), 256, GP_SMEM>>>(
        eh, el, wthi + WT_KVW, wtlo + WT_KVW, nullptr, nullptr,
        nullptr, kvh, kvl, ROWS, 1024, 512);
    vtrans_k<<<dim3(32, 64), 256>>>(kvh, kvl, vt2h, vt2l, 1024, 512);
    flash_ctx_mma<<<dim3(8, 64), 256, CTX_SMEM>>>(q2h, q2l, kvh, kvl, vt2h, vt2l,
                                                  emask, vec2h, vec2l);
    gemm_hmma<false, false><<<dim3(4, 64), 256, GP_SMEM>>>(
        vec2h, vec2l, wthi + WT_O2W, wtlo + WT_O2W, nullptr, h2,
        out2, nullptr, nullptr, ROWS, 512, 512);

    // ---- block 3: FF ----
    ln_k<false, true><<<ROWS, 128>>>(out2, ln3_g, ln3_b, nullptr, hh, hl);
    gemm_hmma<true, true><<<dim3(16, 64), 256, GP_SMEM>>>(
        hh, hl, wthi + WT_FF1, wtlo + WT_FF1, ff_b1, nullptr,
        nullptr, th, tl, ROWS, 2048, 512);
    gemm_hmma<false, false><<<dim3(4, 64), 256, GP_SMEM>>>(
        th, tl, wthi + WT_FF2, wtlo + WT_FF2, ff_b2, out2,
        out, nullptr, nullptr, ROWS, 512, 2048);
}

// round 11
// speedup vs baseline: 2.8698x; 1.0828x over previous
#include <cuda_runtime.h>
#include <cuda_bf16.h>
#include <cstdint>
#include <cstddef>

#define QLEN   1024
#define BATCH  8
#define DMODEL 512
#define NHEAD  8
#define DHEAD  64
#define DINNER 2048
#define ELEN   1024
#define ATT_SCALE 0.125f
#define ROWS (QLEN * BATCH)   /* 8192 */

// ===================== warp MMA helpers =====================================
__device__ __forceinline__ uint32_t smem_u32(const void* p) {
    uint32_t a;
    asm("{ .reg .u64 t; cvta.to.shared.u64 t, %1; cvt.u32.u64 %0, t; }"
        : "=r"(a) : "l"(p));
    return a;
}

__device__ __forceinline__ void ldsm4(uint32_t* r, uint32_t addr) {
    asm volatile("ldmatrix.sync.aligned.m8n8.x4.shared.b16 {%0,%1,%2,%3}, [%4];"
                 : "=r"(r[0]), "=r"(r[1]), "=r"(r[2]), "=r"(r[3]) : "r"(addr));
}

__device__ __forceinline__ void mma16816(float* d, const uint32_t* a, const uint32_t* b) {
    asm volatile(
        "mma.sync.aligned.m16n8k16.row.col.f32.bf16.bf16.f32 "
        "{%0,%1,%2,%3}, {%4,%5,%6,%7}, {%8,%9}, {%0,%1,%2,%3};"
        : "+f"(d[0]), "+f"(d[1]), "+f"(d[2]), "+f"(d[3])
        : "r"(a[0]), "r"(a[1]), "r"(a[2]), "r"(a[3]), "r"(b[0]), "r"(b[1]));
}

__device__ __forceinline__ void cpa16(uint32_t dst, const void* src) {
    asm volatile("cp.async.cg.shared.global [%0], [%1], 16;" :: "r"(dst), "l"(src));
}

// predicated: src_size 0 zero-fills the 16B destination
__device__ __forceinline__ void cpa16p(uint32_t dst, const void* src, int ok) {
    asm volatile("cp.async.cg.shared.global [%0], [%1], 16, %2;"
                 :: "r"(dst), "l"(src), "r"(ok ? 16 : 0));
}

__device__ __forceinline__ void barp(int id) {
    asm volatile("bar.sync %0, %1;" :: "r"(id), "r"(64) : "memory");
}

// 3-term split-bf16 warp GEMM, 64-col B (nt=8), K=64, 144B stride (flash)
__device__ __forceinline__ void wgemm3(uint32_t Ah, uint32_t Al,
                                       uint32_t Bh, uint32_t Bl,
                                       uint32_t a_off, uint32_t b_off,
                                       float acc[8][4])
{
    #pragma unroll
    for (int ks = 0; ks < 4; ks++) {
        const uint32_t ra = (uint32_t)(ks << 5);
        uint32_t ah[4], al[4];
        ldsm4(ah, Ah + ra + a_off);
        ldsm4(al, Al + ra + a_off);
        #pragma unroll
        for (int np = 0; np < 4; np++) {
            uint32_t bh[4], bl[4];
            const uint32_t rb = (uint32_t)(np * 16 * 144 + (ks << 5));
            ldsm4(bh, Bh + rb + b_off);
            ldsm4(bl, Bl + rb + b_off);
            #pragma unroll
            for (int hf = 0; hf < 2; hf++) {
                float* d = acc[(np << 1) + hf];
                mma16816(d, ah, bh + (hf << 1));
                mma16816(d, ah, bl + (hf << 1));
                mma16816(d, al, bh + (hf << 1));
            }
        }
    }
}

// nt=4 variant (32-col B), 144B stride
__device__ __forceinline__ void wgemm3_nt4(uint32_t Ah, uint32_t Al,
                                           uint32_t Bh, uint32_t Bl,
                                           uint32_t a_off, uint32_t b_off,
                                           float acc[4][4])
{
    #pragma unroll
    for (int ks = 0; ks < 4; ks++) {
        const uint32_t ra = (uint32_t)(ks << 5);
        uint32_t ah[4], al[4];
        ldsm4(ah, Ah + ra + a_off);
        ldsm4(al, Al + ra + a_off);
        #pragma unroll
        for (int np = 0; np < 2; np++) {
            uint32_t bh[4], bl[4];
            const uint32_t rb = (uint32_t)(np * 16 * 144 + (ks << 5));
            ldsm4(bh, Bh + rb + b_off);
            ldsm4(bl, Bl + rb + b_off);
            #pragma unroll
            for (int hf = 0; hf < 2; hf++) {
                float* d = acc[(np << 1) + hf];
                mma16816(d, ah, bh + (hf << 1));
                mma16816(d, ah, bl + (hf << 1));
                mma16816(d, al, bh + (hf << 1));
            }
        }
    }
}

__device__ __forceinline__ void split_store4(char* hi, char* lo, float4 v) {
    const __nv_bfloat16 h0 = __float2bfloat16(v.x), h1 = __float2bfloat16(v.y);
    const __nv_bfloat16 h2 = __float2bfloat16(v.z), h3 = __float2bfloat16(v.w);
    *(__nv_bfloat162*)(hi)     = __halves2bfloat162(h0, h1);
    *(__nv_bfloat162*)(hi + 4) = __halves2bfloat162(h2, h3);
    *(__nv_bfloat162*)(lo)     = __halves2bfloat162(
        __float2bfloat16(v.x - __bfloat162float(h0)),
        __float2bfloat16(v.y - __bfloat162float(h1)));
    *(__nv_bfloat162*)(lo + 4) = __halves2bfloat162(
        __float2bfloat16(v.z - __bfloat162float(h2)),
        __float2bfloat16(v.w - __bfloat162float(h3)));
}

// ===================== scratch ==============================================
__device__ float g_out1[ROWS * DMODEL];
__device__ float g_h2  [ROWS * DMODEL];
__device__ float g_out2[ROWS * DMODEL];
__device__ float g_qbias[3 * DMODEL];
__device__ float g_cc  [NHEAD * 1152];        // zero-init pad beyond 1024

__device__ __nv_bfloat16 g_hh[ROWS * DMODEL],    g_hl[ROWS * DMODEL];
__device__ __nv_bfloat16 g_headsh[ROWS * 1536],  g_headsl[ROWS * 1536];
__device__ __nv_bfloat16 g_rh[QLEN * DMODEL],    g_rl[QLEN * DMODEL];
__device__ __nv_bfloat16 g_rkh[QLEN * DMODEL],   g_rkl[QLEN * DMODEL];
__device__ __nv_bfloat16 g_vth[64 * 64 * QLEN],  g_vtl[64 * 64 * QLEN];
__device__ __nv_bfloat16 g_vech[ROWS * DMODEL],  g_vecl[ROWS * DMODEL];
__device__ __nv_bfloat16 g_h2h[ROWS * DMODEL],   g_h2l[ROWS * DMODEL];
__device__ __nv_bfloat16 g_q2h[ROWS * DMODEL],   g_q2l[ROWS * DMODEL];
__device__ __nv_bfloat16 g_eh[ROWS * DMODEL],    g_el[ROWS * DMODEL];
__device__ __nv_bfloat16 g_kvh[ROWS * 1024],     g_kvl[ROWS * 1024];
__device__ __nv_bfloat16 g_vt2h[64 * 64 * ELEN], g_vt2l[64 * 64 * ELEN];
__device__ __nv_bfloat16 g_vec2h[ROWS * DMODEL], g_vec2l[ROWS * DMODEL];
__device__ __nv_bfloat16 g_th[ROWS * DINNER],    g_tl[ROWS * DINNER];

#define WT_QKV 0
#define WT_RW  786432
#define WT_OW  1048576
#define WT_QW  1310720
#define WT_KVW 1572864
#define WT_O2W 2097152
#define WT_FF1 2359296
#define WT_FF2 3407872
#define WT_TOTAL 4456448
__device__ __nv_bfloat16 g_wthi[WT_TOTAL];
__device__ __nv_bfloat16 g_wtlo[WT_TOTAL];

// ===================== small prep kernels ===================================
__global__ __launch_bounds__(256) void split_k(const float* __restrict__ x,
                                               __nv_bfloat16* __restrict__ hi,
                                               __nv_bfloat16* __restrict__ lo, int n4)
{
    const int i = blockIdx.x * 256 + threadIdx.x;
    if (i >= n4) return;
    const float4 v = reinterpret_cast<const float4*>(x)[i];
    split_store4((char*)(hi + (size_t)i * 4), (char*)(lo + (size_t)i * 4), v);
}

// all 8 weight transposes+splits in one launch (linear block-range dispatch)
__global__ __launch_bounds__(256) void tsplit_all(
    const float* __restrict__ qkv, const float* __restrict__ rw,
    const float* __restrict__ ow,  const float* __restrict__ qw,
    const float* __restrict__ kvw, const float* __restrict__ o2w,
    const float* __restrict__ ff1, const float* __restrict__ ff2,
    __nv_bfloat16* __restrict__ hi, __nv_bfloat16* __restrict__ lo)
{
    int bid = blockIdx.x;
    const float* W; int K, N, gx; size_t off;
    if (bid < 768)                      { W = qkv; K = 512;  N = 1536; gx = 48; off = WT_QKV; }
    else if ((bid -= 768)  < 256)       { W = rw;  K = 512;  N = 512;  gx = 16; off = WT_RW;  }
    else if ((bid -= 256)  < 256)       { W = ow;  K = 512;  N = 512;  gx = 16; off = WT_OW;  }
    else if ((bid -= 256)  < 256)       { W = qw;  K = 512;  N = 512;  gx = 16; off = WT_QW;  }
    else if ((bid -= 256)  < 512)       { W = kvw; K = 512;  N = 1024; gx = 32; off = WT_KVW; }
    else if ((bid -= 512)  < 256)       { W = o2w; K = 512;  N = 512;  gx = 16; off = WT_O2W; }
    else if ((bid -= 256)  < 1024)      { W = ff1; K = 512;  N = 2048; gx = 64; off = WT_FF1; }
    else { bid -= 1024;                   W = ff2; K = 2048; N = 512;  gx = 16; off = WT_FF2; }

    __shared__ float t[32][33];
    const int n0 = (bid % gx) << 5, k0 = (bid / gx) << 5;
    const int x = threadIdx.x & 31, y = threadIdx.x >> 5;
    #pragma unroll
    for (int i = 0; i < 32; i += 8)
        t[y + i][x] = W[(size_t)(k0 + y + i) * N + n0 + x];
    __syncthreads();
    #pragma unroll
    for (int i = 0; i < 32; i += 8) {
        const float v = t[x][y + i];
        const size_t o = off + (size_t)(n0 + y + i) * K + k0 + x;
        const __nv_bfloat16 h = __float2bfloat16(v);
        hi[o] = h;
        lo[o] = __float2bfloat16(v - __bfloat162float(h));
    }
}

__global__ void qbias_k(const float* __restrict__ rwb, float* __restrict__ qb) {
    const int i = blockIdx.x * 256 + threadIdx.x;
    if (i < 1536) qb[i] = (i < 512) ? rwb[i] : 0.0f;
}

// c[n][u] = sum_d (rrb-rwb)[n][d] * rk[u][n*64+d]
__global__ __launch_bounds__(256) void c_k(const __nv_bfloat16* __restrict__ rkh,
                                           const __nv_bfloat16* __restrict__ rkl,
                                           const float* __restrict__ rwb,
                                           const float* __restrict__ rrb,
                                           float* __restrict__ cc)
{
    const int u = blockIdx.x;
    const int n = threadIdx.x >> 5, lane = threadIdx.x & 31;
    float s = 0.0f;
    #pragma unroll
    for (int k = 0; k < 2; k++) {
        const int d = lane + k * 32;
        const size_t g = (size_t)u * 512 + n * 64 + d;
        const float rv = __bfloat162float(rkh[g]) + __bfloat162float(rkl[g]);
        s += (rrb[n * 64 + d] - rwb[n * 64 + d]) * rv;
    }
    #pragma unroll
    for (int o = 16; o; o >>= 1) s += __shfl_xor_sync(0xffffffffu, s, o);
    if (lane == 0) cc[n * 1152 + u] = s;
}

// transpose V-part: src[(i*8+b)*stride + off + n*64 + d] -> dst[((b*8+n)*64+d)*1024 + i]
__global__ __launch_bounds__(256) void vtrans_k(const __nv_bfloat16* __restrict__ sh,
                                                const __nv_bfloat16* __restrict__ sl,
                                                __nv_bfloat16* __restrict__ dh,
                                                __nv_bfloat16* __restrict__ dl,
                                                int srcStride, int srcOff)
{
    __shared__ __nv_bfloat16 th[32][72], tl[32][72];
    const int i0 = blockIdx.x << 5;
    const int b = blockIdx.y >> 3, n = blockIdx.y & 7;
    const int t = threadIdx.x;
    {
        const int il = t >> 3, dj = (t & 7) << 3;
        const size_t g = ((size_t)(i0 + il) * 8 + b) * srcStride + srcOff + n * 64 + dj;
        *(uint4*)&th[il][dj] = *(const uint4*)(sh + g);
        *(uint4*)&tl[il][dj] = *(const uint4*)(sl + g);
    }
    __syncthreads();
    {
        const int dr = t >> 2, ij = (t & 3) << 3;
        __nv_bfloat16 oh[8], ol[8];
        #pragma unroll
        for (int k = 0; k < 8; k++) { oh[k] = th[ij + k][dr]; ol[k] = tl[ij + k][dr]; }
        const size_t g = ((size_t)(b * 8 + n) * 64 + dr) * 1024 + i0 + ij;
        *(uint4*)(dh + g) = *(uint4*)oh;
        *(uint4*)(dl + g) = *(uint4*)ol;
    }
}

// ===================== pipelined HMMA GEMM ==================================
// K-chunk 32, 2-stage cp.async double buffer. Tiles [128][40] bf16, 80B stride.
#define GP_STAGE 40960
#define GP_SMEM  81920

template <bool GELU, bool SPLIT>
__global__ __launch_bounds__(256, 2) void gemm_hmma(const __nv_bfloat16* __restrict__ Ahi,
                                                    const __nv_bfloat16* __restrict__ Alo,
                                                    const __nv_bfloat16* __restrict__ Bhi,
                                                    const __nv_bfloat16* __restrict__ Blo,
                                                    const float* __restrict__ bias,
                                                    const float* __restrict__ res,
                                                    float* __restrict__ C,
                                                    __nv_bfloat16* __restrict__ Ch,
                                                    __nv_bfloat16* __restrict__ Cl,
                                                    int M, int N, int K)
{
    extern __shared__ char smem[];
    const uint32_t sb = smem_u32(smem);
    const int tid = threadIdx.x;
    const int lane = tid & 31, wid = tid >> 5;
    const int m0 = blockIdx.y << 7, n0 = blockIdx.x << 7;
    const int wm = (wid & 3) << 5;
    const int wn = (wid >> 2) << 6;
    (void)M;

    float acc[2][8][4];
    #pragma unroll
    for (int mt = 0; mt < 2; mt++)
        #pragma unroll
        for (int nt = 0; nt < 8; nt++)
            #pragma unroll
            for (int e = 0; e < 4; e++) acc[mt][nt][e] = 0.0f;

    const int lr = lane & 7, lg = lane >> 3;
    const uint32_t a_off = (uint32_t)(((lg & 1) << 3) + lr) * 80u + (uint32_t)((lg >> 1) << 4);
    const uint32_t b_off = (uint32_t)(((lg >> 1) << 3) + lr) * 80u + (uint32_t)((lg & 1) << 4);

    const int nch = K >> 5;

    auto load_chunk = [&](int c, int s) {
        const int k0 = c << 5;
        const uint32_t sbase = sb + s * GP_STAGE;
        #pragma unroll
        for (int i = tid; i < 2048; i += 256) {
            const int tile = i >> 9;
            const int idx = i & 511;
            const int row = idx >> 2, kc = (idx & 3) << 3;
            const uint32_t dst = sbase + tile * 10240 + row * 80 + (idx & 3) * 16;
            const __nv_bfloat16* src;
            if (tile == 0)      src = Ahi + (size_t)(m0 + row) * K + k0 + kc;
            else if (tile == 1) src = Alo + (size_t)(m0 + row) * K + k0 + kc;
            else if (tile == 2) src = Bhi + (size_t)(n0 + row) * K + k0 + kc;
            else                src = Blo + (size_t)(n0 + row) * K + k0 + kc;
            cpa16(dst, src);
        }
        asm volatile("cp.async.commit_group;" ::: "memory");
    };

    load_chunk(0, 0);
    load_chunk(1, 1);

    for (int c = 0; c < nch; c++) {
        if (c + 1 < nch) asm volatile("cp.async.wait_group 1;" ::: "memory");
        else             asm volatile("cp.async.wait_group 0;" ::: "memory");
        __syncthreads();

        const uint32_t sbase = sb + (c & 1) * GP_STAGE;
        #pragma unroll
        for (int ks = 0; ks < 2; ks++) {
            const uint32_t kk2 = (uint32_t)(ks << 5);
            uint32_t ah[2][4], al[2][4];
            #pragma unroll
            for (int mt = 0; mt < 2; mt++) {
                const uint32_t ra = (uint32_t)((wm + (mt << 4)) * 80) + kk2 + a_off;
                ldsm4(ah[mt], sbase + ra);
                ldsm4(al[mt], sbase + 10240 + ra);
            }
            #pragma unroll
            for (int np = 0; np < 4; np++) {
                uint32_t bh[4], bl[4];
                const uint32_t rb = (uint32_t)((wn + (np << 4)) * 80) + kk2 + b_off;
                ldsm4(bh, sbase + 20480 + rb);
                ldsm4(bl, sbase + 30720 + rb);
                #pragma unroll
                for (int mt = 0; mt < 2; mt++) {
                    #pragma unroll
                    for (int hf = 0; hf < 2; hf++) {
                        float* d = acc[mt][(np << 1) + hf];
                        mma16816(d, ah[mt], bh + (hf << 1));
                        mma16816(d, ah[mt], bl + (hf << 1));
                        mma16816(d, al[mt], bh + (hf << 1));
                    }
                }
            }
        }
        __syncthreads();
        if (c + 2 < nch) load_chunk(c + 2, c & 1);
    }

    const int er = lane >> 2, ec = (lane & 3) << 1;
    #pragma unroll
    for (int mt = 0; mt < 2; mt++) {
        #pragma unroll
        for (int half = 0; half < 2; half++) {
            const int gr = m0 + wm + (mt << 4) + er + (half << 3);
            #pragma unroll
            for (int nt = 0; nt < 8; nt++) {
                const int gc = n0 + wn + (nt << 3) + ec;
                float v0 = acc[mt][nt][(half << 1) + 0];
                float v1 = acc[mt][nt][(half << 1) + 1];
                if (bias) { v0 += bias[gc]; v1 += bias[gc + 1]; }
                if (GELU) {
                    v0 = 0.5f * v0 * (1.0f + erff(v0 * 0.70710678118654752f));
                    v1 = 0.5f * v1 * (1.0f + erff(v1 * 0.70710678118654752f));
                }
                if (SPLIT) {
                    const __nv_bfloat16 h0 = __float2bfloat16(v0), h1 = __float2bfloat16(v1);
                    *(__nv_bfloat162*)(Ch + (size_t)gr * N + gc) = __halves2bfloat162(h0, h1);
                    *(__nv_bfloat162*)(Cl + (size_t)gr * N + gc) = __halves2bfloat162(
                        __float2bfloat16(v0 - __bfloat162float(h0)),
                        __float2bfloat16(v1 - __bfloat162float(h1)));
                } else {
                    if (res) {
                        const float2 rr = *reinterpret_cast<const float2*>(&res[(size_t)gr * N + gc]);
                        v0 += rr.x; v1 += rr.y;
                    }
                    *reinterpret_cast<float2*>(&C[(size_t)gr * N + gc]) = make_float2(v0, v1);
                }
            }
        }
    }
}

// ===================== LayerNorm ============================================
template <bool F32O, bool SPL>
__global__ __launch_bounds__(128) void ln_k(const float* __restrict__ x,
                                            const float* __restrict__ g,
                                            const float* __restrict__ b,
                                            float* __restrict__ yf,
                                            __nv_bfloat16* __restrict__ yh,
                                            __nv_bfloat16* __restrict__ yl)
{
    const int row = blockIdx.x;
    const int t = threadIdx.x;
    const float4 v = reinterpret_cast<const float4*>(x + (size_t)row * DMODEL)[t];
    float s  = v.x + v.y + v.z + v.w;
    float sq = v.x*v.x + v.y*v.y + v.z*v.z + v.w*v.w;
    #pragma unroll
    for (int o = 16; o; o >>= 1) {
        s  += __shfl_xor_sync(0xffffffffu, s,  o);
        sq += __shfl_xor_sync(0xffffffffu, sq, o);
    }
    __shared__ float ss[4], sqq[4];
    const int w = t >> 5, lane = t & 31;
    if (lane == 0) { ss[w] = s; sqq[w] = sq; }
    __syncthreads();
    s  = ss[0]  + ss[1]  + ss[2]  + ss[3];
    sq = sqq[0] + sqq[1] + sqq[2] + sqq[3];
    const float mean = s * (1.0f / DMODEL);
    const float var  = sq * (1.0f / DMODEL) - mean * mean;
    const float rstd = rsqrtf(var + 1e-5f);
    const float4 gg = reinterpret_cast<const float4*>(g)[t];
    const float4 bb = reinterpret_cast<const float4*>(b)[t];
    float4 o4;
    o4.x = (v.x - mean) * rstd * gg.x + bb.x;
    o4.y = (v.y - mean) * rstd * gg.y + bb.y;
    o4.z = (v.z - mean) * rstd * gg.z + bb.z;
    o4.w = (v.w - mean) * rstd * gg.w + bb.w;
    if (F32O) reinterpret_cast<float4*>(yf + (size_t)row * DMODEL)[t] = o4;
    if (SPL)  split_store4((char*)(yh + (size_t)row * DMODEL + t * 4),
                           (char*)(yl + (size_t)row * DMODEL + t * 4), o4);
}

// ===== flash attention 1 (rel, causal), 256 thr, cp.async 2-stage K/V =======
#define R_QH   0
#define R_QL   9216
#define R_KS0  18432     /* stage s: +s*18432; KH +0, KL +9216 */
#define R_VS0  55296
#define R_PH   92160
#define R_PL   101376
#define R_RH   110592
#define R_RL   129024
#define R_G    147456
#define R_C    181248    /* 2 x 64 floats */
#define R_PM   181760
#define R_PS   182272
#define REL_SMEM 182784

__global__ __launch_bounds__(256) void flash_rel_mma(
    const __nv_bfloat16* __restrict__ hh, const __nv_bfloat16* __restrict__ hl,
    const __nv_bfloat16* __restrict__ vth, const __nv_bfloat16* __restrict__ vtl,
    const __nv_bfloat16* __restrict__ rkh, const __nv_bfloat16* __restrict__ rkl,
    const float* __restrict__ cc,
    __nv_bfloat16* __restrict__ vech, __nv_bfloat16* __restrict__ vecl)
{
    extern __shared__ char sm[];
    const uint32_t sb = smem_u32(sm);
    const int tid = threadIdx.x, lane = tid & 31, wid = tid >> 5;
    const int p = wid >> 1, h = wid & 1;
    const int i0 = blockIdx.x << 6;
    const int b = blockIdx.y >> 3, n = blockIdx.y & 7;
    const int lr = lane & 7, lg = lane >> 3;
    const uint32_t a_off = (uint32_t)(((lg & 1) << 3) + lr) * 144u + (uint32_t)((lg >> 1) << 4);
    const uint32_t b_off = (uint32_t)(((lg >> 1) << 3) + lr) * 144u + (uint32_t)((lg & 1) << 4);
    const int qr_ = lane >> 2, qc_ = (lane & 3) << 1;
    float* G    = (float*)(sm + R_G);
    float* csm  = (float*)(sm + R_C);
    float* pmax = (float*)(sm + R_PM);
    float* psum = (float*)(sm + R_PS);
    const uint32_t AqH = sb + R_QH + p * 16 * 144, AqL = sb + R_QL + p * 16 * 144;
    const uint32_t ApH = sb + R_PH + p * 16 * 144, ApL = sb + R_PL + p * 16 * 144;
    const int ustart = 960 - i0;
    const int nit = (i0 >> 6) + 1;

    // loader for iteration k into stage s: K/V tiles at j0=64k, ring block
    // ustart+64(k+1), csm[s] <- cc for that block (regular store)
    auto load_iter = [&](int k, int s) {
        const int j0k = k << 6;
        const uint32_t Ks = sb + R_KS0 + s * 18432;
        const uint32_t Vs = sb + R_VS0 + s * 18432;
        const int ub = ustart + ((k + 1) << 6);
        #pragma unroll 2
        for (int i = tid; i < 512; i += 256) {
            const int row = i >> 3, ch = i & 7;
            const size_t gk = ((size_t)(j0k + row) * 8 + b) * 1536 + 512 + n * 64 + ch * 8;
            cpa16(Ks + row * 144 + ch * 16, hh + gk);
            cpa16(Ks + 9216 + row * 144 + ch * 16, hl + gk);
            const size_t gv = ((size_t)(b * 8 + n) * 64 + row) * 1024 + j0k + ch * 8;
            cpa16(Vs + row * 144 + ch * 16, vth + gv);
            cpa16(Vs + 9216 + row * 144 + ch * 16, vtl + gv);
            const int u = ub + row;
            const int slot = u & 127;
            const int ok = (u < QLEN);
            const size_t gr = (size_t)(ok ? u : 0) * 512 + n * 64 + ch * 8;
            cpa16p(sb + R_RH + slot * 144 + ch * 16, rkh + gr, ok);
            cpa16p(sb + R_RL + slot * 144 + ch * 16, rkl + gr, ok);
        }
        if (tid < 64) csm[s * 64 + tid] = cc[n * 1152 + ub + tid];
        asm volatile("cp.async.commit_group;" ::: "memory");
    };

    // ---- prologue: Q (rwb pre-folded), ring block0 + its c values (regular)
    for (int t = tid; t < 512; t += 256) {
        const int row = t >> 3, c4 = t & 7;
        const size_t g = ((size_t)(i0 + row) * 8 + b) * 1536 + n * 64 + c4 * 8;
        *(uint4*)(sm + R_QH + row * 144 + c4 * 16) = *(const uint4*)(hh + g);
        *(uint4*)(sm + R_QL + row * 144 + c4 * 16) = *(const uint4*)(hl + g);
    }
    for (int t = tid; t < 512; t += 256) {
        const int jr = t >> 3, c4 = t & 7;
        const int u = ustart + jr, slot = u & 127;
        uint4 vh = make_uint4(0, 0, 0, 0), vl = make_uint4(0, 0, 0, 0);
        if (u < QLEN) {
            const size_t g = (size_t)u * 512 + n * 64 + c4 * 8;
            vh = *(const uint4*)(rkh + g);
            vl = *(const uint4*)(rkl + g);
        }
        *(uint4*)(sm + R_RH + slot * 144 + c4 * 16) = vh;
        *(uint4*)(sm + R_RL + slot * 144 + c4 * 16) = vl;
    }
    if (tid < 64) csm[64 + tid] = cc[n * 1152 + ustart + tid];
    load_iter(0, 0);
    __syncthreads();

    // ---- G for block 0 (ring block ustart, c values in csm[64..])
    {
        const int slotb = ustart & 127;
        float g4[4][4];
        #pragma unroll
        for (int nt = 0; nt < 4; nt++) { g4[nt][0]=0; g4[nt][1]=0; g4[nt][2]=0; g4[nt][3]=0; }
        wgemm3_nt4(AqH, AqL, sb + R_RH + (slotb + h * 32) * 144,
                   sb + R_RL + (slotb + h * 32) * 144, a_off, b_off, g4);
        #pragma unroll
        for (int nt = 0; nt < 4; nt++) {
            const int cl = h * 32 + (nt << 3) + qc_;
            const int col = slotb + cl;
            const float c0 = csm[64 + cl], c1 = csm[64 + cl + 1];
            *(float2*)&G[(16 * p + qr_) * 132 + col]     = make_float2(g4[nt][0] + c0, g4[nt][1] + c1);
            *(float2*)&G[(16 * p + qr_ + 8) * 132 + col] = make_float2(g4[nt][2] + c0, g4[nt][3] + c1);
        }
    }
    __syncthreads();   // all warps done with block0 ring slots / csm[1]

    float m0 = -1e30f, m1 = -1e30f, li0 = 0.f, li1 = 0.f;
    float o[4][4];
    #pragma unroll
    for (int nt = 0; nt < 4; nt++) { o[nt][0]=0; o[nt][1]=0; o[nt][2]=0; o[nt][3]=0; }

    for (int k = 0; k < nit; k++) {
        const int j0 = k << 6;
        if (k + 1 < nit) {
            load_iter(k + 1, (k + 1) & 1);
            asm volatile("cp.async.wait_group 1;" ::: "memory");
        } else {
            asm volatile("cp.async.wait_group 0;" ::: "memory");
        }
        __syncthreads();
        const uint32_t Ks = sb + R_KS0 + (k & 1) * 18432;
        const uint32_t Vs = sb + R_VS0 + (k & 1) * 18432;
        const float* csmb = csm + (k & 1) * 64;

        // G for block ub_k = ustart + 64(k+1)
        {
            const int slotb = (ustart + ((k + 1) << 6)) & 127;
            float g4[4][4];
            #pragma unroll
            for (int nt = 0; nt < 4; nt++) { g4[nt][0]=0; g4[nt][1]=0; g4[nt][2]=0; g4[nt][3]=0; }
            wgemm3_nt4(AqH, AqL, sb + R_RH + (slotb + h * 32) * 144,
                       sb + R_RL + (slotb + h * 32) * 144, a_off, b_off, g4);
            #pragma unroll
            for (int nt = 0; nt < 4; nt++) {
                const int cl = h * 32 + (nt << 3) + qc_;
                const int col = slotb + cl;
                const float c0 = csmb[cl], c1 = csmb[cl + 1];
                *(float2*)&G[(16 * p + qr_) * 132 + col]     = make_float2(g4[nt][0] + c0, g4[nt][1] + c1);
                *(float2*)&G[(16 * p + qr_ + 8) * 132 + col] = make_float2(g4[nt][2] + c0, g4[nt][3] + c1);
            }
        }
        // QK (j-cols half h)
        float s[4][4];
        #pragma unroll
        for (int nt = 0; nt < 4; nt++) { s[nt][0]=0; s[nt][1]=0; s[nt][2]=0; s[nt][3]=0; }
        wgemm3_nt4(AqH, AqL, Ks + h * 32 * 144, Ks + 9216 + h * 32 * 144,
                   a_off, b_off, s);
        barp(1 + p);
        // gather BD + scale + mask
        const int cb = 1023 + j0 - i0;
        const int rA = 16 * p + qr_, rB = rA + 8;
        float rmax0 = -1e30f, rmax1 = -1e30f;
        #pragma unroll
        for (int nt = 0; nt < 4; nt++) {
            const int col = h * 32 + (nt << 3) + qc_;
            s[nt][0] = (s[nt][0] + G[rA * 132 + ((cb + col - rA) & 127)]) * ATT_SCALE;
            s[nt][1] = (s[nt][1] + G[rA * 132 + ((cb + col + 1 - rA) & 127)]) * ATT_SCALE;
            s[nt][2] = (s[nt][2] + G[rB * 132 + ((cb + col - rB) & 127)]) * ATT_SCALE;
            s[nt][3] = (s[nt][3] + G[rB * 132 + ((cb + col + 1 - rB) & 127)]) * ATT_SCALE;
            if (j0 == i0) {
                if (col > rA)     s[nt][0] = -1e30f;
                if (col + 1 > rA) s[nt][1] = -1e30f;
                if (col > rB)     s[nt][2] = -1e30f;
                if (col + 1 > rB) s[nt][3] = -1e30f;
            }
            rmax0 = fmaxf(rmax0, fmaxf(s[nt][0], s[nt][1]));
            rmax1 = fmaxf(rmax1, fmaxf(s[nt][2], s[nt][3]));
        }
        rmax0 = fmaxf(rmax0, __shfl_xor_sync(0xffffffffu, rmax0, 1));
        rmax0 = fmaxf(rmax0, __shfl_xor_sync(0xffffffffu, rmax0, 2));
        rmax1 = fmaxf(rmax1, __shfl_xor_sync(0xffffffffu, rmax1, 1));
        rmax1 = fmaxf(rmax1, __shfl_xor_sync(0xffffffffu, rmax1, 2));
        if ((lane & 3) == 0) {
            pmax[p * 32 + h * 16 + qr_]     = rmax0;
            pmax[p * 32 + h * 16 + qr_ + 8] = rmax1;
        }
        barp(1 + p);
        rmax0 = fmaxf(rmax0, pmax[p * 32 + (1 - h) * 16 + qr_]);
        rmax1 = fmaxf(rmax1, pmax[p * 32 + (1 - h) * 16 + qr_ + 8]);
        const float mn0 = fmaxf(m0, rmax0), mn1 = fmaxf(m1, rmax1);
        const float al0 = __expf(m0 - mn0), al1 = __expf(m1 - mn1);
        float rs0 = 0.f, rs1 = 0.f;
        #pragma unroll
        for (int nt = 0; nt < 4; nt++) {
            const int col = h * 32 + (nt << 3) + qc_;
            const float p0 = __expf(s[nt][0] - mn0), p1 = __expf(s[nt][1] - mn0);
            const float p2 = __expf(s[nt][2] - mn1), p3 = __expf(s[nt][3] - mn1);
            rs0 += p0 + p1; rs1 += p2 + p3;
            const __nv_bfloat16 h0 = __float2bfloat16(p0), h1 = __float2bfloat16(p1);
            const __nv_bfloat16 h2 = __float2bfloat16(p2), h3 = __float2bfloat16(p3);
            *(__nv_bfloat162*)(sm + R_PH + rA * 144 + col * 2) = __halves2bfloat162(h0, h1);
            *(__nv_bfloat162*)(sm + R_PL + rA * 144 + col * 2) = __halves2bfloat162(
                __float2bfloat16(p0 - __bfloat162float(h0)),
                __float2bfloat16(p1 - __bfloat162float(h1)));
            *(__nv_bfloat162*)(sm + R_PH + rB * 144 + col * 2) = __halves2bfloat162(h2, h3);
            *(__nv_bfloat162*)(sm + R_PL + rB * 144 + col * 2) = __halves2bfloat162(
                __float2bfloat16(p2 - __bfloat162float(h2)),
                __float2bfloat16(p3 - __bfloat162float(h3)));
            o[nt][0] *= al0; o[nt][1] *= al0; o[nt][2] *= al1; o[nt][3] *= al1;
        }
        rs0 += __shfl_xor_sync(0xffffffffu, rs0, 1);
        rs0 += __shfl_xor_sync(0xffffffffu, rs0, 2);
        rs1 += __shfl_xor_sync(0xffffffffu, rs1, 1);
        rs1 += __shfl_xor_sync(0xffffffffu, rs1, 2);
        if ((lane & 3) == 0) {
            psum[p * 32 + h * 16 + qr_]     = rs0;
            psum[p * 32 + h * 16 + qr_ + 8] = rs1;
        }
        barp(1 + p);
        rs0 += psum[p * 32 + (1 - h) * 16 + qr_];
        rs1 += psum[p * 32 + (1 - h) * 16 + qr_ + 8];
        li0 = li0 * al0 + rs0; li1 = li1 * al1 + rs1;
        m0 = mn0; m1 = mn1;
        // PV: d-cols half h
        wgemm3_nt4(ApH, ApL, Vs + h * 32 * 144, Vs + 9216 + h * 32 * 144,
                   a_off, b_off, o);
        __syncthreads();
    }

    const float iv0 = 1.f / li0, iv1 = 1.f / li1;
    const int rA = 16 * p + qr_;
    #pragma unroll
    for (int nt = 0; nt < 4; nt++) {
        const int d = h * 32 + (nt << 3) + qc_;
        const float v0 = o[nt][0] * iv0, v1 = o[nt][1] * iv0;
        const float v2 = o[nt][2] * iv1, v3 = o[nt][3] * iv1;
        const size_t gA = ((size_t)(i0 + rA) * 8 + b) * 512 + n * 64 + d;
        const size_t gB = ((size_t)(i0 + rA + 8) * 8 + b) * 512 + n * 64 + d;
        const __nv_bfloat16 h0 = __float2bfloat16(v0), h1 = __float2bfloat16(v1);
        const __nv_bfloat16 h2 = __float2bfloat16(v2), h3 = __float2bfloat16(v3);
        *(__nv_bfloat162*)(vech + gA) = __halves2bfloat162(h0, h1);
        *(__nv_bfloat162*)(vecl + gA) = __halves2bfloat162(
            __float2bfloat16(v0 - __bfloat162float(h0)),
            __float2bfloat16(v1 - __bfloat162float(h1)));
        *(__nv_bfloat162*)(vech + gB) = __halves2bfloat162(h2, h3);
        *(__nv_bfloat162*)(vecl + gB) = __halves2bfloat162(
            __float2bfloat16(v2 - __bfloat162float(h2)),
            __float2bfloat16(v3 - __bfloat162float(h3)));
    }
}

// ===== flash attention 2 (cross), 256 thr, 128-row tile, cp.async 2-stage ===
#define C_QH   0
#define C_QL   18432
#define C_KS0  36864     /* stage s: +s*18432; KH +0, KL +9216 */
#define C_VS0  73728
#define C_PH   110592
#define C_PL   129024
#define C_FL0  147456    /* 2 x 64 bytes */
#define CTX_SMEM 147584

__global__ __launch_bounds__(256) void flash_ctx_mma(
    const __nv_bfloat16* __restrict__ qh, const __nv_bfloat16* __restrict__ ql,
    const __nv_bfloat16* __restrict__ kvh, const __nv_bfloat16* __restrict__ kvl,
    const __nv_bfloat16* __restrict__ vth, const __nv_bfloat16* __restrict__ vtl,
    const unsigned char* __restrict__ emask,
    __nv_bfloat16* __restrict__ vech, __nv_bfloat16* __restrict__ vecl)
{
    extern __shared__ char sm[];
    const uint32_t sb = smem_u32(sm);
    const int tid = threadIdx.x, lane = tid & 31, wid = tid >> 5;
    const int i0 = blockIdx.x << 7;
    const int b = blockIdx.y >> 3, n = blockIdx.y & 7;
    const int wrow = wid << 4;
    const int lr = lane & 7, lg = lane >> 3;
    const uint32_t a_off = (uint32_t)(((lg & 1) << 3) + lr) * 144u + (uint32_t)((lg >> 1) << 4);
    const uint32_t b_off = (uint32_t)(((lg >> 1) << 3) + lr) * 144u + (uint32_t)((lg & 1) << 4);
    const int qr_ = lane >> 2, qc_ = (lane & 3) << 1;
    const uint32_t AqH = sb + C_QH + wrow * 144, AqL = sb + C_QL + wrow * 144;
    const uint32_t ApH = sb + C_PH + wrow * 144, ApL = sb + C_PL + wrow * 144;
    const int nit = ELEN >> 6;

    auto load_iter = [&](int k, int s) {
        const int j0k = k << 6;
        const uint32_t Ks = sb + C_KS0 + s * 18432;
        const uint32_t Vs = sb + C_VS0 + s * 18432;
        #pragma unroll 2
        for (int i = tid; i < 512; i += 256) {
            const int row = i >> 3, ch = i & 7;
            const size_t gk = ((size_t)(j0k + row) * 8 + b) * 1024 + n * 64 + ch * 8;
            cpa16(Ks + row * 144 + ch * 16, kvh + gk);
            cpa16(Ks + 9216 + row * 144 + ch * 16, kvl + gk);
            const size_t gv = ((size_t)(b * 8 + n) * 64 + row) * 1024 + j0k + ch * 8;
            cpa16(Vs + row * 144 + ch * 16, vth + gv);
            cpa16(Vs + 9216 + row * 144 + ch * 16, vtl + gv);
        }
        if (tid < 64) sm[C_FL0 + s * 64 + tid] = (char)emask[(size_t)(j0k + tid) * 8 + b];
        asm volatile("cp.async.commit_group;" ::: "memory");
    };

    for (int t = tid; t < 1024; t += 256) {
        const int row = t >> 3, c4 = t & 7;
        const size_t g = ((size_t)(i0 + row) * 8 + b) * 512 + n * 64 + c4 * 8;
        *(uint4*)(sm + C_QH + row * 144 + c4 * 16) = *(const uint4*)(qh + g);
        *(uint4*)(sm + C_QL + row * 144 + c4 * 16) = *(const uint4*)(ql + g);
    }
    load_iter(0, 0);

    float m0 = -1e30f, m1 = -1e30f, li0 = 0.f, li1 = 0.f;
    float o[8][4];
    #pragma unroll
    for (int nt = 0; nt < 8; nt++) { o[nt][0]=0; o[nt][1]=0; o[nt][2]=0; o[nt][3]=0; }

    for (int k = 0; k < nit; k++) {
        if (k + 1 < nit) {
            load_iter(k + 1, (k + 1) & 1);
            asm volatile("cp.async.wait_group 1;" ::: "memory");
        } else {
            asm volatile("cp.async.wait_group 0;" ::: "memory");
        }
        __syncthreads();
        const uint32_t Ks = sb + C_KS0 + (k & 1) * 18432;
        const uint32_t Vs = sb + C_VS0 + (k & 1) * 18432;
        const int fl = C_FL0 + (k & 1) * 64;

        float s[8][4];
        #pragma unroll
        for (int nt = 0; nt < 8; nt++) { s[nt][0]=0; s[nt][1]=0; s[nt][2]=0; s[nt][3]=0; }
        wgemm3(AqH, AqL, Ks, Ks + 9216, a_off, b_off, s);
        __syncwarp();

        const int rA = wrow + qr_, rB = rA + 8;
        float rmax0 = -1e30f, rmax1 = -1e30f;
        #pragma unroll
        for (int nt = 0; nt < 8; nt++) {
            const int col = (nt << 3) + qc_;
            const bool f0 = sm[fl + col] != 0, f1 = sm[fl + col + 1] != 0;
            s[nt][0] = f0 ? -1e4f : s[nt][0] * ATT_SCALE;
            s[nt][1] = f1 ? -1e4f : s[nt][1] * ATT_SCALE;
            s[nt][2] = f0 ? -1e4f : s[nt][2] * ATT_SCALE;
            s[nt][3] = f1 ? -1e4f : s[nt][3] * ATT_SCALE;
            rmax0 = fmaxf(rmax0, fmaxf(s[nt][0], s[nt][1]));
            rmax1 = fmaxf(rmax1, fmaxf(s[nt][2], s[nt][3]));
        }
        rmax0 = fmaxf(rmax0, __shfl_xor_sync(0xffffffffu, rmax0, 1));
        rmax0 = fmaxf(rmax0, __shfl_xor_sync(0xffffffffu, rmax0, 2));
        rmax1 = fmaxf(rmax1, __shfl_xor_sync(0xffffffffu, rmax1, 1));
        rmax1 = fmaxf(rmax1, __shfl_xor_sync(0xffffffffu, rmax1, 2));
        const float mn0 = fmaxf(m0, rmax0), mn1 = fmaxf(m1, rmax1);
        const float al0 = __expf(m0 - mn0), al1 = __expf(m1 - mn1);
        float rs0 = 0.f, rs1 = 0.f;
        #pragma unroll
        for (int nt = 0; nt < 8; nt++) {
            const int col = (nt << 3) + qc_;
            const float p0 = __expf(s[nt][0] - mn0), p1 = __expf(s[nt][1] - mn0);
            const float p2 = __expf(s[nt][2] - mn1), p3 = __expf(s[nt][3] - mn1);
            rs0 += p0 + p1; rs1 += p2 + p3;
            const __nv_bfloat16 h0 = __float2bfloat16(p0), h1 = __float2bfloat16(p1);
            const __nv_bfloat16 h2 = __float2bfloat16(p2), h3 = __float2bfloat16(p3);
            *(__nv_bfloat162*)(sm + C_PH + rA * 144 + col * 2) = __halves2bfloat162(h0, h1);
            *(__nv_bfloat162*)(sm + C_PL + rA * 144 + col * 2) = __halves2bfloat162(
                __float2bfloat16(p0 - __bfloat162float(h0)),
                __float2bfloat16(p1 - __bfloat162float(h1)));
            *(__nv_bfloat162*)(sm + C_PH + rB * 144 + col * 2) = __halves2bfloat162(h2, h3);
            *(__nv_bfloat162*)(sm + C_PL + rB * 144 + col * 2) = __halves2bfloat162(
                __float2bfloat16(p2 - __bfloat162float(h2)),
                __float2bfloat16(p3 - __bfloat162float(h3)));
            o[nt][0] *= al0; o[nt][1] *= al0; o[nt][2] *= al1; o[nt][3] *= al1;
        }
        rs0 += __shfl_xor_sync(0xffffffffu, rs0, 1);
        rs0 += __shfl_xor_sync(0xffffffffu, rs0, 2);
        rs1 += __shfl_xor_sync(0xffffffffu, rs1, 1);
        rs1 += __shfl_xor_sync(0xffffffffu, rs1, 2);
        li0 = li0 * al0 + rs0; li1 = li1 * al1 + rs1;
        m0 = mn0; m1 = mn1;
        __syncwarp();
        wgemm3(ApH, ApL, Vs, Vs + 9216, a_off, b_off, o);
        __syncthreads();
    }

    const float iv0 = 1.f / li0, iv1 = 1.f / li1;
    const int rA = wrow + qr_;
    #pragma unroll
    for (int nt = 0; nt < 8; nt++) {
        const int d = (nt << 3) + qc_;
        const float v0 = o[nt][0] * iv0, v1 = o[nt][1] * iv0;
        const float v2 = o[nt][2] * iv1, v3 = o[nt][3] * iv1;
        const size_t gA = ((size_t)(i0 + rA) * 8 + b) * 512 + n * 64 + d;
        const size_t gB = ((size_t)(i0 + rA + 8) * 8 + b) * 512 + n * 64 + d;
        const __nv_bfloat16 h0 = __float2bfloat16(v0), h1 = __float2bfloat16(v1);
        const __nv_bfloat16 h2 = __float2bfloat16(v2), h3 = __float2bfloat16(v3);
        *(__nv_bfloat162*)(vech + gA) = __halves2bfloat162(h0, h1);
        *(__nv_bfloat162*)(vecl + gA) = __halves2bfloat162(
            __float2bfloat16(v0 - __bfloat162float(h0)),
            __float2bfloat16(v1 - __bfloat162float(h1)));
        *(__nv_bfloat162*)(vech + gB) = __halves2bfloat162(h2, h3);
        *(__nv_bfloat162*)(vecl + gB) = __halves2bfloat162(
            __float2bfloat16(v2 - __bfloat162float(h2)),
            __float2bfloat16(v3 - __bfloat162float(h3)));
    }
}

// ===================== host orchestration ====================================
extern "C" void kernel_launch(void* const* d_in, const int* in_sizes, int n_in,
                              void* d_out, int out_size)
{
    (void)in_sizes; (void)n_in; (void)out_size;
    const float* dec_inp = (const float*)d_in[0];
    const float* r       = (const float*)d_in[1];
    const float* enc_out = (const float*)d_in[2];
    const float* rwb     = (const float*)d_in[3];
    const float* rrb     = (const float*)d_in[4];
    const float* qkv_w   = (const float*)d_in[5];
    const float* r_w     = (const float*)d_in[6];
    const float* o_w     = (const float*)d_in[7];
    const float* ln1_g   = (const float*)d_in[8];
    const float* ln1_b   = (const float*)d_in[9];
    const float* q_w     = (const float*)d_in[10];
    const float* kv_w    = (const float*)d_in[11];
    const float* o2_w    = (const float*)d_in[12];
    const float* ln2_g   = (const float*)d_in[13];
    const float* ln2_b   = (const float*)d_in[14];
    const float* ff_w1   = (const float*)d_in[15];
    const float* ff_b1   = (const float*)d_in[16];
    const float* ff_w2   = (const float*)d_in[17];
    const float* ff_b2   = (const float*)d_in[18];
    const float* ln3_g   = (const float*)d_in[19];
    const float* ln3_b   = (const float*)d_in[20];
    const unsigned char* emask = (const unsigned char*)d_in[22];
    float* out = (float*)d_out;

    float *out1, *h2, *out2, *qbias, *ccv;
    __nv_bfloat16 *wthi, *wtlo, *hh, *hl, *headsh, *headsl, *rh, *rl, *rkh, *rkl;
    __nv_bfloat16 *vth, *vtl, *vech, *vecl, *h2h, *h2l, *q2h, *q2l, *eh, *el;
    __nv_bfloat16 *kvh, *kvl, *vt2h, *vt2l, *vec2h, *vec2l, *th, *tl;
    cudaGetSymbolAddress((void**)&out1,  g_out1);
    cudaGetSymbolAddress((void**)&h2,    g_h2);
    cudaGetSymbolAddress((void**)&out2,  g_out2);
    cudaGetSymbolAddress((void**)&qbias, g_qbias);
    cudaGetSymbolAddress((void**)&ccv,   g_cc);
    cudaGetSymbolAddress((void**)&wthi,  g_wthi);
    cudaGetSymbolAddress((void**)&wtlo,  g_wtlo);
    cudaGetSymbolAddress((void**)&hh,    g_hh);
    cudaGetSymbolAddress((void**)&hl,    g_hl);
    cudaGetSymbolAddress((void**)&headsh,g_headsh);
    cudaGetSymbolAddress((void**)&headsl,g_headsl);
    cudaGetSymbolAddress((void**)&rh,    g_rh);
    cudaGetSymbolAddress((void**)&rl,    g_rl);
    cudaGetSymbolAddress((void**)&rkh,   g_rkh);
    cudaGetSymbolAddress((void**)&rkl,   g_rkl);
    cudaGetSymbolAddress((void**)&vth,   g_vth);
    cudaGetSymbolAddress((void**)&vtl,   g_vtl);
    cudaGetSymbolAddress((void**)&vech,  g_vech);
    cudaGetSymbolAddress((void**)&vecl,  g_vecl);
    cudaGetSymbolAddress((void**)&h2h,   g_h2h);
    cudaGetSymbolAddress((void**)&h2l,   g_h2l);
    cudaGetSymbolAddress((void**)&q2h,   g_q2h);
    cudaGetSymbolAddress((void**)&q2l,   g_q2l);
    cudaGetSymbolAddress((void**)&eh,    g_eh);
    cudaGetSymbolAddress((void**)&el,    g_el);
    cudaGetSymbolAddress((void**)&kvh,   g_kvh);
    cudaGetSymbolAddress((void**)&kvl,   g_kvl);
    cudaGetSymbolAddress((void**)&vt2h,  g_vt2h);
    cudaGetSymbolAddress((void**)&vt2l,  g_vt2l);
    cudaGetSymbolAddress((void**)&vec2h, g_vec2h);
    cudaGetSymbolAddress((void**)&vec2l, g_vec2l);
    cudaGetSymbolAddress((void**)&th,    g_th);
    cudaGetSymbolAddress((void**)&tl,    g_tl);

    cudaFuncSetAttribute(flash_rel_mma, cudaFuncAttributeMaxDynamicSharedMemorySize, REL_SMEM);
    cudaFuncSetAttribute(flash_ctx_mma, cudaFuncAttributeMaxDynamicSharedMemorySize, CTX_SMEM);
    cudaFuncSetAttribute(gemm_hmma<false, false>, cudaFuncAttributeMaxDynamicSharedMemorySize, GP_SMEM);
    cudaFuncSetAttribute(gemm_hmma<false, true>,  cudaFuncAttributeMaxDynamicSharedMemorySize, GP_SMEM);
    cudaFuncSetAttribute(gemm_hmma<true, true>,   cudaFuncAttributeMaxDynamicSharedMemorySize, GP_SMEM);

    // ---- weights + misc prep ----
    tsplit_all<<<4352, 256>>>(qkv_w, r_w, o_w, q_w, kv_w, o2_w, ff_w1, ff_w2,
                              wthi, wtlo);
    qbias_k<<<6, 256>>>(rwb, qbias);
    split_k<<<QLEN * DMODEL / 1024, 256>>>(r, rh, rl, QLEN * DMODEL / 4);
    split_k<<<ROWS * DMODEL / 1024, 256>>>(enc_out, eh, el, ROWS * DMODEL / 4);

    // ---- block 1: relative self-attention ----
    ln_k<false, true><<<ROWS, 128>>>(dec_inp, ln1_g, ln1_b, nullptr, hh, hl);
    gemm_hmma<false, true><<<dim3(12, 64), 256, GP_SMEM>>>(
        hh, hl, wthi + WT_QKV, wtlo + WT_QKV, qbias, nullptr,
        nullptr, headsh, headsl, ROWS, 1536, 512);
    gemm_hmma<false, true><<<dim3(4, 8), 256, GP_SMEM>>>(
        rh, rl, wthi + WT_RW, wtlo + WT_RW, nullptr, nullptr,
        nullptr, rkh, rkl, QLEN, 512, 512);
    vtrans_k<<<dim3(32, 64), 256>>>(headsh, headsl, vth, vtl, 1536, 1024);
    c_k<<<1024, 256>>>(rkh, rkl, rwb, rrb, ccv);
    flash_rel_mma<<<dim3(16, 64), 256, REL_SMEM>>>(headsh, headsl, vth, vtl,
                                                   rkh, rkl, ccv, vech, vecl);
    gemm_hmma<false, false><<<dim3(4, 64), 256, GP_SMEM>>>(
        vech, vecl, wthi + WT_OW, wtlo + WT_OW, nullptr, dec_inp,
        out1, nullptr, nullptr, ROWS, 512, 512);

    // ---- block 2: cross attention ----
    ln_k<true, true><<<ROWS, 128>>>(out1, ln2_g, ln2_b, h2, h2h, h2l);
    gemm_hmma<false, true><<<dim3(4, 64), 256, GP_SMEM>>>(
        h2h, h2l, wthi + WT_QW, wtlo + WT_QW, nullptr, nullptr,
        nullptr, q2h, q2l, ROWS, 512, 512);
    gemm_hmma<false, true><<<dim3(8, 64), 256, GP_SMEM>>>(
        eh, el, wthi + WT_KVW, wtlo + WT_KVW, nullptr, nullptr,
        nullptr, kvh, kvl, ROWS, 1024, 512);
    vtrans_k<<<dim3(32, 64), 256>>>(kvh, kvl, vt2h, vt2l, 1024, 512);
    flash_ctx_mma<<<dim3(8, 64), 256, CTX_SMEM>>>(q2h, q2l, kvh, kvl, vt2h, vt2l,
                                                  emask, vec2h, vec2l);
    gemm_hmma<false, false><<<dim3(4, 64), 256, GP_SMEM>>>(
        vec2h, vec2l, wthi + WT_O2W, wtlo + WT_O2W, nullptr, h2,
        out2, nullptr, nullptr, ROWS, 512, 512);

    // ---- block 3: FF ----
    ln_k<false, true><<<ROWS, 128>>>(out2, ln3_g, ln3_b, nullptr, hh, hl);
    gemm_hmma<true, true><<<dim3(16, 64), 256, GP_SMEM>>>(
        hh, hl, wthi + WT_FF1, wtlo + WT_FF1, ff_b1, nullptr,
        nullptr, th, tl, ROWS, 2048, 512);
    gemm_hmma<false, false><<<dim3(4, 64), 256, GP_SMEM>>>(
        th, tl, wthi + WT_FF2, wtlo + WT_FF2, ff_b2, out2,
        out, nullptr, nullptr, ROWS, 512, 2048);
}

// round 12
// speedup vs baseline: 3.0516x; 1.0633x over previous
#include <cuda_runtime.h>
#include <cuda_bf16.h>
#include <cstdint>
#include <cstddef>

#define QLEN   1024
#define BATCH  8
#define DMODEL 512
#define NHEAD  8
#define DHEAD  64
#define DINNER 2048
#define ELEN   1024
#define ATT_SCALE 0.125f
#define ROWS (QLEN * BATCH)   /* 8192 */

// ===================== warp MMA helpers =====================================
__device__ __forceinline__ uint32_t smem_u32(const void* p) {
    uint32_t a;
    asm("{ .reg .u64 t; cvta.to.shared.u64 t, %1; cvt.u32.u64 %0, t; }"
        : "=r"(a) : "l"(p));
    return a;
}

__device__ __forceinline__ void ldsm4(uint32_t* r, uint32_t addr) {
    asm volatile("ldmatrix.sync.aligned.m8n8.x4.shared.b16 {%0,%1,%2,%3}, [%4];"
                 : "=r"(r[0]), "=r"(r[1]), "=r"(r[2]), "=r"(r[3]) : "r"(addr));
}

__device__ __forceinline__ void mma16816(float* d, const uint32_t* a, const uint32_t* b) {
    asm volatile(
        "mma.sync.aligned.m16n8k16.row.col.f32.bf16.bf16.f32 "
        "{%0,%1,%2,%3}, {%4,%5,%6,%7}, {%8,%9}, {%0,%1,%2,%3};"
        : "+f"(d[0]), "+f"(d[1]), "+f"(d[2]), "+f"(d[3])
        : "r"(a[0]), "r"(a[1]), "r"(a[2]), "r"(a[3]), "r"(b[0]), "r"(b[1]));
}

__device__ __forceinline__ void cpa16(uint32_t dst, const void* src) {
    asm volatile("cp.async.cg.shared.global [%0], [%1], 16;" :: "r"(dst), "l"(src));
}

// predicated: src_size 0 zero-fills the 16B destination
__device__ __forceinline__ void cpa16p(uint32_t dst, const void* src, int ok) {
    asm volatile("cp.async.cg.shared.global [%0], [%1], 16, %2;"
                 :: "r"(dst), "l"(src), "r"(ok ? 16 : 0));
}

__device__ __forceinline__ void barp(int id) {
    asm volatile("bar.sync %0, %1;" :: "r"(id), "r"(64) : "memory");
}

// 3-term split-bf16 warp GEMM, 64-col B (nt=8), K=64, 144B stride (flash)
__device__ __forceinline__ void wgemm3(uint32_t Ah, uint32_t Al,
                                       uint32_t Bh, uint32_t Bl,
                                       uint32_t a_off, uint32_t b_off,
                                       float acc[8][4])
{
    #pragma unroll
    for (int ks = 0; ks < 4; ks++) {
        const uint32_t ra = (uint32_t)(ks << 5);
        uint32_t ah[4], al[4];
        ldsm4(ah, Ah + ra + a_off);
        ldsm4(al, Al + ra + a_off);
        #pragma unroll
        for (int np = 0; np < 4; np++) {
            uint32_t bh[4], bl[4];
            const uint32_t rb = (uint32_t)(np * 16 * 144 + (ks << 5));
            ldsm4(bh, Bh + rb + b_off);
            ldsm4(bl, Bl + rb + b_off);
            #pragma unroll
            for (int hf = 0; hf < 2; hf++) {
                float* d = acc[(np << 1) + hf];
                mma16816(d, ah, bh + (hf << 1));
                mma16816(d, ah, bl + (hf << 1));
                mma16816(d, al, bh + (hf << 1));
            }
        }
    }
}

// nt=4 variant (32-col B), 144B stride
__device__ __forceinline__ void wgemm3_nt4(uint32_t Ah, uint32_t Al,
                                           uint32_t Bh, uint32_t Bl,
                                           uint32_t a_off, uint32_t b_off,
                                           float acc[4][4])
{
    #pragma unroll
    for (int ks = 0; ks < 4; ks++) {
        const uint32_t ra = (uint32_t)(ks << 5);
        uint32_t ah[4], al[4];
        ldsm4(ah, Ah + ra + a_off);
        ldsm4(al, Al + ra + a_off);
        #pragma unroll
        for (int np = 0; np < 2; np++) {
            uint32_t bh[4], bl[4];
            const uint32_t rb = (uint32_t)(np * 16 * 144 + (ks << 5));
            ldsm4(bh, Bh + rb + b_off);
            ldsm4(bl, Bl + rb + b_off);
            #pragma unroll
            for (int hf = 0; hf < 2; hf++) {
                float* d = acc[(np << 1) + hf];
                mma16816(d, ah, bh + (hf << 1));
                mma16816(d, ah, bl + (hf << 1));
                mma16816(d, al, bh + (hf << 1));
            }
        }
    }
}

__device__ __forceinline__ void split_store4(char* hi, char* lo, float4 v) {
    const __nv_bfloat16 h0 = __float2bfloat16(v.x), h1 = __float2bfloat16(v.y);
    const __nv_bfloat16 h2 = __float2bfloat16(v.z), h3 = __float2bfloat16(v.w);
    *(__nv_bfloat162*)(hi)     = __halves2bfloat162(h0, h1);
    *(__nv_bfloat162*)(hi + 4) = __halves2bfloat162(h2, h3);
    *(__nv_bfloat162*)(lo)     = __halves2bfloat162(
        __float2bfloat16(v.x - __bfloat162float(h0)),
        __float2bfloat16(v.y - __bfloat162float(h1)));
    *(__nv_bfloat162*)(lo + 4) = __halves2bfloat162(
        __float2bfloat16(v.z - __bfloat162float(h2)),
        __float2bfloat16(v.w - __bfloat162float(h3)));
}

// ===================== scratch ==============================================
__device__ float g_out1[ROWS * DMODEL];
__device__ float g_h2  [ROWS * DMODEL];
__device__ float g_out2[ROWS * DMODEL];
__device__ float g_qbias[3 * DMODEL];
__device__ float g_cc  [NHEAD * 1152];        // zero-init pad beyond 1024

__device__ __nv_bfloat16 g_hh[ROWS * DMODEL],    g_hl[ROWS * DMODEL];
__device__ __nv_bfloat16 g_headsh[ROWS * 1536],  g_headsl[ROWS * 1536];
__device__ __nv_bfloat16 g_rh[QLEN * DMODEL],    g_rl[QLEN * DMODEL];
__device__ __nv_bfloat16 g_rkh[QLEN * DMODEL],   g_rkl[QLEN * DMODEL];
__device__ __nv_bfloat16 g_vth[64 * 64 * QLEN],  g_vtl[64 * 64 * QLEN];
__device__ __nv_bfloat16 g_vech[ROWS * DMODEL],  g_vecl[ROWS * DMODEL];
__device__ __nv_bfloat16 g_h2h[ROWS * DMODEL],   g_h2l[ROWS * DMODEL];
__device__ __nv_bfloat16 g_q2h[ROWS * DMODEL],   g_q2l[ROWS * DMODEL];
__device__ __nv_bfloat16 g_eh[ROWS * DMODEL],    g_el[ROWS * DMODEL];
__device__ __nv_bfloat16 g_kvh[ROWS * 1024],     g_kvl[ROWS * 1024];
__device__ __nv_bfloat16 g_vt2h[64 * 64 * ELEN], g_vt2l[64 * 64 * ELEN];
__device__ __nv_bfloat16 g_vec2h[ROWS * DMODEL], g_vec2l[ROWS * DMODEL];
__device__ __nv_bfloat16 g_th[ROWS * DINNER],    g_tl[ROWS * DINNER];

#define WT_QKV 0
#define WT_RW  786432
#define WT_OW  1048576
#define WT_QW  1310720
#define WT_KVW 1572864
#define WT_O2W 2097152
#define WT_FF1 2359296
#define WT_FF2 3407872
#define WT_TOTAL 4456448
__device__ __nv_bfloat16 g_wthi[WT_TOTAL];
__device__ __nv_bfloat16 g_wtlo[WT_TOTAL];

// ===================== small prep kernels ===================================
__global__ __launch_bounds__(256) void split_k(const float* __restrict__ x,
                                               __nv_bfloat16* __restrict__ hi,
                                               __nv_bfloat16* __restrict__ lo, int n4)
{
    const int i = blockIdx.x * 256 + threadIdx.x;
    if (i >= n4) return;
    const float4 v = reinterpret_cast<const float4*>(x)[i];
    split_store4((char*)(hi + (size_t)i * 4), (char*)(lo + (size_t)i * 4), v);
}

// all 8 weight transposes+splits in one launch (linear block-range dispatch)
__global__ __launch_bounds__(256) void tsplit_all(
    const float* __restrict__ qkv, const float* __restrict__ rw,
    const float* __restrict__ ow,  const float* __restrict__ qw,
    const float* __restrict__ kvw, const float* __restrict__ o2w,
    const float* __restrict__ ff1, const float* __restrict__ ff2,
    __nv_bfloat16* __restrict__ hi, __nv_bfloat16* __restrict__ lo)
{
    int bid = blockIdx.x;
    const float* W; int K, N, gx; size_t off;
    if (bid < 768)                      { W = qkv; K = 512;  N = 1536; gx = 48; off = WT_QKV; }
    else if ((bid -= 768)  < 256)       { W = rw;  K = 512;  N = 512;  gx = 16; off = WT_RW;  }
    else if ((bid -= 256)  < 256)       { W = ow;  K = 512;  N = 512;  gx = 16; off = WT_OW;  }
    else if ((bid -= 256)  < 256)       { W = qw;  K = 512;  N = 512;  gx = 16; off = WT_QW;  }
    else if ((bid -= 256)  < 512)       { W = kvw; K = 512;  N = 1024; gx = 32; off = WT_KVW; }
    else if ((bid -= 512)  < 256)       { W = o2w; K = 512;  N = 512;  gx = 16; off = WT_O2W; }
    else if ((bid -= 256)  < 1024)      { W = ff1; K = 512;  N = 2048; gx = 64; off = WT_FF1; }
    else { bid -= 1024;                   W = ff2; K = 2048; N = 512;  gx = 16; off = WT_FF2; }

    __shared__ float t[32][33];
    const int n0 = (bid % gx) << 5, k0 = (bid / gx) << 5;
    const int x = threadIdx.x & 31, y = threadIdx.x >> 5;
    #pragma unroll
    for (int i = 0; i < 32; i += 8)
        t[y + i][x] = W[(size_t)(k0 + y + i) * N + n0 + x];
    __syncthreads();
    #pragma unroll
    for (int i = 0; i < 32; i += 8) {
        const float v = t[x][y + i];
        const size_t o = off + (size_t)(n0 + y + i) * K + k0 + x;
        const __nv_bfloat16 h = __float2bfloat16(v);
        hi[o] = h;
        lo[o] = __float2bfloat16(v - __bfloat162float(h));
    }
}

__global__ void qbias_k(const float* __restrict__ rwb, float* __restrict__ qb) {
    const int i = blockIdx.x * 256 + threadIdx.x;
    if (i < 1536) qb[i] = (i < 512) ? rwb[i] : 0.0f;
}

// c[n][u] = sum_d (rrb-rwb)[n][d] * rk[u][n*64+d]
__global__ __launch_bounds__(256) void c_k(const __nv_bfloat16* __restrict__ rkh,
                                           const __nv_bfloat16* __restrict__ rkl,
                                           const float* __restrict__ rwb,
                                           const float* __restrict__ rrb,
                                           float* __restrict__ cc)
{
    const int u = blockIdx.x;
    const int n = threadIdx.x >> 5, lane = threadIdx.x & 31;
    float s = 0.0f;
    #pragma unroll
    for (int k = 0; k < 2; k++) {
        const int d = lane + k * 32;
        const size_t g = (size_t)u * 512 + n * 64 + d;
        const float rv = __bfloat162float(rkh[g]) + __bfloat162float(rkl[g]);
        s += (rrb[n * 64 + d] - rwb[n * 64 + d]) * rv;
    }
    #pragma unroll
    for (int o = 16; o; o >>= 1) s += __shfl_xor_sync(0xffffffffu, s, o);
    if (lane == 0) cc[n * 1152 + u] = s;
}

// transpose V-part: src[(i*8+b)*stride + off + n*64 + d] -> dst[((b*8+n)*64+d)*1024 + i]
__global__ __launch_bounds__(256) void vtrans_k(const __nv_bfloat16* __restrict__ sh,
                                                const __nv_bfloat16* __restrict__ sl,
                                                __nv_bfloat16* __restrict__ dh,
                                                __nv_bfloat16* __restrict__ dl,
                                                int srcStride, int srcOff)
{
    __shared__ __nv_bfloat16 th[32][72], tl[32][72];
    const int i0 = blockIdx.x << 5;
    const int b = blockIdx.y >> 3, n = blockIdx.y & 7;
    const int t = threadIdx.x;
    {
        const int il = t >> 3, dj = (t & 7) << 3;
        const size_t g = ((size_t)(i0 + il) * 8 + b) * srcStride + srcOff + n * 64 + dj;
        *(uint4*)&th[il][dj] = *(const uint4*)(sh + g);
        *(uint4*)&tl[il][dj] = *(const uint4*)(sl + g);
    }
    __syncthreads();
    {
        const int dr = t >> 2, ij = (t & 3) << 3;
        __nv_bfloat16 oh[8], ol[8];
        #pragma unroll
        for (int k = 0; k < 8; k++) { oh[k] = th[ij + k][dr]; ol[k] = tl[ij + k][dr]; }
        const size_t g = ((size_t)(b * 8 + n) * 64 + dr) * 1024 + i0 + ij;
        *(uint4*)(dh + g) = *(uint4*)oh;
        *(uint4*)(dl + g) = *(uint4*)ol;
    }
}

// ===================== pipelined HMMA GEMM ==================================
// K-chunk 32, 2-stage cp.async double buffer. Tiles [128][40] bf16, 80B stride.
#define GP_STAGE 40960
#define GP_SMEM  81920

template <bool GELU, bool SPLIT>
__global__ __launch_bounds__(256, 2) void gemm_hmma(const __nv_bfloat16* __restrict__ Ahi,
                                                    const __nv_bfloat16* __restrict__ Alo,
                                                    const __nv_bfloat16* __restrict__ Bhi,
                                                    const __nv_bfloat16* __restrict__ Blo,
                                                    const float* __restrict__ bias,
                                                    const float* __restrict__ res,
                                                    float* __restrict__ C,
                                                    __nv_bfloat16* __restrict__ Ch,
                                                    __nv_bfloat16* __restrict__ Cl,
                                                    int M, int N, int K)
{
    extern __shared__ char smem[];
    const uint32_t sb = smem_u32(smem);
    const int tid = threadIdx.x;
    const int lane = tid & 31, wid = tid >> 5;
    const int m0 = blockIdx.y << 7, n0 = blockIdx.x << 7;
    const int wm = (wid & 3) << 5;
    const int wn = (wid >> 2) << 6;
    (void)M;

    float acc[2][8][4];
    #pragma unroll
    for (int mt = 0; mt < 2; mt++)
        #pragma unroll
        for (int nt = 0; nt < 8; nt++)
            #pragma unroll
            for (int e = 0; e < 4; e++) acc[mt][nt][e] = 0.0f;

    const int lr = lane & 7, lg = lane >> 3;
    const uint32_t a_off = (uint32_t)(((lg & 1) << 3) + lr) * 80u + (uint32_t)((lg >> 1) << 4);
    const uint32_t b_off = (uint32_t)(((lg >> 1) << 3) + lr) * 80u + (uint32_t)((lg & 1) << 4);

    const int nch = K >> 5;

    auto load_chunk = [&](int c, int s) {
        const int k0 = c << 5;
        const uint32_t sbase = sb + s * GP_STAGE;
        #pragma unroll
        for (int i = tid; i < 2048; i += 256) {
            const int tile = i >> 9;
            const int idx = i & 511;
            const int row = idx >> 2, kc = (idx & 3) << 3;
            const uint32_t dst = sbase + tile * 10240 + row * 80 + (idx & 3) * 16;
            const __nv_bfloat16* src;
            if (tile == 0)      src = Ahi + (size_t)(m0 + row) * K + k0 + kc;
            else if (tile == 1) src = Alo + (size_t)(m0 + row) * K + k0 + kc;
            else if (tile == 2) src = Bhi + (size_t)(n0 + row) * K + k0 + kc;
            else                src = Blo + (size_t)(n0 + row) * K + k0 + kc;
            cpa16(dst, src);
        }
        asm volatile("cp.async.commit_group;" ::: "memory");
    };

    load_chunk(0, 0);
    load_chunk(1, 1);

    for (int c = 0; c < nch; c++) {
        if (c + 1 < nch) asm volatile("cp.async.wait_group 1;" ::: "memory");
        else             asm volatile("cp.async.wait_group 0;" ::: "memory");
        __syncthreads();

        const uint32_t sbase = sb + (c & 1) * GP_STAGE;
        #pragma unroll
        for (int ks = 0; ks < 2; ks++) {
            const uint32_t kk2 = (uint32_t)(ks << 5);
            uint32_t ah[2][4], al[2][4];
            #pragma unroll
            for (int mt = 0; mt < 2; mt++) {
                const uint32_t ra = (uint32_t)((wm + (mt << 4)) * 80) + kk2 + a_off;
                ldsm4(ah[mt], sbase + ra);
                ldsm4(al[mt], sbase + 10240 + ra);
            }
            #pragma unroll
            for (int np = 0; np < 4; np++) {
                uint32_t bh[4], bl[4];
                const uint32_t rb = (uint32_t)((wn + (np << 4)) * 80) + kk2 + b_off;
                ldsm4(bh, sbase + 20480 + rb);
                ldsm4(bl, sbase + 30720 + rb);
                #pragma unroll
                for (int mt = 0; mt < 2; mt++) {
                    #pragma unroll
                    for (int hf = 0; hf < 2; hf++) {
                        float* d = acc[mt][(np << 1) + hf];
                        mma16816(d, ah[mt], bh + (hf << 1));
                        mma16816(d, ah[mt], bl + (hf << 1));
                        mma16816(d, al[mt], bh + (hf << 1));
                    }
                }
            }
        }
        __syncthreads();
        if (c + 2 < nch) load_chunk(c + 2, c & 1);
    }

    const int er = lane >> 2, ec = (lane & 3) << 1;
    #pragma unroll
    for (int mt = 0; mt < 2; mt++) {
        #pragma unroll
        for (int half = 0; half < 2; half++) {
            const int gr = m0 + wm + (mt << 4) + er + (half << 3);
            #pragma unroll
            for (int nt = 0; nt < 8; nt++) {
                const int gc = n0 + wn + (nt << 3) + ec;
                float v0 = acc[mt][nt][(half << 1) + 0];
                float v1 = acc[mt][nt][(half << 1) + 1];
                if (bias) { v0 += bias[gc]; v1 += bias[gc + 1]; }
                if (GELU) {
                    v0 = 0.5f * v0 * (1.0f + erff(v0 * 0.70710678118654752f));
                    v1 = 0.5f * v1 * (1.0f + erff(v1 * 0.70710678118654752f));
                }
                if (SPLIT) {
                    const __nv_bfloat16 h0 = __float2bfloat16(v0), h1 = __float2bfloat16(v1);
                    *(__nv_bfloat162*)(Ch + (size_t)gr * N + gc) = __halves2bfloat162(h0, h1);
                    *(__nv_bfloat162*)(Cl + (size_t)gr * N + gc) = __halves2bfloat162(
                        __float2bfloat16(v0 - __bfloat162float(h0)),
                        __float2bfloat16(v1 - __bfloat162float(h1)));
                } else {
                    if (res) {
                        const float2 rr = *reinterpret_cast<const float2*>(&res[(size_t)gr * N + gc]);
                        v0 += rr.x; v1 += rr.y;
                    }
                    *reinterpret_cast<float2*>(&C[(size_t)gr * N + gc]) = make_float2(v0, v1);
                }
            }
        }
    }
}

// ===================== LayerNorm ============================================
template <bool F32O, bool SPL>
__global__ __launch_bounds__(128) void ln_k(const float* __restrict__ x,
                                            const float* __restrict__ g,
                                            const float* __restrict__ b,
                                            float* __restrict__ yf,
                                            __nv_bfloat16* __restrict__ yh,
                                            __nv_bfloat16* __restrict__ yl)
{
    const int row = blockIdx.x;
    const int t = threadIdx.x;
    const float4 v = reinterpret_cast<const float4*>(x + (size_t)row * DMODEL)[t];
    float s  = v.x + v.y + v.z + v.w;
    float sq = v.x*v.x + v.y*v.y + v.z*v.z + v.w*v.w;
    #pragma unroll
    for (int o = 16; o; o >>= 1) {
        s  += __shfl_xor_sync(0xffffffffu, s,  o);
        sq += __shfl_xor_sync(0xffffffffu, sq, o);
    }
    __shared__ float ss[4], sqq[4];
    const int w = t >> 5, lane = t & 31;
    if (lane == 0) { ss[w] = s; sqq[w] = sq; }
    __syncthreads();
    s  = ss[0]  + ss[1]  + ss[2]  + ss[3];
    sq = sqq[0] + sqq[1] + sqq[2] + sqq[3];
    const float mean = s * (1.0f / DMODEL);
    const float var  = sq * (1.0f / DMODEL) - mean * mean;
    const float rstd = rsqrtf(var + 1e-5f);
    const float4 gg = reinterpret_cast<const float4*>(g)[t];
    const float4 bb = reinterpret_cast<const float4*>(b)[t];
    float4 o4;
    o4.x = (v.x - mean) * rstd * gg.x + bb.x;
    o4.y = (v.y - mean) * rstd * gg.y + bb.y;
    o4.z = (v.z - mean) * rstd * gg.z + bb.z;
    o4.w = (v.w - mean) * rstd * gg.w + bb.w;
    if (F32O) reinterpret_cast<float4*>(yf + (size_t)row * DMODEL)[t] = o4;
    if (SPL)  split_store4((char*)(yh + (size_t)row * DMODEL + t * 4),
                           (char*)(yl + (size_t)row * DMODEL + t * 4), o4);
}

// ===== flash attention 1 (rel, causal), 256 thr, cp.async 2-stage K/V =======
#define R_QH   0
#define R_QL   9216
#define R_KS0  18432     /* stage s: +s*18432; KH +0, KL +9216 */
#define R_VS0  55296
#define R_PH   92160
#define R_PL   101376
#define R_RH   110592
#define R_RL   129024
#define R_G    147456
#define R_C    181248    /* 2 x 64 floats */
#define R_PM   181760
#define R_PS   182272
#define REL_SMEM 182784

__global__ __launch_bounds__(256) void flash_rel_mma(
    const __nv_bfloat16* __restrict__ hh, const __nv_bfloat16* __restrict__ hl,
    const __nv_bfloat16* __restrict__ vth, const __nv_bfloat16* __restrict__ vtl,
    const __nv_bfloat16* __restrict__ rkh, const __nv_bfloat16* __restrict__ rkl,
    const float* __restrict__ cc,
    __nv_bfloat16* __restrict__ vech, __nv_bfloat16* __restrict__ vecl)
{
    extern __shared__ char sm[];
    const uint32_t sb = smem_u32(sm);
    const int tid = threadIdx.x, lane = tid & 31, wid = tid >> 5;
    const int p = wid >> 1, h = wid & 1;
    const int i0 = blockIdx.x << 6;
    const int b = blockIdx.y >> 3, n = blockIdx.y & 7;
    const int lr = lane & 7, lg = lane >> 3;
    const uint32_t a_off = (uint32_t)(((lg & 1) << 3) + lr) * 144u + (uint32_t)((lg >> 1) << 4);
    const uint32_t b_off = (uint32_t)(((lg >> 1) << 3) + lr) * 144u + (uint32_t)((lg & 1) << 4);
    const int qr_ = lane >> 2, qc_ = (lane & 3) << 1;
    float* G    = (float*)(sm + R_G);
    float* csm  = (float*)(sm + R_C);
    float* pmax = (float*)(sm + R_PM);
    float* psum = (float*)(sm + R_PS);
    const uint32_t AqH = sb + R_QH + p * 16 * 144, AqL = sb + R_QL + p * 16 * 144;
    const uint32_t ApH = sb + R_PH + p * 16 * 144, ApL = sb + R_PL + p * 16 * 144;
    const int ustart = 960 - i0;
    const int nit = (i0 >> 6) + 1;

    auto load_iter = [&](int k, int s) {
        const int j0k = k << 6;
        const uint32_t Ks = sb + R_KS0 + s * 18432;
        const uint32_t Vs = sb + R_VS0 + s * 18432;
        const int ub = ustart + ((k + 1) << 6);
        #pragma unroll 2
        for (int i = tid; i < 512; i += 256) {
            const int row = i >> 3, ch = i & 7;
            const size_t gk = ((size_t)(j0k + row) * 8 + b) * 1536 + 512 + n * 64 + ch * 8;
            cpa16(Ks + row * 144 + ch * 16, hh + gk);
            cpa16(Ks + 9216 + row * 144 + ch * 16, hl + gk);
            const size_t gv = ((size_t)(b * 8 + n) * 64 + row) * 1024 + j0k + ch * 8;
            cpa16(Vs + row * 144 + ch * 16, vth + gv);
            cpa16(Vs + 9216 + row * 144 + ch * 16, vtl + gv);
            const int u = ub + row;
            const int slot = u & 127;
            const int ok = (u < QLEN);
            const size_t gr = (size_t)(ok ? u : 0) * 512 + n * 64 + ch * 8;
            cpa16p(sb + R_RH + slot * 144 + ch * 16, rkh + gr, ok);
            cpa16p(sb + R_RL + slot * 144 + ch * 16, rkl + gr, ok);
        }
        if (tid < 64) csm[s * 64 + tid] = cc[n * 1152 + ub + tid];
        asm volatile("cp.async.commit_group;" ::: "memory");
    };

    for (int t = tid; t < 512; t += 256) {
        const int row = t >> 3, c4 = t & 7;
        const size_t g = ((size_t)(i0 + row) * 8 + b) * 1536 + n * 64 + c4 * 8;
        *(uint4*)(sm + R_QH + row * 144 + c4 * 16) = *(const uint4*)(hh + g);
        *(uint4*)(sm + R_QL + row * 144 + c4 * 16) = *(const uint4*)(hl + g);
    }
    for (int t = tid; t < 512; t += 256) {
        const int jr = t >> 3, c4 = t & 7;
        const int u = ustart + jr, slot = u & 127;
        uint4 vh = make_uint4(0, 0, 0, 0), vl = make_uint4(0, 0, 0, 0);
        if (u < QLEN) {
            const size_t g = (size_t)u * 512 + n * 64 + c4 * 8;
            vh = *(const uint4*)(rkh + g);
            vl = *(const uint4*)(rkl + g);
        }
        *(uint4*)(sm + R_RH + slot * 144 + c4 * 16) = vh;
        *(uint4*)(sm + R_RL + slot * 144 + c4 * 16) = vl;
    }
    if (tid < 64) csm[64 + tid] = cc[n * 1152 + ustart + tid];
    load_iter(0, 0);
    __syncthreads();

    {
        const int slotb = ustart & 127;
        float g4[4][4];
        #pragma unroll
        for (int nt = 0; nt < 4; nt++) { g4[nt][0]=0; g4[nt][1]=0; g4[nt][2]=0; g4[nt][3]=0; }
        wgemm3_nt4(AqH, AqL, sb + R_RH + (slotb + h * 32) * 144,
                   sb + R_RL + (slotb + h * 32) * 144, a_off, b_off, g4);
        #pragma unroll
        for (int nt = 0; nt < 4; nt++) {
            const int cl = h * 32 + (nt << 3) + qc_;
            const int col = slotb + cl;
            const float c0 = csm[64 + cl], c1 = csm[64 + cl + 1];
            *(float2*)&G[(16 * p + qr_) * 132 + col]     = make_float2(g4[nt][0] + c0, g4[nt][1] + c1);
            *(float2*)&G[(16 * p + qr_ + 8) * 132 + col] = make_float2(g4[nt][2] + c0, g4[nt][3] + c1);
        }
    }
    __syncthreads();

    float m0 = -1e30f, m1 = -1e30f, li0 = 0.f, li1 = 0.f;
    float o[4][4];
    #pragma unroll
    for (int nt = 0; nt < 4; nt++) { o[nt][0]=0; o[nt][1]=0; o[nt][2]=0; o[nt][3]=0; }

    for (int k = 0; k < nit; k++) {
        const int j0 = k << 6;
        if (k + 1 < nit) {
            load_iter(k + 1, (k + 1) & 1);
            asm volatile("cp.async.wait_group 1;" ::: "memory");
        } else {
            asm volatile("cp.async.wait_group 0;" ::: "memory");
        }
        __syncthreads();
        const uint32_t Ks = sb + R_KS0 + (k & 1) * 18432;
        const uint32_t Vs = sb + R_VS0 + (k & 1) * 18432;
        const float* csmb = csm + (k & 1) * 64;

        {
            const int slotb = (ustart + ((k + 1) << 6)) & 127;
            float g4[4][4];
            #pragma unroll
            for (int nt = 0; nt < 4; nt++) { g4[nt][0]=0; g4[nt][1]=0; g4[nt][2]=0; g4[nt][3]=0; }
            wgemm3_nt4(AqH, AqL, sb + R_RH + (slotb + h * 32) * 144,
                       sb + R_RL + (slotb + h * 32) * 144, a_off, b_off, g4);
            #pragma unroll
            for (int nt = 0; nt < 4; nt++) {
                const int cl = h * 32 + (nt << 3) + qc_;
                const int col = slotb + cl;
                const float c0 = csmb[cl], c1 = csmb[cl + 1];
                *(float2*)&G[(16 * p + qr_) * 132 + col]     = make_float2(g4[nt][0] + c0, g4[nt][1] + c1);
                *(float2*)&G[(16 * p + qr_ + 8) * 132 + col] = make_float2(g4[nt][2] + c0, g4[nt][3] + c1);
            }
        }
        float s[4][4];
        #pragma unroll
        for (int nt = 0; nt < 4; nt++) { s[nt][0]=0; s[nt][1]=0; s[nt][2]=0; s[nt][3]=0; }
        wgemm3_nt4(AqH, AqL, Ks + h * 32 * 144, Ks + 9216 + h * 32 * 144,
                   a_off, b_off, s);
        barp(1 + p);
        const int cb = 1023 + j0 - i0;
        const int rA = 16 * p + qr_, rB = rA + 8;
        float rmax0 = -1e30f, rmax1 = -1e30f;
        #pragma unroll
        for (int nt = 0; nt < 4; nt++) {
            const int col = h * 32 + (nt << 3) + qc_;
            s[nt][0] = (s[nt][0] + G[rA * 132 + ((cb + col - rA) & 127)]) * ATT_SCALE;
            s[nt][1] = (s[nt][1] + G[rA * 132 + ((cb + col + 1 - rA) & 127)]) * ATT_SCALE;
            s[nt][2] = (s[nt][2] + G[rB * 132 + ((cb + col - rB) & 127)]) * ATT_SCALE;
            s[nt][3] = (s[nt][3] + G[rB * 132 + ((cb + col + 1 - rB) & 127)]) * ATT_SCALE;
            if (j0 == i0) {
                if (col > rA)     s[nt][0] = -1e30f;
                if (col + 1 > rA) s[nt][1] = -1e30f;
                if (col > rB)     s[nt][2] = -1e30f;
                if (col + 1 > rB) s[nt][3] = -1e30f;
            }
            rmax0 = fmaxf(rmax0, fmaxf(s[nt][0], s[nt][1]));
            rmax1 = fmaxf(rmax1, fmaxf(s[nt][2], s[nt][3]));
        }
        rmax0 = fmaxf(rmax0, __shfl_xor_sync(0xffffffffu, rmax0, 1));
        rmax0 = fmaxf(rmax0, __shfl_xor_sync(0xffffffffu, rmax0, 2));
        rmax1 = fmaxf(rmax1, __shfl_xor_sync(0xffffffffu, rmax1, 1));
        rmax1 = fmaxf(rmax1, __shfl_xor_sync(0xffffffffu, rmax1, 2));
        if ((lane & 3) == 0) {
            pmax[p * 32 + h * 16 + qr_]     = rmax0;
            pmax[p * 32 + h * 16 + qr_ + 8] = rmax1;
        }
        barp(1 + p);
        rmax0 = fmaxf(rmax0, pmax[p * 32 + (1 - h) * 16 + qr_]);
        rmax1 = fmaxf(rmax1, pmax[p * 32 + (1 - h) * 16 + qr_ + 8]);
        const float mn0 = fmaxf(m0, rmax0), mn1 = fmaxf(m1, rmax1);
        const float al0 = __expf(m0 - mn0), al1 = __expf(m1 - mn1);
        float rs0 = 0.f, rs1 = 0.f;
        #pragma unroll
        for (int nt = 0; nt < 4; nt++) {
            const int col = h * 32 + (nt << 3) + qc_;
            const float p0 = __expf(s[nt][0] - mn0), p1 = __expf(s[nt][1] - mn0);
            const float p2 = __expf(s[nt][2] - mn1), p3 = __expf(s[nt][3] - mn1);
            rs0 += p0 + p1; rs1 += p2 + p3;
            const __nv_bfloat16 h0 = __float2bfloat16(p0), h1 = __float2bfloat16(p1);
            const __nv_bfloat16 h2 = __float2bfloat16(p2), h3 = __float2bfloat16(p3);
            *(__nv_bfloat162*)(sm + R_PH + rA * 144 + col * 2) = __halves2bfloat162(h0, h1);
            *(__nv_bfloat162*)(sm + R_PL + rA * 144 + col * 2) = __halves2bfloat162(
                __float2bfloat16(p0 - __bfloat162float(h0)),
                __float2bfloat16(p1 - __bfloat162float(h1)));
            *(__nv_bfloat162*)(sm + R_PH + rB * 144 + col * 2) = __halves2bfloat162(h2, h3);
            *(__nv_bfloat162*)(sm + R_PL + rB * 144 + col * 2) = __halves2bfloat162(
                __float2bfloat16(p2 - __bfloat162float(h2)),
                __float2bfloat16(p3 - __bfloat162float(h3)));
            o[nt][0] *= al0; o[nt][1] *= al0; o[nt][2] *= al1; o[nt][3] *= al1;
        }
        rs0 += __shfl_xor_sync(0xffffffffu, rs0, 1);
        rs0 += __shfl_xor_sync(0xffffffffu, rs0, 2);
        rs1 += __shfl_xor_sync(0xffffffffu, rs1, 1);
        rs1 += __shfl_xor_sync(0xffffffffu, rs1, 2);
        if ((lane & 3) == 0) {
            psum[p * 32 + h * 16 + qr_]     = rs0;
            psum[p * 32 + h * 16 + qr_ + 8] = rs1;
        }
        barp(1 + p);
        rs0 += psum[p * 32 + (1 - h) * 16 + qr_];
        rs1 += psum[p * 32 + (1 - h) * 16 + qr_ + 8];
        li0 = li0 * al0 + rs0; li1 = li1 * al1 + rs1;
        m0 = mn0; m1 = mn1;
        wgemm3_nt4(ApH, ApL, Vs + h * 32 * 144, Vs + 9216 + h * 32 * 144,
                   a_off, b_off, o);
        __syncthreads();
    }

    const float iv0 = 1.f / li0, iv1 = 1.f / li1;
    const int rA = 16 * p + qr_;
    #pragma unroll
    for (int nt = 0; nt < 4; nt++) {
        const int d = h * 32 + (nt << 3) + qc_;
        const float v0 = o[nt][0] * iv0, v1 = o[nt][1] * iv0;
        const float v2 = o[nt][2] * iv1, v3 = o[nt][3] * iv1;
        const size_t gA = ((size_t)(i0 + rA) * 8 + b) * 512 + n * 64 + d;
        const size_t gB = ((size_t)(i0 + rA + 8) * 8 + b) * 512 + n * 64 + d;
        const __nv_bfloat16 h0 = __float2bfloat16(v0), h1 = __float2bfloat16(v1);
        const __nv_bfloat16 h2 = __float2bfloat16(v2), h3 = __float2bfloat16(v3);
        *(__nv_bfloat162*)(vech + gA) = __halves2bfloat162(h0, h1);
        *(__nv_bfloat162*)(vecl + gA) = __halves2bfloat162(
            __float2bfloat16(v0 - __bfloat162float(h0)),
            __float2bfloat16(v1 - __bfloat162float(h1)));
        *(__nv_bfloat162*)(vech + gB) = __halves2bfloat162(h2, h3);
        *(__nv_bfloat162*)(vecl + gB) = __halves2bfloat162(
            __float2bfloat16(v2 - __bfloat162float(h2)),
            __float2bfloat16(v3 - __bfloat162float(h3)));
    }
}

// ===== flash attention 2 (cross), 256 thr, 128-row tile, cp.async 2-stage ===
#define C_QH   0
#define C_QL   18432
#define C_KS0  36864
#define C_VS0  73728
#define C_PH   110592
#define C_PL   129024
#define C_FL0  147456
#define CTX_SMEM 147584

__global__ __launch_bounds__(256) void flash_ctx_mma(
    const __nv_bfloat16* __restrict__ qh, const __nv_bfloat16* __restrict__ ql,
    const __nv_bfloat16* __restrict__ kvh, const __nv_bfloat16* __restrict__ kvl,
    const __nv_bfloat16* __restrict__ vth, const __nv_bfloat16* __restrict__ vtl,
    const unsigned char* __restrict__ emask,
    __nv_bfloat16* __restrict__ vech, __nv_bfloat16* __restrict__ vecl)
{
    extern __shared__ char sm[];
    const uint32_t sb = smem_u32(sm);
    const int tid = threadIdx.x, lane = tid & 31, wid = tid >> 5;
    const int i0 = blockIdx.x << 7;
    const int b = blockIdx.y >> 3, n = blockIdx.y & 7;
    const int wrow = wid << 4;
    const int lr = lane & 7, lg = lane >> 3;
    const uint32_t a_off = (uint32_t)(((lg & 1) << 3) + lr) * 144u + (uint32_t)((lg >> 1) << 4);
    const uint32_t b_off = (uint32_t)(((lg >> 1) << 3) + lr) * 144u + (uint32_t)((lg & 1) << 4);
    const int qr_ = lane >> 2, qc_ = (lane & 3) << 1;
    const uint32_t AqH = sb + C_QH + wrow * 144, AqL = sb + C_QL + wrow * 144;
    const uint32_t ApH = sb + C_PH + wrow * 144, ApL = sb + C_PL + wrow * 144;
    const int nit = ELEN >> 6;

    auto load_iter = [&](int k, int s) {
        const int j0k = k << 6;
        const uint32_t Ks = sb + C_KS0 + s * 18432;
        const uint32_t Vs = sb + C_VS0 + s * 18432;
        #pragma unroll 2
        for (int i = tid; i < 512; i += 256) {
            const int row = i >> 3, ch = i & 7;
            const size_t gk = ((size_t)(j0k + row) * 8 + b) * 1024 + n * 64 + ch * 8;
            cpa16(Ks + row * 144 + ch * 16, kvh + gk);
            cpa16(Ks + 9216 + row * 144 + ch * 16, kvl + gk);
            const size_t gv = ((size_t)(b * 8 + n) * 64 + row) * 1024 + j0k + ch * 8;
            cpa16(Vs + row * 144 + ch * 16, vth + gv);
            cpa16(Vs + 9216 + row * 144 + ch * 16, vtl + gv);
        }
        if (tid < 64) sm[C_FL0 + s * 64 + tid] = (char)emask[(size_t)(j0k + tid) * 8 + b];
        asm volatile("cp.async.commit_group;" ::: "memory");
    };

    for (int t = tid; t < 1024; t += 256) {
        const int row = t >> 3, c4 = t & 7;
        const size_t g = ((size_t)(i0 + row) * 8 + b) * 512 + n * 64 + c4 * 8;
        *(uint4*)(sm + C_QH + row * 144 + c4 * 16) = *(const uint4*)(qh + g);
        *(uint4*)(sm + C_QL + row * 144 + c4 * 16) = *(const uint4*)(ql + g);
    }
    load_iter(0, 0);

    float m0 = -1e30f, m1 = -1e30f, li0 = 0.f, li1 = 0.f;
    float o[8][4];
    #pragma unroll
    for (int nt = 0; nt < 8; nt++) { o[nt][0]=0; o[nt][1]=0; o[nt][2]=0; o[nt][3]=0; }

    for (int k = 0; k < nit; k++) {
        if (k + 1 < nit) {
            load_iter(k + 1, (k + 1) & 1);
            asm volatile("cp.async.wait_group 1;" ::: "memory");
        } else {
            asm volatile("cp.async.wait_group 0;" ::: "memory");
        }
        __syncthreads();
        const uint32_t Ks = sb + C_KS0 + (k & 1) * 18432;
        const uint32_t Vs = sb + C_VS0 + (k & 1) * 18432;
        const int fl = C_FL0 + (k & 1) * 64;

        float s[8][4];
        #pragma unroll
        for (int nt = 0; nt < 8; nt++) { s[nt][0]=0; s[nt][1]=0; s[nt][2]=0; s[nt][3]=0; }
        wgemm3(AqH, AqL, Ks, Ks + 9216, a_off, b_off, s);
        __syncwarp();

        const int rA = wrow + qr_, rB = rA + 8;
        float rmax0 = -1e30f, rmax1 = -1e30f;
        #pragma unroll
        for (int nt = 0; nt < 8; nt++) {
            const int col = (nt << 3) + qc_;
            const bool f0 = sm[fl + col] != 0, f1 = sm[fl + col + 1] != 0;
            s[nt][0] = f0 ? -1e4f : s[nt][0] * ATT_SCALE;
            s[nt][1] = f1 ? -1e4f : s[nt][1] * ATT_SCALE;
            s[nt][2] = f0 ? -1e4f : s[nt][2] * ATT_SCALE;
            s[nt][3] = f1 ? -1e4f : s[nt][3] * ATT_SCALE;
            rmax0 = fmaxf(rmax0, fmaxf(s[nt][0], s[nt][1]));
            rmax1 = fmaxf(rmax1, fmaxf(s[nt][2], s[nt][3]));
        }
        rmax0 = fmaxf(rmax0, __shfl_xor_sync(0xffffffffu, rmax0, 1));
        rmax0 = fmaxf(rmax0, __shfl_xor_sync(0xffffffffu, rmax0, 2));
        rmax1 = fmaxf(rmax1, __shfl_xor_sync(0xffffffffu, rmax1, 1));
        rmax1 = fmaxf(rmax1, __shfl_xor_sync(0xffffffffu, rmax1, 2));
        const float mn0 = fmaxf(m0, rmax0), mn1 = fmaxf(m1, rmax1);
        const float al0 = __expf(m0 - mn0), al1 = __expf(m1 - mn1);
        float rs0 = 0.f, rs1 = 0.f;
        #pragma unroll
        for (int nt = 0; nt < 8; nt++) {
            const int col = (nt << 3) + qc_;
            const float p0 = __expf(s[nt][0] - mn0), p1 = __expf(s[nt][1] - mn0);
            const float p2 = __expf(s[nt][2] - mn1), p3 = __expf(s[nt][3] - mn1);
            rs0 += p0 + p1; rs1 += p2 + p3;
            const __nv_bfloat16 h0 = __float2bfloat16(p0), h1 = __float2bfloat16(p1);
            const __nv_bfloat16 h2 = __float2bfloat16(p2), h3 = __float2bfloat16(p3);
            *(__nv_bfloat162*)(sm + C_PH + rA * 144 + col * 2) = __halves2bfloat162(h0, h1);
            *(__nv_bfloat162*)(sm + C_PL + rA * 144 + col * 2) = __halves2bfloat162(
                __float2bfloat16(p0 - __bfloat162float(h0)),
                __float2bfloat16(p1 - __bfloat162float(h1)));
            *(__nv_bfloat162*)(sm + C_PH + rB * 144 + col * 2) = __halves2bfloat162(h2, h3);
            *(__nv_bfloat162*)(sm + C_PL + rB * 144 + col * 2) = __halves2bfloat162(
                __float2bfloat16(p2 - __bfloat162float(h2)),
                __float2bfloat16(p3 - __bfloat162float(h3)));
            o[nt][0] *= al0; o[nt][1] *= al0; o[nt][2] *= al1; o[nt][3] *= al1;
        }
        rs0 += __shfl_xor_sync(0xffffffffu, rs0, 1);
        rs0 += __shfl_xor_sync(0xffffffffu, rs0, 2);
        rs1 += __shfl_xor_sync(0xffffffffu, rs1, 1);
        rs1 += __shfl_xor_sync(0xffffffffu, rs1, 2);
        li0 = li0 * al0 + rs0; li1 = li1 * al1 + rs1;
        m0 = mn0; m1 = mn1;
        __syncwarp();
        wgemm3(ApH, ApL, Vs, Vs + 9216, a_off, b_off, o);
        __syncthreads();
    }

    const float iv0 = 1.f / li0, iv1 = 1.f / li1;
    const int rA = wrow + qr_;
    #pragma unroll
    for (int nt = 0; nt < 8; nt++) {
        const int d = (nt << 3) + qc_;
        const float v0 = o[nt][0] * iv0, v1 = o[nt][1] * iv0;
        const float v2 = o[nt][2] * iv1, v3 = o[nt][3] * iv1;
        const size_t gA = ((size_t)(i0 + rA) * 8 + b) * 512 + n * 64 + d;
        const size_t gB = ((size_t)(i0 + rA + 8) * 8 + b) * 512 + n * 64 + d;
        const __nv_bfloat16 h0 = __float2bfloat16(v0), h1 = __float2bfloat16(v1);
        const __nv_bfloat16 h2 = __float2bfloat16(v2), h3 = __float2bfloat16(v3);
        *(__nv_bfloat162*)(vech + gA) = __halves2bfloat162(h0, h1);
        *(__nv_bfloat162*)(vecl + gA) = __halves2bfloat162(
            __float2bfloat16(v0 - __bfloat162float(h0)),
            __float2bfloat16(v1 - __bfloat162float(h1)));
        *(__nv_bfloat162*)(vech + gB) = __halves2bfloat162(h2, h3);
        *(__nv_bfloat162*)(vecl + gB) = __halves2bfloat162(
            __float2bfloat16(v2 - __bfloat162float(h2)),
            __float2bfloat16(v3 - __bfloat162float(h3)));
    }
}

// ===================== host orchestration ====================================
extern "C" void kernel_launch(void* const* d_in, const int* in_sizes, int n_in,
                              void* d_out, int out_size)
{
    (void)in_sizes; (void)n_in; (void)out_size;
    const float* dec_inp = (const float*)d_in[0];
    const float* r       = (const float*)d_in[1];
    const float* enc_out = (const float*)d_in[2];
    const float* rwb     = (const float*)d_in[3];
    const float* rrb     = (const float*)d_in[4];
    const float* qkv_w   = (const float*)d_in[5];
    const float* r_w     = (const float*)d_in[6];
    const float* o_w     = (const float*)d_in[7];
    const float* ln1_g   = (const float*)d_in[8];
    const float* ln1_b   = (const float*)d_in[9];
    const float* q_w     = (const float*)d_in[10];
    const float* kv_w    = (const float*)d_in[11];
    const float* o2_w    = (const float*)d_in[12];
    const float* ln2_g   = (const float*)d_in[13];
    const float* ln2_b   = (const float*)d_in[14];
    const float* ff_w1   = (const float*)d_in[15];
    const float* ff_b1   = (const float*)d_in[16];
    const float* ff_w2   = (const float*)d_in[17];
    const float* ff_b2   = (const float*)d_in[18];
    const float* ln3_g   = (const float*)d_in[19];
    const float* ln3_b   = (const float*)d_in[20];
    const unsigned char* emask = (const unsigned char*)d_in[22];
    float* out = (float*)d_out;

    float *out1, *h2, *out2, *qbias, *ccv;
    __nv_bfloat16 *wthi, *wtlo, *hh, *hl, *headsh, *headsl, *rh, *rl, *rkh, *rkl;
    __nv_bfloat16 *vth, *vtl, *vech, *vecl, *h2h, *h2l, *q2h, *q2l, *eh, *el;
    __nv_bfloat16 *kvh, *kvl, *vt2h, *vt2l, *vec2h, *vec2l, *th, *tl;
    cudaGetSymbolAddress((void**)&out1,  g_out1);
    cudaGetSymbolAddress((void**)&h2,    g_h2);
    cudaGetSymbolAddress((void**)&out2,  g_out2);
    cudaGetSymbolAddress((void**)&qbias, g_qbias);
    cudaGetSymbolAddress((void**)&ccv,   g_cc);
    cudaGetSymbolAddress((void**)&wthi,  g_wthi);
    cudaGetSymbolAddress((void**)&wtlo,  g_wtlo);
    cudaGetSymbolAddress((void**)&hh,    g_hh);
    cudaGetSymbolAddress((void**)&hl,    g_hl);
    cudaGetSymbolAddress((void**)&headsh,g_headsh);
    cudaGetSymbolAddress((void**)&headsl,g_headsl);
    cudaGetSymbolAddress((void**)&rh,    g_rh);
    cudaGetSymbolAddress((void**)&rl,    g_rl);
    cudaGetSymbolAddress((void**)&rkh,   g_rkh);
    cudaGetSymbolAddress((void**)&rkl,   g_rkl);
    cudaGetSymbolAddress((void**)&vth,   g_vth);
    cudaGetSymbolAddress((void**)&vtl,   g_vtl);
    cudaGetSymbolAddress((void**)&vech,  g_vech);
    cudaGetSymbolAddress((void**)&vecl,  g_vecl);
    cudaGetSymbolAddress((void**)&h2h,   g_h2h);
    cudaGetSymbolAddress((void**)&h2l,   g_h2l);
    cudaGetSymbolAddress((void**)&q2h,   g_q2h);
    cudaGetSymbolAddress((void**)&q2l,   g_q2l);
    cudaGetSymbolAddress((void**)&eh,    g_eh);
    cudaGetSymbolAddress((void**)&el,    g_el);
    cudaGetSymbolAddress((void**)&kvh,   g_kvh);
    cudaGetSymbolAddress((void**)&kvl,   g_kvl);
    cudaGetSymbolAddress((void**)&vt2h,  g_vt2h);
    cudaGetSymbolAddress((void**)&vt2l,  g_vt2l);
    cudaGetSymbolAddress((void**)&vec2h, g_vec2h);
    cudaGetSymbolAddress((void**)&vec2l, g_vec2l);
    cudaGetSymbolAddress((void**)&th,    g_th);
    cudaGetSymbolAddress((void**)&tl,    g_tl);

    cudaFuncSetAttribute(flash_rel_mma, cudaFuncAttributeMaxDynamicSharedMemorySize, REL_SMEM);
    cudaFuncSetAttribute(flash_ctx_mma, cudaFuncAttributeMaxDynamicSharedMemorySize, CTX_SMEM);
    cudaFuncSetAttribute(gemm_hmma<false, false>, cudaFuncAttributeMaxDynamicSharedMemorySize, GP_SMEM);
    cudaFuncSetAttribute(gemm_hmma<false, true>,  cudaFuncAttributeMaxDynamicSharedMemorySize, GP_SMEM);
    cudaFuncSetAttribute(gemm_hmma<true, true>,   cudaFuncAttributeMaxDynamicSharedMemorySize, GP_SMEM);

    // ---- two-stream fork/join (graph-capture-legal pattern) ----
    cudaStream_t s1;
    cudaStreamCreateWithFlags(&s1, cudaStreamNonBlocking);
    cudaEvent_t e0, eP, eW, eC, eKV;
    cudaEventCreateWithFlags(&e0,  cudaEventDisableTiming);
    cudaEventCreateWithFlags(&eP,  cudaEventDisableTiming);
    cudaEventCreateWithFlags(&eW,  cudaEventDisableTiming);
    cudaEventCreateWithFlags(&eC,  cudaEventDisableTiming);
    cudaEventCreateWithFlags(&eKV, cudaEventDisableTiming);

    cudaEventRecord(e0, 0);
    cudaStreamWaitEvent(s1, e0, 0);

    // stream 0: weight prep
    tsplit_all<<<4352, 256>>>(qkv_w, r_w, o_w, q_w, kv_w, o2_w, ff_w1, ff_w2,
                              wthi, wtlo);
    qbias_k<<<6, 256>>>(rwb, qbias);
    cudaEventRecord(eW, 0);

    // stream 1: activation prep
    ln_k<false, true><<<ROWS, 128, 0, s1>>>(dec_inp, ln1_g, ln1_b, nullptr, hh, hl);
    split_k<<<QLEN * DMODEL / 1024, 256, 0, s1>>>(r, rh, rl, QLEN * DMODEL / 4);
    split_k<<<ROWS * DMODEL / 1024, 256, 0, s1>>>(enc_out, eh, el, ROWS * DMODEL / 4);
    cudaEventRecord(eP, s1);

    // stream 0 spine: qkv -> vtrans1
    cudaStreamWaitEvent(0, eP, 0);
    gemm_hmma<false, true><<<dim3(12, 64), 256, GP_SMEM>>>(
        hh, hl, wthi + WT_QKV, wtlo + WT_QKV, qbias, nullptr,
        nullptr, headsh, headsl, ROWS, 1536, 512);
    vtrans_k<<<dim3(32, 64), 256>>>(headsh, headsl, vth, vtl, 1536, 1024);

    // stream 1 branch: rk -> c_k, then kv -> vtrans2 (overlaps flash_rel)
    cudaStreamWaitEvent(s1, eW, 0);
    gemm_hmma<false, true><<<dim3(4, 8), 256, GP_SMEM, s1>>>(
        rh, rl, wthi + WT_RW, wtlo + WT_RW, nullptr, nullptr,
        nullptr, rkh, rkl, QLEN, 512, 512);
    c_k<<<1024, 256, 0, s1>>>(rkh, rkl, rwb, rrb, ccv);
    cudaEventRecord(eC, s1);
    gemm_hmma<false, true><<<dim3(8, 64), 256, GP_SMEM, s1>>>(
        eh, el, wthi + WT_KVW, wtlo + WT_KVW, nullptr, nullptr,
        nullptr, kvh, kvl, ROWS, 1024, 512);
    vtrans_k<<<dim3(32, 64), 256, 0, s1>>>(kvh, kvl, vt2h, vt2l, 1024, 512);
    cudaEventRecord(eKV, s1);

    // stream 0: block 1 tail + block 2 head
    cudaStreamWaitEvent(0, eC, 0);
    flash_rel_mma<<<dim3(16, 64), 256, REL_SMEM>>>(headsh, headsl, vth, vtl,
                                                   rkh, rkl, ccv, vech, vecl);
    gemm_hmma<false, false><<<dim3(4, 64), 256, GP_SMEM>>>(
        vech, vecl, wthi + WT_OW, wtlo + WT_OW, nullptr, dec_inp,
        out1, nullptr, nullptr, ROWS, 512, 512);
    ln_k<true, true><<<ROWS, 128>>>(out1, ln2_g, ln2_b, h2, h2h, h2l);
    gemm_hmma<false, true><<<dim3(4, 64), 256, GP_SMEM>>>(
        h2h, h2l, wthi + WT_QW, wtlo + WT_QW, nullptr, nullptr,
        nullptr, q2h, q2l, ROWS, 512, 512);

    // join: cross attention needs kv/vt2 from stream 1
    cudaStreamWaitEvent(0, eKV, 0);
    flash_ctx_mma<<<dim3(8, 64), 256, CTX_SMEM>>>(q2h, q2l, kvh, kvl, vt2h, vt2l,
                                                  emask, vec2h, vec2l);
    gemm_hmma<false, false><<<dim3(4, 64), 256, GP_SMEM>>>(
        vec2h, vec2l, wthi + WT_O2W, wtlo + WT_O2W, nullptr, h2,
        out2, nullptr, nullptr, ROWS, 512, 512);

    // ---- block 3: FF ----
    ln_k<false, true><<<ROWS, 128>>>(out2, ln3_g, ln3_b, nullptr, hh, hl);
    gemm_hmma<true, true><<<dim3(16, 64), 256, GP_SMEM>>>(
        hh, hl, wthi + WT_FF1, wtlo + WT_FF1, ff_b1, nullptr,
        nullptr, th, tl, ROWS, 2048, 512);
    gemm_hmma<false, false><<<dim3(4, 64), 256, GP_SMEM>>>(
        th, tl, wthi + WT_FF2, wtlo + WT_FF2, ff_b2, out2,
        out, nullptr, nullptr, ROWS, 512, 2048);

    // destroy only when NOT capturing (destroying mid-capture invalidates the graph)
    cudaStreamCaptureStatus st = cudaStreamCaptureStatusNone;
    cudaStreamIsCapturing(0, &st);
    if (st == cudaStreamCaptureStatusNone) {
        cudaStreamDestroy(s1);
        cudaEventDestroy(e0);
        cudaEventDestroy(eP);
        cudaEventDestroy(eW);
        cudaEventDestroy(eC);
        cudaEventDestroy(eKV);
    }
}

// round 13
// speedup vs baseline: 3.2109x; 1.0522x over previous
#include <cuda_runtime.h>
#include <cuda_bf16.h>
#include <cstdint>
#include <cstddef>

#define QLEN   1024
#define BATCH  8
#define DMODEL 512
#define NHEAD  8
#define DHEAD  64
#define DINNER 2048
#define ELEN   1024
#define ATT_SCALE 0.125f
#define ROWS (QLEN * BATCH)   /* 8192 */

// ===================== warp MMA helpers =====================================
__device__ __forceinline__ uint32_t smem_u32(const void* p) {
    uint32_t a;
    asm("{ .reg .u64 t; cvta.to.shared.u64 t, %1; cvt.u32.u64 %0, t; }"
        : "=r"(a) : "l"(p));
    return a;
}

__device__ __forceinline__ void ldsm4(uint32_t* r, uint32_t addr) {
    asm volatile("ldmatrix.sync.aligned.m8n8.x4.shared.b16 {%0,%1,%2,%3}, [%4];"
                 : "=r"(r[0]), "=r"(r[1]), "=r"(r[2]), "=r"(r[3]) : "r"(addr));
}

__device__ __forceinline__ void mma16816(float* d, const uint32_t* a, const uint32_t* b) {
    asm volatile(
        "mma.sync.aligned.m16n8k16.row.col.f32.bf16.bf16.f32 "
        "{%0,%1,%2,%3}, {%4,%5,%6,%7}, {%8,%9}, {%0,%1,%2,%3};"
        : "+f"(d[0]), "+f"(d[1]), "+f"(d[2]), "+f"(d[3])
        : "r"(a[0]), "r"(a[1]), "r"(a[2]), "r"(a[3]), "r"(b[0]), "r"(b[1]));
}

__device__ __forceinline__ void cpa16(uint32_t dst, const void* src) {
    asm volatile("cp.async.cg.shared.global [%0], [%1], 16;" :: "r"(dst), "l"(src));
}

// predicated: src_size 0 zero-fills the 16B destination
__device__ __forceinline__ void cpa16p(uint32_t dst, const void* src, int ok) {
    asm volatile("cp.async.cg.shared.global [%0], [%1], 16, %2;"
                 :: "r"(dst), "l"(src), "r"(ok ? 16 : 0));
}

__device__ __forceinline__ void barp(int id) {
    asm volatile("bar.sync %0, %1;" :: "r"(id), "r"(64) : "memory");
}

// nt=4 variant (32-col B), 144B stride
__device__ __forceinline__ void wgemm3_nt4(uint32_t Ah, uint32_t Al,
                                           uint32_t Bh, uint32_t Bl,
                                           uint32_t a_off, uint32_t b_off,
                                           float acc[4][4])
{
    #pragma unroll
    for (int ks = 0; ks < 4; ks++) {
        const uint32_t ra = (uint32_t)(ks << 5);
        uint32_t ah[4], al[4];
        ldsm4(ah, Ah + ra + a_off);
        ldsm4(al, Al + ra + a_off);
        #pragma unroll
        for (int np = 0; np < 2; np++) {
            uint32_t bh[4], bl[4];
            const uint32_t rb = (uint32_t)(np * 16 * 144 + (ks << 5));
            ldsm4(bh, Bh + rb + b_off);
            ldsm4(bl, Bl + rb + b_off);
            #pragma unroll
            for (int hf = 0; hf < 2; hf++) {
                float* d = acc[(np << 1) + hf];
                mma16816(d, ah, bh + (hf << 1));
                mma16816(d, ah, bl + (hf << 1));
                mma16816(d, al, bh + (hf << 1));
            }
        }
    }
}

__device__ __forceinline__ void split_store4(char* hi, char* lo, float4 v) {
    const __nv_bfloat16 h0 = __float2bfloat16(v.x), h1 = __float2bfloat16(v.y);
    const __nv_bfloat16 h2 = __float2bfloat16(v.z), h3 = __float2bfloat16(v.w);
    *(__nv_bfloat162*)(hi)     = __halves2bfloat162(h0, h1);
    *(__nv_bfloat162*)(hi + 4) = __halves2bfloat162(h2, h3);
    *(__nv_bfloat162*)(lo)     = __halves2bfloat162(
        __float2bfloat16(v.x - __bfloat162float(h0)),
        __float2bfloat16(v.y - __bfloat162float(h1)));
    *(__nv_bfloat162*)(lo + 4) = __halves2bfloat162(
        __float2bfloat16(v.z - __bfloat162float(h2)),
        __float2bfloat16(v.w - __bfloat162float(h3)));
}

// ===================== scratch ==============================================
__device__ float g_out1[ROWS * DMODEL];
__device__ float g_h2  [ROWS * DMODEL];
__device__ float g_out2[ROWS * DMODEL];
__device__ float g_qbias[3 * DMODEL];
__device__ float g_cc  [NHEAD * 1152];        // zero-init pad beyond 1024

__device__ __nv_bfloat16 g_hh[ROWS * DMODEL],    g_hl[ROWS * DMODEL];
__device__ __nv_bfloat16 g_headsh[ROWS * 1536],  g_headsl[ROWS * 1536];
__device__ __nv_bfloat16 g_rh[QLEN * DMODEL],    g_rl[QLEN * DMODEL];
__device__ __nv_bfloat16 g_rkh[QLEN * DMODEL],   g_rkl[QLEN * DMODEL];
__device__ __nv_bfloat16 g_vth[64 * 64 * QLEN],  g_vtl[64 * 64 * QLEN];
__device__ __nv_bfloat16 g_vech[ROWS * DMODEL],  g_vecl[ROWS * DMODEL];
__device__ __nv_bfloat16 g_h2h[ROWS * DMODEL],   g_h2l[ROWS * DMODEL];
__device__ __nv_bfloat16 g_q2h[ROWS * DMODEL],   g_q2l[ROWS * DMODEL];
__device__ __nv_bfloat16 g_eh[ROWS * DMODEL],    g_el[ROWS * DMODEL];
__device__ __nv_bfloat16 g_kvh[ROWS * 1024],     g_kvl[ROWS * 1024];
__device__ __nv_bfloat16 g_vt2h[64 * 64 * ELEN], g_vt2l[64 * 64 * ELEN];
__device__ __nv_bfloat16 g_vec2h[ROWS * DMODEL], g_vec2l[ROWS * DMODEL];
__device__ __nv_bfloat16 g_th[ROWS * DINNER],    g_tl[ROWS * DINNER];

#define WT_QKV 0
#define WT_RW  786432
#define WT_OW  1048576
#define WT_QW  1310720
#define WT_KVW 1572864
#define WT_O2W 2097152
#define WT_FF1 2359296
#define WT_FF2 3407872
#define WT_TOTAL 4456448
__device__ __nv_bfloat16 g_wthi[WT_TOTAL];
__device__ __nv_bfloat16 g_wtlo[WT_TOTAL];

// ===================== small prep kernels ===================================
__global__ __launch_bounds__(256) void split_k(const float* __restrict__ x,
                                               __nv_bfloat16* __restrict__ hi,
                                               __nv_bfloat16* __restrict__ lo, int n4)
{
    const int i = blockIdx.x * 256 + threadIdx.x;
    if (i >= n4) return;
    const float4 v = reinterpret_cast<const float4*>(x)[i];
    split_store4((char*)(hi + (size_t)i * 4), (char*)(lo + (size_t)i * 4), v);
}

// all 8 weight transposes+splits in one launch (linear block-range dispatch)
__global__ __launch_bounds__(256) void tsplit_all(
    const float* __restrict__ qkv, const float* __restrict__ rw,
    const float* __restrict__ ow,  const float* __restrict__ qw,
    const float* __restrict__ kvw, const float* __restrict__ o2w,
    const float* __restrict__ ff1, const float* __restrict__ ff2,
    __nv_bfloat16* __restrict__ hi, __nv_bfloat16* __restrict__ lo)
{
    int bid = blockIdx.x;
    const float* W; int K, N, gx; size_t off;
    if (bid < 768)                      { W = qkv; K = 512;  N = 1536; gx = 48; off = WT_QKV; }
    else if ((bid -= 768)  < 256)       { W = rw;  K = 512;  N = 512;  gx = 16; off = WT_RW;  }
    else if ((bid -= 256)  < 256)       { W = ow;  K = 512;  N = 512;  gx = 16; off = WT_OW;  }
    else if ((bid -= 256)  < 256)       { W = qw;  K = 512;  N = 512;  gx = 16; off = WT_QW;  }
    else if ((bid -= 256)  < 512)       { W = kvw; K = 512;  N = 1024; gx = 32; off = WT_KVW; }
    else if ((bid -= 512)  < 256)       { W = o2w; K = 512;  N = 512;  gx = 16; off = WT_O2W; }
    else if ((bid -= 256)  < 1024)      { W = ff1; K = 512;  N = 2048; gx = 64; off = WT_FF1; }
    else { bid -= 1024;                   W = ff2; K = 2048; N = 512;  gx = 16; off = WT_FF2; }

    __shared__ float t[32][33];
    const int n0 = (bid % gx) << 5, k0 = (bid / gx) << 5;
    const int x = threadIdx.x & 31, y = threadIdx.x >> 5;
    #pragma unroll
    for (int i = 0; i < 32; i += 8)
        t[y + i][x] = W[(size_t)(k0 + y + i) * N + n0 + x];
    __syncthreads();
    #pragma unroll
    for (int i = 0; i < 32; i += 8) {
        const float v = t[x][y + i];
        const size_t o = off + (size_t)(n0 + y + i) * K + k0 + x;
        const __nv_bfloat16 h = __float2bfloat16(v);
        hi[o] = h;
        lo[o] = __float2bfloat16(v - __bfloat162float(h));
    }
}

__global__ void qbias_k(const float* __restrict__ rwb, float* __restrict__ qb) {
    const int i = blockIdx.x * 256 + threadIdx.x;
    if (i < 1536) qb[i] = (i < 512) ? rwb[i] : 0.0f;
}

// c[n][u] = sum_d (rrb-rwb)[n][d] * rk[u][n*64+d]
__global__ __launch_bounds__(256) void c_k(const __nv_bfloat16* __restrict__ rkh,
                                           const __nv_bfloat16* __restrict__ rkl,
                                           const float* __restrict__ rwb,
                                           const float* __restrict__ rrb,
                                           float* __restrict__ cc)
{
    const int u = blockIdx.x;
    const int n = threadIdx.x >> 5, lane = threadIdx.x & 31;
    float s = 0.0f;
    #pragma unroll
    for (int k = 0; k < 2; k++) {
        const int d = lane + k * 32;
        const size_t g = (size_t)u * 512 + n * 64 + d;
        const float rv = __bfloat162float(rkh[g]) + __bfloat162float(rkl[g]);
        s += (rrb[n * 64 + d] - rwb[n * 64 + d]) * rv;
    }
    #pragma unroll
    for (int o = 16; o; o >>= 1) s += __shfl_xor_sync(0xffffffffu, s, o);
    if (lane == 0) cc[n * 1152 + u] = s;
}

// transpose V-part: src[(i*8+b)*stride + off + n*64 + d] -> dst[((b*8+n)*64+d)*1024 + i]
__global__ __launch_bounds__(256) void vtrans_k(const __nv_bfloat16* __restrict__ sh,
                                                const __nv_bfloat16* __restrict__ sl,
                                                __nv_bfloat16* __restrict__ dh,
                                                __nv_bfloat16* __restrict__ dl,
                                                int srcStride, int srcOff)
{
    __shared__ __nv_bfloat16 th[32][72], tl[32][72];
    const int i0 = blockIdx.x << 5;
    const int b = blockIdx.y >> 3, n = blockIdx.y & 7;
    const int t = threadIdx.x;
    {
        const int il = t >> 3, dj = (t & 7) << 3;
        const size_t g = ((size_t)(i0 + il) * 8 + b) * srcStride + srcOff + n * 64 + dj;
        *(uint4*)&th[il][dj] = *(const uint4*)(sh + g);
        *(uint4*)&tl[il][dj] = *(const uint4*)(sl + g);
    }
    __syncthreads();
    {
        const int dr = t >> 2, ij = (t & 3) << 3;
        __nv_bfloat16 oh[8], ol[8];
        #pragma unroll
        for (int k = 0; k < 8; k++) { oh[k] = th[ij + k][dr]; ol[k] = tl[ij + k][dr]; }
        const size_t g = ((size_t)(b * 8 + n) * 64 + dr) * 1024 + i0 + ij;
        *(uint4*)(dh + g) = *(uint4*)oh;
        *(uint4*)(dl + g) = *(uint4*)ol;
    }
}

// ===================== pipelined HMMA GEMM ==================================
// K-chunk 32, 2-stage cp.async double buffer. Tiles [128][40] bf16, 80B stride.
#define GP_STAGE 40960
#define GP_SMEM  81920

template <bool GELU, bool SPLIT>
__global__ __launch_bounds__(256, 2) void gemm_hmma(const __nv_bfloat16* __restrict__ Ahi,
                                                    const __nv_bfloat16* __restrict__ Alo,
                                                    const __nv_bfloat16* __restrict__ Bhi,
                                                    const __nv_bfloat16* __restrict__ Blo,
                                                    const float* __restrict__ bias,
                                                    const float* __restrict__ res,
                                                    float* __restrict__ C,
                                                    __nv_bfloat16* __restrict__ Ch,
                                                    __nv_bfloat16* __restrict__ Cl,
                                                    int M, int N, int K)
{
    extern __shared__ char smem[];
    const uint32_t sb = smem_u32(smem);
    const int tid = threadIdx.x;
    const int lane = tid & 31, wid = tid >> 5;
    const int m0 = blockIdx.y << 7, n0 = blockIdx.x << 7;
    const int wm = (wid & 3) << 5;
    const int wn = (wid >> 2) << 6;
    (void)M;

    float acc[2][8][4];
    #pragma unroll
    for (int mt = 0; mt < 2; mt++)
        #pragma unroll
        for (int nt = 0; nt < 8; nt++)
            #pragma unroll
            for (int e = 0; e < 4; e++) acc[mt][nt][e] = 0.0f;

    const int lr = lane & 7, lg = lane >> 3;
    const uint32_t a_off = (uint32_t)(((lg & 1) << 3) + lr) * 80u + (uint32_t)((lg >> 1) << 4);
    const uint32_t b_off = (uint32_t)(((lg >> 1) << 3) + lr) * 80u + (uint32_t)((lg & 1) << 4);

    const int nch = K >> 5;

    auto load_chunk = [&](int c, int s) {
        const int k0 = c << 5;
        const uint32_t sbase = sb + s * GP_STAGE;
        #pragma unroll
        for (int i = tid; i < 2048; i += 256) {
            const int tile = i >> 9;
            const int idx = i & 511;
            const int row = idx >> 2, kc = (idx & 3) << 3;
            const uint32_t dst = sbase + tile * 10240 + row * 80 + (idx & 3) * 16;
            const __nv_bfloat16* src;
            if (tile == 0)      src = Ahi + (size_t)(m0 + row) * K + k0 + kc;
            else if (tile == 1) src = Alo + (size_t)(m0 + row) * K + k0 + kc;
            else if (tile == 2) src = Bhi + (size_t)(n0 + row) * K + k0 + kc;
            else                src = Blo + (size_t)(n0 + row) * K + k0 + kc;
            cpa16(dst, src);
        }
        asm volatile("cp.async.commit_group;" ::: "memory");
    };

    load_chunk(0, 0);
    load_chunk(1, 1);

    for (int c = 0; c < nch; c++) {
        if (c + 1 < nch) asm volatile("cp.async.wait_group 1;" ::: "memory");
        else             asm volatile("cp.async.wait_group 0;" ::: "memory");
        __syncthreads();

        const uint32_t sbase = sb + (c & 1) * GP_STAGE;
        #pragma unroll
        for (int ks = 0; ks < 2; ks++) {
            const uint32_t kk2 = (uint32_t)(ks << 5);
            uint32_t ah[2][4], al[2][4];
            #pragma unroll
            for (int mt = 0; mt < 2; mt++) {
                const uint32_t ra = (uint32_t)((wm + (mt << 4)) * 80) + kk2 + a_off;
                ldsm4(ah[mt], sbase + ra);
                ldsm4(al[mt], sbase + 10240 + ra);
            }
            #pragma unroll
            for (int np = 0; np < 4; np++) {
                uint32_t bh[4], bl[4];
                const uint32_t rb = (uint32_t)((wn + (np << 4)) * 80) + kk2 + b_off;
                ldsm4(bh, sbase + 20480 + rb);
                ldsm4(bl, sbase + 30720 + rb);
                #pragma unroll
                for (int mt = 0; mt < 2; mt++) {
                    #pragma unroll
                    for (int hf = 0; hf < 2; hf++) {
                        float* d = acc[mt][(np << 1) + hf];
                        mma16816(d, ah[mt], bh + (hf << 1));
                        mma16816(d, ah[mt], bl + (hf << 1));
                        mma16816(d, al[mt], bh + (hf << 1));
                    }
                }
            }
        }
        __syncthreads();
        if (c + 2 < nch) load_chunk(c + 2, c & 1);
    }

    const int er = lane >> 2, ec = (lane & 3) << 1;
    #pragma unroll
    for (int mt = 0; mt < 2; mt++) {
        #pragma unroll
        for (int half = 0; half < 2; half++) {
            const int gr = m0 + wm + (mt << 4) + er + (half << 3);
            #pragma unroll
            for (int nt = 0; nt < 8; nt++) {
                const int gc = n0 + wn + (nt << 3) + ec;
                float v0 = acc[mt][nt][(half << 1) + 0];
                float v1 = acc[mt][nt][(half << 1) + 1];
                if (bias) { v0 += bias[gc]; v1 += bias[gc + 1]; }
                if (GELU) {
                    v0 = 0.5f * v0 * (1.0f + erff(v0 * 0.70710678118654752f));
                    v1 = 0.5f * v1 * (1.0f + erff(v1 * 0.70710678118654752f));
                }
                if (SPLIT) {
                    const __nv_bfloat16 h0 = __float2bfloat16(v0), h1 = __float2bfloat16(v1);
                    *(__nv_bfloat162*)(Ch + (size_t)gr * N + gc) = __halves2bfloat162(h0, h1);
                    *(__nv_bfloat162*)(Cl + (size_t)gr * N + gc) = __halves2bfloat162(
                        __float2bfloat16(v0 - __bfloat162float(h0)),
                        __float2bfloat16(v1 - __bfloat162float(h1)));
                } else {
                    if (res) {
                        const float2 rr = *reinterpret_cast<const float2*>(&res[(size_t)gr * N + gc]);
                        v0 += rr.x; v1 += rr.y;
                    }
                    *reinterpret_cast<float2*>(&C[(size_t)gr * N + gc]) = make_float2(v0, v1);
                }
            }
        }
    }
}

// ===================== LayerNorm ============================================
template <bool F32O, bool SPL>
__global__ __launch_bounds__(128) void ln_k(const float* __restrict__ x,
                                            const float* __restrict__ g,
                                            const float* __restrict__ b,
                                            float* __restrict__ yf,
                                            __nv_bfloat16* __restrict__ yh,
                                            __nv_bfloat16* __restrict__ yl)
{
    const int row = blockIdx.x;
    const int t = threadIdx.x;
    const float4 v = reinterpret_cast<const float4*>(x + (size_t)row * DMODEL)[t];
    float s  = v.x + v.y + v.z + v.w;
    float sq = v.x*v.x + v.y*v.y + v.z*v.z + v.w*v.w;
    #pragma unroll
    for (int o = 16; o; o >>= 1) {
        s  += __shfl_xor_sync(0xffffffffu, s,  o);
        sq += __shfl_xor_sync(0xffffffffu, sq, o);
    }
    __shared__ float ss[4], sqq[4];
    const int w = t >> 5, lane = t & 31;
    if (lane == 0) { ss[w] = s; sqq[w] = sq; }
    __syncthreads();
    s  = ss[0]  + ss[1]  + ss[2]  + ss[3];
    sq = sqq[0] + sqq[1] + sqq[2] + sqq[3];
    const float mean = s * (1.0f / DMODEL);
    const float var  = sq * (1.0f / DMODEL) - mean * mean;
    const float rstd = rsqrtf(var + 1e-5f);
    const float4 gg = reinterpret_cast<const float4*>(g)[t];
    const float4 bb = reinterpret_cast<const float4*>(b)[t];
    float4 o4;
    o4.x = (v.x - mean) * rstd * gg.x + bb.x;
    o4.y = (v.y - mean) * rstd * gg.y + bb.y;
    o4.z = (v.z - mean) * rstd * gg.z + bb.z;
    o4.w = (v.w - mean) * rstd * gg.w + bb.w;
    if (F32O) reinterpret_cast<float4*>(yf + (size_t)row * DMODEL)[t] = o4;
    if (SPL)  split_store4((char*)(yh + (size_t)row * DMODEL + t * 4),
                           (char*)(yl + (size_t)row * DMODEL + t * 4), o4);
}

// ===== flash attention 1 (rel, causal), 256 thr, cp.async 2-stage K/V =======
// grid (64, 16): blockIdx.x = b*8+n, blockIdx.y reversed i-tile (LPT order)
#define R_QH   0
#define R_QL   9216
#define R_KS0  18432     /* stage s: +s*18432; KH +0, KL +9216 */
#define R_VS0  55296
#define R_PH   92160
#define R_PL   101376
#define R_RH   110592
#define R_RL   129024
#define R_G    147456
#define R_C    181248    /* 2 x 64 floats */
#define R_PM   181760
#define R_PS   182272
#define REL_SMEM 182784

__global__ __launch_bounds__(256) void flash_rel_mma(
    const __nv_bfloat16* __restrict__ hh, const __nv_bfloat16* __restrict__ hl,
    const __nv_bfloat16* __restrict__ vth, const __nv_bfloat16* __restrict__ vtl,
    const __nv_bfloat16* __restrict__ rkh, const __nv_bfloat16* __restrict__ rkl,
    const float* __restrict__ cc,
    __nv_bfloat16* __restrict__ vech, __nv_bfloat16* __restrict__ vecl)
{
    extern __shared__ char sm[];
    const uint32_t sb = smem_u32(sm);
    const int tid = threadIdx.x, lane = tid & 31, wid = tid >> 5;
    const int p = wid >> 1, h = wid & 1;
    const int i0 = (15 - (int)blockIdx.y) << 6;           // LPT: longest first
    const int b = blockIdx.x >> 3, n = blockIdx.x & 7;
    const int lr = lane & 7, lg = lane >> 3;
    const uint32_t a_off = (uint32_t)(((lg & 1) << 3) + lr) * 144u + (uint32_t)((lg >> 1) << 4);
    const uint32_t b_off = (uint32_t)(((lg >> 1) << 3) + lr) * 144u + (uint32_t)((lg & 1) << 4);
    const int qr_ = lane >> 2, qc_ = (lane & 3) << 1;
    float* G    = (float*)(sm + R_G);
    float* csm  = (float*)(sm + R_C);
    float* pmax = (float*)(sm + R_PM);
    float* psum = (float*)(sm + R_PS);
    const uint32_t AqH = sb + R_QH + p * 16 * 144, AqL = sb + R_QL + p * 16 * 144;
    const uint32_t ApH = sb + R_PH + p * 16 * 144, ApL = sb + R_PL + p * 16 * 144;
    const int ustart = 960 - i0;
    const int nit = (i0 >> 6) + 1;

    auto load_iter = [&](int k, int s) {
        const int j0k = k << 6;
        const uint32_t Ks = sb + R_KS0 + s * 18432;
        const uint32_t Vs = sb + R_VS0 + s * 18432;
        const int ub = ustart + ((k + 1) << 6);
        #pragma unroll 2
        for (int i = tid; i < 512; i += 256) {
            const int row = i >> 3, ch = i & 7;
            const size_t gk = ((size_t)(j0k + row) * 8 + b) * 1536 + 512 + n * 64 + ch * 8;
            cpa16(Ks + row * 144 + ch * 16, hh + gk);
            cpa16(Ks + 9216 + row * 144 + ch * 16, hl + gk);
            const size_t gv = ((size_t)(b * 8 + n) * 64 + row) * 1024 + j0k + ch * 8;
            cpa16(Vs + row * 144 + ch * 16, vth + gv);
            cpa16(Vs + 9216 + row * 144 + ch * 16, vtl + gv);
            const int u = ub + row;
            const int slot = u & 127;
            const int ok = (u < QLEN);
            const size_t gr = (size_t)(ok ? u : 0) * 512 + n * 64 + ch * 8;
            cpa16p(sb + R_RH + slot * 144 + ch * 16, rkh + gr, ok);
            cpa16p(sb + R_RL + slot * 144 + ch * 16, rkl + gr, ok);
        }
        if (tid < 64) csm[s * 64 + tid] = cc[n * 1152 + ub + tid];
        asm volatile("cp.async.commit_group;" ::: "memory");
    };

    for (int t = tid; t < 512; t += 256) {
        const int row = t >> 3, c4 = t & 7;
        const size_t g = ((size_t)(i0 + row) * 8 + b) * 1536 + n * 64 + c4 * 8;
        *(uint4*)(sm + R_QH + row * 144 + c4 * 16) = *(const uint4*)(hh + g);
        *(uint4*)(sm + R_QL + row * 144 + c4 * 16) = *(const uint4*)(hl + g);
    }
    for (int t = tid; t < 512; t += 256) {
        const int jr = t >> 3, c4 = t & 7;
        const int u = ustart + jr, slot = u & 127;
        uint4 vh = make_uint4(0, 0, 0, 0), vl = make_uint4(0, 0, 0, 0);
        if (u < QLEN) {
            const size_t g = (size_t)u * 512 + n * 64 + c4 * 8;
            vh = *(const uint4*)(rkh + g);
            vl = *(const uint4*)(rkl + g);
        }
        *(uint4*)(sm + R_RH + slot * 144 + c4 * 16) = vh;
        *(uint4*)(sm + R_RL + slot * 144 + c4 * 16) = vl;
    }
    if (tid < 64) csm[64 + tid] = cc[n * 1152 + ustart + tid];
    load_iter(0, 0);
    __syncthreads();

    {
        const int slotb = ustart & 127;
        float g4[4][4];
        #pragma unroll
        for (int nt = 0; nt < 4; nt++) { g4[nt][0]=0; g4[nt][1]=0; g4[nt][2]=0; g4[nt][3]=0; }
        wgemm3_nt4(AqH, AqL, sb + R_RH + (slotb + h * 32) * 144,
                   sb + R_RL + (slotb + h * 32) * 144, a_off, b_off, g4);
        #pragma unroll
        for (int nt = 0; nt < 4; nt++) {
            const int cl = h * 32 + (nt << 3) + qc_;
            const int col = slotb + cl;
            const float c0 = csm[64 + cl], c1 = csm[64 + cl + 1];
            *(float2*)&G[(16 * p + qr_) * 132 + col]     = make_float2(g4[nt][0] + c0, g4[nt][1] + c1);
            *(float2*)&G[(16 * p + qr_ + 8) * 132 + col] = make_float2(g4[nt][2] + c0, g4[nt][3] + c1);
        }
    }
    __syncthreads();

    float m0 = -1e30f, m1 = -1e30f, li0 = 0.f, li1 = 0.f;
    float o[4][4];
    #pragma unroll
    for (int nt = 0; nt < 4; nt++) { o[nt][0]=0; o[nt][1]=0; o[nt][2]=0; o[nt][3]=0; }

    for (int k = 0; k < nit; k++) {
        const int j0 = k << 6;
        if (k + 1 < nit) {
            load_iter(k + 1, (k + 1) & 1);
            asm volatile("cp.async.wait_group 1;" ::: "memory");
        } else {
            asm volatile("cp.async.wait_group 0;" ::: "memory");
        }
        __syncthreads();
        const uint32_t Ks = sb + R_KS0 + (k & 1) * 18432;
        const uint32_t Vs = sb + R_VS0 + (k & 1) * 18432;
        const float* csmb = csm + (k & 1) * 64;

        {
            const int slotb = (ustart + ((k + 1) << 6)) & 127;
            float g4[4][4];
            #pragma unroll
            for (int nt = 0; nt < 4; nt++) { g4[nt][0]=0; g4[nt][1]=0; g4[nt][2]=0; g4[nt][3]=0; }
            wgemm3_nt4(AqH, AqL, sb + R_RH + (slotb + h * 32) * 144,
                       sb + R_RL + (slotb + h * 32) * 144, a_off, b_off, g4);
            #pragma unroll
            for (int nt = 0; nt < 4; nt++) {
                const int cl = h * 32 + (nt << 3) + qc_;
                const int col = slotb + cl;
                const float c0 = csmb[cl], c1 = csmb[cl + 1];
                *(float2*)&G[(16 * p + qr_) * 132 + col]     = make_float2(g4[nt][0] + c0, g4[nt][1] + c1);
                *(float2*)&G[(16 * p + qr_ + 8) * 132 + col] = make_float2(g4[nt][2] + c0, g4[nt][3] + c1);
            }
        }
        float s[4][4];
        #pragma unroll
        for (int nt = 0; nt < 4; nt++) { s[nt][0]=0; s[nt][1]=0; s[nt][2]=0; s[nt][3]=0; }
        wgemm3_nt4(AqH, AqL, Ks + h * 32 * 144, Ks + 9216 + h * 32 * 144,
                   a_off, b_off, s);
        barp(1 + p);
        const int cb = 1023 + j0 - i0;
        const int rA = 16 * p + qr_, rB = rA + 8;
        float rmax0 = -1e30f, rmax1 = -1e30f;
        #pragma unroll
        for (int nt = 0; nt < 4; nt++) {
            const int col = h * 32 + (nt << 3) + qc_;
            s[nt][0] = (s[nt][0] + G[rA * 132 + ((cb + col - rA) & 127)]) * ATT_SCALE;
            s[nt][1] = (s[nt][1] + G[rA * 132 + ((cb + col + 1 - rA) & 127)]) * ATT_SCALE;
            s[nt][2] = (s[nt][2] + G[rB * 132 + ((cb + col - rB) & 127)]) * ATT_SCALE;
            s[nt][3] = (s[nt][3] + G[rB * 132 + ((cb + col + 1 - rB) & 127)]) * ATT_SCALE;
            if (j0 == i0) {
                if (col > rA)     s[nt][0] = -1e30f;
                if (col + 1 > rA) s[nt][1] = -1e30f;
                if (col > rB)     s[nt][2] = -1e30f;
                if (col + 1 > rB) s[nt][3] = -1e30f;
            }
            rmax0 = fmaxf(rmax0, fmaxf(s[nt][0], s[nt][1]));
            rmax1 = fmaxf(rmax1, fmaxf(s[nt][2], s[nt][3]));
        }
        rmax0 = fmaxf(rmax0, __shfl_xor_sync(0xffffffffu, rmax0, 1));
        rmax0 = fmaxf(rmax0, __shfl_xor_sync(0xffffffffu, rmax0, 2));
        rmax1 = fmaxf(rmax1, __shfl_xor_sync(0xffffffffu, rmax1, 1));
        rmax1 = fmaxf(rmax1, __shfl_xor_sync(0xffffffffu, rmax1, 2));
        if ((lane & 3) == 0) {
            pmax[p * 32 + h * 16 + qr_]     = rmax0;
            pmax[p * 32 + h * 16 + qr_ + 8] = rmax1;
        }
        barp(1 + p);
        rmax0 = fmaxf(rmax0, pmax[p * 32 + (1 - h) * 16 + qr_]);
        rmax1 = fmaxf(rmax1, pmax[p * 32 + (1 - h) * 16 + qr_ + 8]);
        const float mn0 = fmaxf(m0, rmax0), mn1 = fmaxf(m1, rmax1);
        const float al0 = __expf(m0 - mn0), al1 = __expf(m1 - mn1);
        float rs0 = 0.f, rs1 = 0.f;
        #pragma unroll
        for (int nt = 0; nt < 4; nt++) {
            const int col = h * 32 + (nt << 3) + qc_;
            const float p0 = __expf(s[nt][0] - mn0), p1 = __expf(s[nt][1] - mn0);
            const float p2 = __expf(s[nt][2] - mn1), p3 = __expf(s[nt][3] - mn1);
            rs0 += p0 + p1; rs1 += p2 + p3;
            const __nv_bfloat16 h0 = __float2bfloat16(p0), h1 = __float2bfloat16(p1);
            const __nv_bfloat16 h2 = __float2bfloat16(p2), h3 = __float2bfloat16(p3);
            *(__nv_bfloat162*)(sm + R_PH + rA * 144 + col * 2) = __halves2bfloat162(h0, h1);
            *(__nv_bfloat162*)(sm + R_PL + rA * 144 + col * 2) = __halves2bfloat162(
                __float2bfloat16(p0 - __bfloat162float(h0)),
                __float2bfloat16(p1 - __bfloat162float(h1)));
            *(__nv_bfloat162*)(sm + R_PH + rB * 144 + col * 2) = __halves2bfloat162(h2, h3);
            *(__nv_bfloat162*)(sm + R_PL + rB * 144 + col * 2) = __halves2bfloat162(
                __float2bfloat16(p2 - __bfloat162float(h2)),
                __float2bfloat16(p3 - __bfloat162float(h3)));
            o[nt][0] *= al0; o[nt][1] *= al0; o[nt][2] *= al1; o[nt][3] *= al1;
        }
        rs0 += __shfl_xor_sync(0xffffffffu, rs0, 1);
        rs0 += __shfl_xor_sync(0xffffffffu, rs0, 2);
        rs1 += __shfl_xor_sync(0xffffffffu, rs1, 1);
        rs1 += __shfl_xor_sync(0xffffffffu, rs1, 2);
        if ((lane & 3) == 0) {
            psum[p * 32 + h * 16 + qr_]     = rs0;
            psum[p * 32 + h * 16 + qr_ + 8] = rs1;
        }
        barp(1 + p);
        rs0 += psum[p * 32 + (1 - h) * 16 + qr_];
        rs1 += psum[p * 32 + (1 - h) * 16 + qr_ + 8];
        li0 = li0 * al0 + rs0; li1 = li1 * al1 + rs1;
        m0 = mn0; m1 = mn1;
        wgemm3_nt4(ApH, ApL, Vs + h * 32 * 144, Vs + 9216 + h * 32 * 144,
                   a_off, b_off, o);
        __syncthreads();
    }

    const float iv0 = 1.f / li0, iv1 = 1.f / li1;
    const int rA = 16 * p + qr_;
    #pragma unroll
    for (int nt = 0; nt < 4; nt++) {
        const int d = h * 32 + (nt << 3) + qc_;
        const float v0 = o[nt][0] * iv0, v1 = o[nt][1] * iv0;
        const float v2 = o[nt][2] * iv1, v3 = o[nt][3] * iv1;
        const size_t gA = ((size_t)(i0 + rA) * 8 + b) * 512 + n * 64 + d;
        const size_t gB = ((size_t)(i0 + rA + 8) * 8 + b) * 512 + n * 64 + d;
        const __nv_bfloat16 h0 = __float2bfloat16(v0), h1 = __float2bfloat16(v1);
        const __nv_bfloat16 h2 = __float2bfloat16(v2), h3 = __float2bfloat16(v3);
        *(__nv_bfloat162*)(vech + gA) = __halves2bfloat162(h0, h1);
        *(__nv_bfloat162*)(vecl + gA) = __halves2bfloat162(
            __float2bfloat16(v0 - __bfloat162float(h0)),
            __float2bfloat16(v1 - __bfloat162float(h1)));
        *(__nv_bfloat162*)(vech + gB) = __halves2bfloat162(h2, h3);
        *(__nv_bfloat162*)(vecl + gB) = __halves2bfloat162(
            __float2bfloat16(v2 - __bfloat162float(h2)),
            __float2bfloat16(v3 - __bfloat162float(h3)));
    }
}

// ===== flash attention 2 (cross), 256 thr, 64-row Q tile, 2 CTAs/SM =========
#define C_QH   0
#define C_QL   9216
#define C_KS0  18432     /* stage s: +s*18432; KH +0, KL +9216 */
#define C_VS0  55296
#define C_PH   92160
#define C_PL   101376
#define C_PM   110592    /* 512B */
#define C_PS   111104    /* 512B */
#define C_FL0  111616    /* 2 x 64 bytes */
#define CTX_SMEM 111744

__global__ __launch_bounds__(256, 2) void flash_ctx_mma(
    const __nv_bfloat16* __restrict__ qh, const __nv_bfloat16* __restrict__ ql,
    const __nv_bfloat16* __restrict__ kvh, const __nv_bfloat16* __restrict__ kvl,
    const __nv_bfloat16* __restrict__ vth, const __nv_bfloat16* __restrict__ vtl,
    const unsigned char* __restrict__ emask,
    __nv_bfloat16* __restrict__ vech, __nv_bfloat16* __restrict__ vecl)
{
    extern __shared__ char sm[];
    const uint32_t sb = smem_u32(sm);
    const int tid = threadIdx.x, lane = tid & 31, wid = tid >> 5;
    const int p = wid >> 1, h = wid & 1;
    const int i0 = blockIdx.x << 6;
    const int b = blockIdx.y >> 3, n = blockIdx.y & 7;
    const int lr = lane & 7, lg = lane >> 3;
    const uint32_t a_off = (uint32_t)(((lg & 1) << 3) + lr) * 144u + (uint32_t)((lg >> 1) << 4);
    const uint32_t b_off = (uint32_t)(((lg >> 1) << 3) + lr) * 144u + (uint32_t)((lg & 1) << 4);
    const int qr_ = lane >> 2, qc_ = (lane & 3) << 1;
    float* pmax = (float*)(sm + C_PM);
    float* psum = (float*)(sm + C_PS);
    const uint32_t AqH = sb + C_QH + p * 16 * 144, AqL = sb + C_QL + p * 16 * 144;
    const uint32_t ApH = sb + C_PH + p * 16 * 144, ApL = sb + C_PL + p * 16 * 144;
    const int nit = ELEN >> 6;

    auto load_iter = [&](int k, int s) {
        const int j0k = k << 6;
        const uint32_t Ks = sb + C_KS0 + s * 18432;
        const uint32_t Vs = sb + C_VS0 + s * 18432;
        #pragma unroll 2
        for (int i = tid; i < 512; i += 256) {
            const int row = i >> 3, ch = i & 7;
            const size_t gk = ((size_t)(j0k + row) * 8 + b) * 1024 + n * 64 + ch * 8;
            cpa16(Ks + row * 144 + ch * 16, kvh + gk);
            cpa16(Ks + 9216 + row * 144 + ch * 16, kvl + gk);
            const size_t gv = ((size_t)(b * 8 + n) * 64 + row) * 1024 + j0k + ch * 8;
            cpa16(Vs + row * 144 + ch * 16, vth + gv);
            cpa16(Vs + 9216 + row * 144 + ch * 16, vtl + gv);
        }
        if (tid < 64) sm[C_FL0 + s * 64 + tid] = (char)emask[(size_t)(j0k + tid) * 8 + b];
        asm volatile("cp.async.commit_group;" ::: "memory");
    };

    for (int t = tid; t < 512; t += 256) {
        const int row = t >> 3, c4 = t & 7;
        const size_t g = ((size_t)(i0 + row) * 8 + b) * 512 + n * 64 + c4 * 8;
        *(uint4*)(sm + C_QH + row * 144 + c4 * 16) = *(const uint4*)(qh + g);
        *(uint4*)(sm + C_QL + row * 144 + c4 * 16) = *(const uint4*)(ql + g);
    }
    load_iter(0, 0);

    float m0 = -1e30f, m1 = -1e30f, li0 = 0.f, li1 = 0.f;
    float o[4][4];
    #pragma unroll
    for (int nt = 0; nt < 4; nt++) { o[nt][0]=0; o[nt][1]=0; o[nt][2]=0; o[nt][3]=0; }

    for (int k = 0; k < nit; k++) {
        if (k + 1 < nit) {
            load_iter(k + 1, (k + 1) & 1);
            asm volatile("cp.async.wait_group 1;" ::: "memory");
        } else {
            asm volatile("cp.async.wait_group 0;" ::: "memory");
        }
        __syncthreads();
        const uint32_t Ks = sb + C_KS0 + (k & 1) * 18432;
        const uint32_t Vs = sb + C_VS0 + (k & 1) * 18432;
        const int fl = C_FL0 + (k & 1) * 64;

        // QK: this warp handles j-cols [h*32, h*32+32)
        float s[4][4];
        #pragma unroll
        for (int nt = 0; nt < 4; nt++) { s[nt][0]=0; s[nt][1]=0; s[nt][2]=0; s[nt][3]=0; }
        wgemm3_nt4(AqH, AqL, Ks + h * 32 * 144, Ks + 9216 + h * 32 * 144,
                   a_off, b_off, s);

        const int rA = 16 * p + qr_, rB = rA + 8;
        float rmax0 = -1e30f, rmax1 = -1e30f;
        #pragma unroll
        for (int nt = 0; nt < 4; nt++) {
            const int col = h * 32 + (nt << 3) + qc_;
            const bool f0 = sm[fl + col] != 0, f1 = sm[fl + col + 1] != 0;
            s[nt][0] = f0 ? -1e4f : s[nt][0] * ATT_SCALE;
            s[nt][1] = f1 ? -1e4f : s[nt][1] * ATT_SCALE;
            s[nt][2] = f0 ? -1e4f : s[nt][2] * ATT_SCALE;
            s[nt][3] = f1 ? -1e4f : s[nt][3] * ATT_SCALE;
            rmax0 = fmaxf(rmax0, fmaxf(s[nt][0], s[nt][1]));
            rmax1 = fmaxf(rmax1, fmaxf(s[nt][2], s[nt][3]));
        }
        rmax0 = fmaxf(rmax0, __shfl_xor_sync(0xffffffffu, rmax0, 1));
        rmax0 = fmaxf(rmax0, __shfl_xor_sync(0xffffffffu, rmax0, 2));
        rmax1 = fmaxf(rmax1, __shfl_xor_sync(0xffffffffu, rmax1, 1));
        rmax1 = fmaxf(rmax1, __shfl_xor_sync(0xffffffffu, rmax1, 2));
        if ((lane & 3) == 0) {
            pmax[p * 32 + h * 16 + qr_]     = rmax0;
            pmax[p * 32 + h * 16 + qr_ + 8] = rmax1;
        }
        barp(1 + p);
        rmax0 = fmaxf(rmax0, pmax[p * 32 + (1 - h) * 16 + qr_]);
        rmax1 = fmaxf(rmax1, pmax[p * 32 + (1 - h) * 16 + qr_ + 8]);
        const float mn0 = fmaxf(m0, rmax0), mn1 = fmaxf(m1, rmax1);
        const float al0 = __expf(m0 - mn0), al1 = __expf(m1 - mn1);
        float rs0 = 0.f, rs1 = 0.f;
        #pragma unroll
        for (int nt = 0; nt < 4; nt++) {
            const int col = h * 32 + (nt << 3) + qc_;
            const float p0 = __expf(s[nt][0] - mn0), p1 = __expf(s[nt][1] - mn0);
            const float p2 = __expf(s[nt][2] - mn1), p3 = __expf(s[nt][3] - mn1);
            rs0 += p0 + p1; rs1 += p2 + p3;
            const __nv_bfloat16 h0 = __float2bfloat16(p0), h1 = __float2bfloat16(p1);
            const __nv_bfloat16 h2 = __float2bfloat16(p2), h3 = __float2bfloat16(p3);
            *(__nv_bfloat162*)(sm + C_PH + rA * 144 + col * 2) = __halves2bfloat162(h0, h1);
            *(__nv_bfloat162*)(sm + C_PL + rA * 144 + col * 2) = __halves2bfloat162(
                __float2bfloat16(p0 - __bfloat162float(h0)),
                __float2bfloat16(p1 - __bfloat162float(h1)));
            *(__nv_bfloat162*)(sm + C_PH + rB * 144 + col * 2) = __halves2bfloat162(h2, h3);
            *(__nv_bfloat162*)(sm + C_PL + rB * 144 + col * 2) = __halves2bfloat162(
                __float2bfloat16(p2 - __bfloat162float(h2)),
                __float2bfloat16(p3 - __bfloat162float(h3)));
            o[nt][0] *= al0; o[nt][1] *= al0; o[nt][2] *= al1; o[nt][3] *= al1;
        }
        rs0 += __shfl_xor_sync(0xffffffffu, rs0, 1);
        rs0 += __shfl_xor_sync(0xffffffffu, rs0, 2);
        rs1 += __shfl_xor_sync(0xffffffffu, rs1, 1);
        rs1 += __shfl_xor_sync(0xffffffffu, rs1, 2);
        if ((lane & 3) == 0) {
            psum[p * 32 + h * 16 + qr_]     = rs0;
            psum[p * 32 + h * 16 + qr_ + 8] = rs1;
        }
        barp(1 + p);   // psum exchange + partner P visibility
        rs0 += psum[p * 32 + (1 - h) * 16 + qr_];
        rs1 += psum[p * 32 + (1 - h) * 16 + qr_ + 8];
        li0 = li0 * al0 + rs0; li1 = li1 * al1 + rs1;
        m0 = mn0; m1 = mn1;
        // PV: d-cols half h
        wgemm3_nt4(ApH, ApL, Vs + h * 32 * 144, Vs + 9216 + h * 32 * 144,
                   a_off, b_off, o);
        __syncthreads();
    }

    const float iv0 = 1.f / li0, iv1 = 1.f / li1;
    const int rA = 16 * p + qr_;
    #pragma unroll
    for (int nt = 0; nt < 4; nt++) {
        const int d = h * 32 + (nt << 3) + qc_;
        const float v0 = o[nt][0] * iv0, v1 = o[nt][1] * iv0;
        const float v2 = o[nt][2] * iv1, v3 = o[nt][3] * iv1;
        const size_t gA = ((size_t)(i0 + rA) * 8 + b) * 512 + n * 64 + d;
        const size_t gB = ((size_t)(i0 + rA + 8) * 8 + b) * 512 + n * 64 + d;
        const __nv_bfloat16 h0 = __float2bfloat16(v0), h1 = __float2bfloat16(v1);
        const __nv_bfloat16 h2 = __float2bfloat16(v2), h3 = __float2bfloat16(v3);
        *(__nv_bfloat162*)(vech + gA) = __halves2bfloat162(h0, h1);
        *(__nv_bfloat162*)(vecl + gA) = __halves2bfloat162(
            __float2bfloat16(v0 - __bfloat162float(h0)),
            __float2bfloat16(v1 - __bfloat162float(h1)));
        *(__nv_bfloat162*)(vech + gB) = __halves2bfloat162(h2, h3);
        *(__nv_bfloat162*)(vecl + gB) = __halves2bfloat162(
            __float2bfloat16(v2 - __bfloat162float(h2)),
            __float2bfloat16(v3 - __bfloat162float(h3)));
    }
}

// ===================== host orchestration ====================================
extern "C" void kernel_launch(void* const* d_in, const int* in_sizes, int n_in,
                              void* d_out, int out_size)
{
    (void)in_sizes; (void)n_in; (void)out_size;
    const float* dec_inp = (const float*)d_in[0];
    const float* r       = (const float*)d_in[1];
    const float* enc_out = (const float*)d_in[2];
    const float* rwb     = (const float*)d_in[3];
    const float* rrb     = (const float*)d_in[4];
    const float* qkv_w   = (const float*)d_in[5];
    const float* r_w     = (const float*)d_in[6];
    const float* o_w     = (const float*)d_in[7];
    const float* ln1_g   = (const float*)d_in[8];
    const float* ln1_b   = (const float*)d_in[9];
    const float* q_w     = (const float*)d_in[10];
    const float* kv_w    = (const float*)d_in[11];
    const float* o2_w    = (const float*)d_in[12];
    const float* ln2_g   = (const float*)d_in[13];
    const float* ln2_b   = (const float*)d_in[14];
    const float* ff_w1   = (const float*)d_in[15];
    const float* ff_b1   = (const float*)d_in[16];
    const float* ff_w2   = (const float*)d_in[17];
    const float* ff_b2   = (const float*)d_in[18];
    const float* ln3_g   = (const float*)d_in[19];
    const float* ln3_b   = (const float*)d_in[20];
    const unsigned char* emask = (const unsigned char*)d_in[22];
    float* out = (float*)d_out;

    float *out1, *h2, *out2, *qbias, *ccv;
    __nv_bfloat16 *wthi, *wtlo, *hh, *hl, *headsh, *headsl, *rh, *rl, *rkh, *rkl;
    __nv_bfloat16 *vth, *vtl, *vech, *vecl, *h2h, *h2l, *q2h, *q2l, *eh, *el;
    __nv_bfloat16 *kvh, *kvl, *vt2h, *vt2l, *vec2h, *vec2l, *th, *tl;
    cudaGetSymbolAddress((void**)&out1,  g_out1);
    cudaGetSymbolAddress((void**)&h2,    g_h2);
    cudaGetSymbolAddress((void**)&out2,  g_out2);
    cudaGetSymbolAddress((void**)&qbias, g_qbias);
    cudaGetSymbolAddress((void**)&ccv,   g_cc);
    cudaGetSymbolAddress((void**)&wthi,  g_wthi);
    cudaGetSymbolAddress((void**)&wtlo,  g_wtlo);
    cudaGetSymbolAddress((void**)&hh,    g_hh);
    cudaGetSymbolAddress((void**)&hl,    g_hl);
    cudaGetSymbolAddress((void**)&headsh,g_headsh);
    cudaGetSymbolAddress((void**)&headsl,g_headsl);
    cudaGetSymbolAddress((void**)&rh,    g_rh);
    cudaGetSymbolAddress((void**)&rl,    g_rl);
    cudaGetSymbolAddress((void**)&rkh,   g_rkh);
    cudaGetSymbolAddress((void**)&rkl,   g_rkl);
    cudaGetSymbolAddress((void**)&vth,   g_vth);
    cudaGetSymbolAddress((void**)&vtl,   g_vtl);
    cudaGetSymbolAddress((void**)&vech,  g_vech);
    cudaGetSymbolAddress((void**)&vecl,  g_vecl);
    cudaGetSymbolAddress((void**)&h2h,   g_h2h);
    cudaGetSymbolAddress((void**)&h2l,   g_h2l);
    cudaGetSymbolAddress((void**)&q2h,   g_q2h);
    cudaGetSymbolAddress((void**)&q2l,   g_q2l);
    cudaGetSymbolAddress((void**)&eh,    g_eh);
    cudaGetSymbolAddress((void**)&el,    g_el);
    cudaGetSymbolAddress((void**)&kvh,   g_kvh);
    cudaGetSymbolAddress((void**)&kvl,   g_kvl);
    cudaGetSymbolAddress((void**)&vt2h,  g_vt2h);
    cudaGetSymbolAddress((void**)&vt2l,  g_vt2l);
    cudaGetSymbolAddress((void**)&vec2h, g_vec2h);
    cudaGetSymbolAddress((void**)&vec2l, g_vec2l);
    cudaGetSymbolAddress((void**)&th,    g_th);
    cudaGetSymbolAddress((void**)&tl,    g_tl);

    cudaFuncSetAttribute(flash_rel_mma, cudaFuncAttributeMaxDynamicSharedMemorySize, REL_SMEM);
    cudaFuncSetAttribute(flash_ctx_mma, cudaFuncAttributeMaxDynamicSharedMemorySize, CTX_SMEM);
    cudaFuncSetAttribute(gemm_hmma<false, false>, cudaFuncAttributeMaxDynamicSharedMemorySize, GP_SMEM);
    cudaFuncSetAttribute(gemm_hmma<false, true>,  cudaFuncAttributeMaxDynamicSharedMemorySize, GP_SMEM);
    cudaFuncSetAttribute(gemm_hmma<true, true>,   cudaFuncAttributeMaxDynamicSharedMemorySize, GP_SMEM);

    // ---- two-stream fork/join (graph-capture-legal pattern) ----
    cudaStream_t s1;
    cudaStreamCreateWithFlags(&s1, cudaStreamNonBlocking);
    cudaEvent_t e0, eP, eW, eC, eKV;
    cudaEventCreateWithFlags(&e0,  cudaEventDisableTiming);
    cudaEventCreateWithFlags(&eP,  cudaEventDisableTiming);
    cudaEventCreateWithFlags(&eW,  cudaEventDisableTiming);
    cudaEventCreateWithFlags(&eC,  cudaEventDisableTiming);
    cudaEventCreateWithFlags(&eKV, cudaEventDisableTiming);

    cudaEventRecord(e0, 0);
    cudaStreamWaitEvent(s1, e0, 0);

    // stream 0: weight prep
    tsplit_all<<<4352, 256>>>(qkv_w, r_w, o_w, q_w, kv_w, o2_w, ff_w1, ff_w2,
                              wthi, wtlo);
    qbias_k<<<6, 256>>>(rwb, qbias);
    cudaEventRecord(eW, 0);

    // stream 1: activation prep
    ln_k<false, true><<<ROWS, 128, 0, s1>>>(dec_inp, ln1_g, ln1_b, nullptr, hh, hl);
    split_k<<<QLEN * DMODEL / 1024, 256, 0, s1>>>(r, rh, rl, QLEN * DMODEL / 4);
    split_k<<<ROWS * DMODEL / 1024, 256, 0, s1>>>(enc_out, eh, el, ROWS * DMODEL / 4);
    cudaEventRecord(eP, s1);

    // stream 0 spine: qkv -> vtrans1
    cudaStreamWaitEvent(0, eP, 0);
    gemm_hmma<false, true><<<dim3(12, 64), 256, GP_SMEM>>>(
        hh, hl, wthi + WT_QKV, wtlo + WT_QKV, qbias, nullptr,
        nullptr, headsh, headsl, ROWS, 1536, 512);
    vtrans_k<<<dim3(32, 64), 256>>>(headsh, headsl, vth, vtl, 1536, 1024);

    // stream 1 branch: rk -> c_k, then kv -> vtrans2 (overlaps flash_rel)
    cudaStreamWaitEvent(s1, eW, 0);
    gemm_hmma<false, true><<<dim3(4, 8), 256, GP_SMEM, s1>>>(
        rh, rl, wthi + WT_RW, wtlo + WT_RW, nullptr, nullptr,
        nullptr, rkh, rkl, QLEN, 512, 512);
    c_k<<<1024, 256, 0, s1>>>(rkh, rkl, rwb, rrb, ccv);
    cudaEventRecord(eC, s1);
    gemm_hmma<false, true><<<dim3(8, 64), 256, GP_SMEM, s1>>>(
        eh, el, wthi + WT_KVW, wtlo + WT_KVW, nullptr, nullptr,
        nullptr, kvh, kvl, ROWS, 1024, 512);
    vtrans_k<<<dim3(32, 64), 256, 0, s1>>>(kvh, kvl, vt2h, vt2l, 1024, 512);
    cudaEventRecord(eKV, s1);

    // stream 0: block 1 tail + block 2 head
    cudaStreamWaitEvent(0, eC, 0);
    flash_rel_mma<<<dim3(64, 16), 256, REL_SMEM>>>(headsh, headsl, vth, vtl,
                                                   rkh, rkl, ccv, vech, vecl);
    gemm_hmma<false, false><<<dim3(4, 64), 256, GP_SMEM>>>(
        vech, vecl, wthi + WT_OW, wtlo + WT_OW, nullptr, dec_inp,
        out1, nullptr, nullptr, ROWS, 512, 512);
    ln_k<true, true><<<ROWS, 128>>>(out1, ln2_g, ln2_b, h2, h2h, h2l);
    gemm_hmma<false, true><<<dim3(4, 64), 256, GP_SMEM>>>(
        h2h, h2l, wthi + WT_QW, wtlo + WT_QW, nullptr, nullptr,
        nullptr, q2h, q2l, ROWS, 512, 512);

    // join: cross attention needs kv/vt2 from stream 1
    cudaStreamWaitEvent(0, eKV, 0);
    flash_ctx_mma<<<dim3(16, 64), 256, CTX_SMEM>>>(q2h, q2l, kvh, kvl, vt2h, vt2l,
                                                   emask, vec2h, vec2l);
    gemm_hmma<false, false><<<dim3(4, 64), 256, GP_SMEM>>>(
        vec2h, vec2l, wthi + WT_O2W, wtlo + WT_O2W, nullptr, h2,
        out2, nullptr, nullptr, ROWS, 512, 512);

    // ---- block 3: FF ----
    ln_k<false, true><<<ROWS, 128>>>(out2, ln3_g, ln3_b, nullptr, hh, hl);
    gemm_hmma<true, true><<<dim3(16, 64), 256, GP_SMEM>>>(
        hh, hl, wthi + WT_FF1, wtlo + WT_FF1, ff_b1, nullptr,
        nullptr, th, tl, ROWS, 2048, 512);
    gemm_hmma<false, false><<<dim3(4, 64), 256, GP_SMEM>>>(
        th, tl, wthi + WT_FF2, wtlo + WT_FF2, ff_b2, out2,
        out, nullptr, nullptr, ROWS, 512, 2048);

    // destroy only when NOT capturing (destroying mid-capture invalidates the graph)
    cudaStreamCaptureStatus st = cudaStreamCaptureStatusNone;
    cudaStreamIsCapturing(0, &st);
    if (st == cudaStreamCaptureStatusNone) {
        cudaStreamDestroy(s1);
        cudaEventDestroy(e0);
        cudaEventDestroy(eP);
        cudaEventDestroy(eW);
        cudaEventDestroy(eC);
        cudaEventDestroy(eKV);
    }
}